// round 8
// baseline (speedup 1.0000x reference)
#include <cuda_runtime.h>
#include <cuda_fp16.h>
#include <math.h>
#include <stdint.h>

// Problem constants (fixed by the reference)
#define BB   4
#define SS   4096
#define EE   512
#define HH   8
#define DD   64
#define NT   (BB*SS)        // 16384 tokens
#define QW   1536           // 3*E

#define VAL_SCALE     1048576.0f          // 2^20: lift values out of fp16 subnormals
#define VAL_INV_SCALE (1.0f / 1048576.0f)

// ---------------- scratch (static device globals; no allocation) -------------
__device__ float g_qkv[(size_t)NT * QW];   // sig(q), sig(k), raw v  (96 MB)
__device__ float g_sums[4 * 32 * 64];
__device__ float g_part[16 * 32 * 128];
__device__ float g_io[(size_t)NT * HH * 2];
__device__ float g_hat[(size_t)NT * HH * 2];
__device__ float g_sm[64];
// fp16 hi/lo GEMM operands
__device__ __half g_xhi[(size_t)NT * EE];
__device__ __half g_xlo[(size_t)NT * EE];
__device__ __half g_whi[(size_t)QW * EE];   // W_qkv hi
__device__ __half g_wohi[(size_t)EE * EE];  // W_out hi
__device__ __half g_vhi[(size_t)NT * EE];   // values*2^20 hi (GEMM2 A)
__device__ __half g_vlo[(size_t)NT * EE];   // values*2^20 lo

// ===================== portable PTX helpers (sm_80+) =========================
__device__ __forceinline__ uint32_t smem_u32(const void* p) {
    uint32_t a;
    asm("{ .reg .u64 t; cvta.to.shared.u64 t, %1; cvt.u32.u64 %0, t; }"
        : "=r"(a) : "l"(p));
    return a;
}
#define LDSM_X4(r0, r1, r2, r3, addr) \
    asm volatile("ldmatrix.sync.aligned.m8n8.x4.shared.b16 {%0,%1,%2,%3}, [%4];" \
        : "=r"(r0), "=r"(r1), "=r"(r2), "=r"(r3) : "r"(addr))
#define MMA_F16(d, a, b) \
    asm volatile("mma.sync.aligned.m16n8k16.row.col.f32.f16.f16.f32 " \
        "{%0,%1,%2,%3},{%4,%5,%6,%7},{%8,%9},{%0,%1,%2,%3};" \
        : "+f"((d)[0]), "+f"((d)[1]), "+f"((d)[2]), "+f"((d)[3]) \
        : "r"((a)[0]), "r"((a)[1]), "r"((a)[2]), "r"((a)[3]), \
          "r"((b)[0]), "r"((b)[1]))
#define CP_ASYNC16(dst, src) \
    asm volatile("cp.async.cg.shared.global [%0], [%1], 16;" \
        :: "r"(dst), "l"(src))
#define CP_COMMIT() asm volatile("cp.async.commit_group;" ::: "memory")
#define CP_WAIT(n)  asm volatile("cp.async.wait_group %0;" :: "n"(n) : "memory")

// SMEM geometry: rows of 32 fp16 (64B) padded to 80B (16B-aligned; the 8
// row-addresses of each ldmatrix phase land on distinct 16B banks).
#define PITCH_B   80u
#define PLANE_A   20480u               // 256 rows * 80B   (A hi / A lo planes)
#define PLANE_BP  10240u               // 128 rows * 80B   (B hi plane)
#define STAGE_B   51200u               // Ahi + Alo + Bhi
#define NSTAGE    4
#define SMEM_GEMM (NSTAGE * STAGE_B)   // 204800 bytes

// ======== HMMA split-fp16 GEMM: C[m,n] = sum_k A[m,k]B[n,k] + bias[n] ========
// A supplied as fp16 hi+lo, B as fp16 hi. 2 products: Ahi*Bhi + Alo*Bhi.
// 256x128 tile, BK=32, 512 threads = 16 warps (4M x 4N), warp tile 64x32.
__device__ __forceinline__ void issue_stage(
    uint32_t sbase, int stage, int k0,
    const __half* __restrict__ ahi, const __half* __restrict__ alo,
    const __half* __restrict__ bhi, int K, int tid)
{
    const uint32_t sb = sbase + (uint32_t)stage * STAGE_B;
    // A hi: 256 rows x 4 x 16B  (its 0..1)
#pragma unroll
    for (int it = 0; it < 2; it++) {
        int idx = it * 512 + tid;
        int r = idx >> 2, c = idx & 3;
        CP_ASYNC16(sb + (uint32_t)r * PITCH_B + (uint32_t)c * 16u,
                   ahi + (size_t)r * K + k0 + c * 8);
    }
    // A lo
#pragma unroll
    for (int it = 0; it < 2; it++) {
        int idx = it * 512 + tid;
        int r = idx >> 2, c = idx & 3;
        CP_ASYNC16(sb + PLANE_A + (uint32_t)r * PITCH_B + (uint32_t)c * 16u,
                   alo + (size_t)r * K + k0 + c * 8);
    }
    // B hi: 128 rows x 4 x 16B
    {
        int r = tid >> 2, c = tid & 3;
        CP_ASYNC16(sb + 2u * PLANE_A + (uint32_t)r * PITCH_B + (uint32_t)c * 16u,
                   bhi + (size_t)r * K + k0 + c * 8);
    }
}

__global__ __launch_bounds__(512, 1) void hmma_gemm(
    const __half* __restrict__ Ahi, const __half* __restrict__ Alo,
    const __half* __restrict__ Bhi,
    const float* __restrict__ bias, float* __restrict__ C,
    int N, int K, int sigmode, float ascale)
{
    extern __shared__ char dynsmem[];
    const uint32_t sbase = smem_u32(dynsmem);

    const int tid   = threadIdx.x;
    const int warp  = tid >> 5;
    const int lane  = tid & 31;
    const int warpM = warp & 3;        // 4 x 64-row slabs
    const int warpN = warp >> 2;       // 4 x 32-col slabs

    const __half* ahi = Ahi + (size_t)blockIdx.y * 256 * K;
    const __half* alo = Alo + (size_t)blockIdx.y * 256 * K;
    const __half* bhi = Bhi + (size_t)blockIdx.x * 128 * K;

    float acc[16][4];
#pragma unroll
    for (int i = 0; i < 16; i++)
#pragma unroll
        for (int j = 0; j < 4; j++) acc[i][j] = 0.f;

    const int NC = K >> 5;   // chunks of 32

    const uint32_t a_lane = (uint32_t)(warpM * 64 + (lane & 15)) * PITCH_B
                          + (uint32_t)((lane >> 4) * 16);
    const uint32_t b_lane = 2u * PLANE_A
                          + (uint32_t)(warpN * 32 + (lane & 7) + ((lane >> 4) & 1) * 8) * PITCH_B
                          + (uint32_t)(((lane >> 3) & 1) * 16);

    // prologue: fill NSTAGE-1 stages
#pragma unroll
    for (int s = 0; s < NSTAGE - 1; s++) {
        issue_stage(sbase, s, s * 32, ahi, alo, bhi, K, tid);
        CP_COMMIT();
    }

    for (int c = 0; c < NC; c++) {
        CP_WAIT(NSTAGE - 2);
        __syncthreads();   // stage c resident; slot (c-1)%N free for refill
        if (c + NSTAGE - 1 < NC)
            issue_stage(sbase, (c + NSTAGE - 1) % NSTAGE, (c + NSTAGE - 1) * 32,
                        ahi, alo, bhi, K, tid);
        CP_COMMIT();

        const uint32_t cur = sbase + (uint32_t)(c % NSTAGE) * STAGE_B;
#pragma unroll
        for (int ks = 0; ks < 2; ks++) {
            const uint32_t koff = (uint32_t)ks * 32u;   // 16 fp16 = 32B
            uint32_t bh[4][2];
#pragma unroll
            for (int p = 0; p < 2; p++) {
                uint32_t addr = cur + b_lane + (uint32_t)(p * 16) * PITCH_B + koff;
                LDSM_X4(bh[2*p][0], bh[2*p][1], bh[2*p+1][0], bh[2*p+1][1], addr);
            }
#pragma unroll
            for (int mi = 0; mi < 4; mi++) {
                uint32_t ah[4], al[4];
                uint32_t addr = cur + a_lane + (uint32_t)(mi * 16) * PITCH_B + koff;
                LDSM_X4(ah[0], ah[1], ah[2], ah[3], addr);
                LDSM_X4(al[0], al[1], al[2], al[3], addr + PLANE_A);
#pragma unroll
                for (int ni = 0; ni < 4; ni++) {
                    MMA_F16(acc[mi * 4 + ni], ah, bh[ni]);
                    MMA_F16(acc[mi * 4 + ni], al, bh[ni]);
                }
            }
        }
    }

    // ---- epilogue: unscale + bias + optional sigmoid ----
#pragma unroll
    for (int mi = 0; mi < 4; mi++) {
        const int r0 = blockIdx.y * 256 + warpM * 64 + mi * 16 + (lane >> 2);
#pragma unroll
        for (int ni = 0; ni < 4; ni++) {
            const int col = blockIdx.x * 128 + warpN * 32 + ni * 8 + (lane & 3) * 2;
            const float b0 = __ldg(bias + col);
            const float b1 = __ldg(bias + col + 1);
            const bool s0 = sigmode && ((col % 192) < 128);
            const bool s1 = sigmode && (((col + 1) % 192) < 128);
            float v0 = acc[mi * 4 + ni][0] * ascale + b0;
            float v1 = acc[mi * 4 + ni][1] * ascale + b1;
            float v2 = acc[mi * 4 + ni][2] * ascale + b0;
            float v3 = acc[mi * 4 + ni][3] * ascale + b1;
            if (s0) { v0 = 1.f / (1.f + __expf(-v0)); v2 = 1.f / (1.f + __expf(-v2)); }
            if (s1) { v1 = 1.f / (1.f + __expf(-v1)); v3 = 1.f / (1.f + __expf(-v3)); }
            *(float2*)(C + (size_t)r0 * N + col)       = make_float2(v0, v1);
            *(float2*)(C + (size_t)(r0 + 8) * N + col) = make_float2(v2, v3);
        }
    }
}

// ---------------- fp32 -> fp16 hi/lo converters -------------------------------
__global__ __launch_bounds__(256) void cvt_split(
    const float4* __restrict__ src, __half2* __restrict__ hi,
    __half2* __restrict__ lo, int n4)
{
    int i = blockIdx.x * 256 + threadIdx.x;
    if (i >= n4) return;
    float4 v = src[i];
    __half h0 = __float2half(v.x), h1 = __float2half(v.y);
    __half h2 = __float2half(v.z), h3 = __float2half(v.w);
    hi[2 * i]     = __half2(h0, h1);
    hi[2 * i + 1] = __half2(h2, h3);
    lo[2 * i]     = __half2(__float2half(v.x - __half2float(h0)),
                            __float2half(v.y - __half2float(h1)));
    lo[2 * i + 1] = __half2(__float2half(v.z - __half2float(h2)),
                            __float2half(v.w - __half2float(h3)));
}

__global__ __launch_bounds__(256) void cvt_hi(
    const float4* __restrict__ src, __half2* __restrict__ hi, int n4)
{
    int i = blockIdx.x * 256 + threadIdx.x;
    if (i >= n4) return;
    float4 v = src[i];
    hi[2 * i]     = __half2(__float2half(v.x), __float2half(v.y));
    hi[2 * i + 1] = __half2(__float2half(v.z), __float2half(v.w));
}

// ---------------- seq reductions: deterministic 2-stage ----------------------
__global__ __launch_bounds__(128) void reduce_stage1(int phase)
{
    int chunk = blockIdx.x;
    int bh    = blockIdx.y;
    int b = bh >> 3, h = bh & 7;
    int tid = threadIdx.x;
    int isk = tid >> 6;
    int d   = tid & 63;
    int s0  = chunk * (SS / 16);

    const float* base = g_qkv + ((size_t)(b * SS + s0)) * QW + h * 192 + isk * 64 + d;
    float acc = 0.f;
    if (phase == 0) {
        for (int s = 0; s < SS / 16; s++) acc += base[(size_t)s * QW];
    } else {
        const float* io = g_io + (isk ? (size_t)NT * 8 : 0) + ((size_t)(b * SS + s0)) * 8 + h;
        for (int s = 0; s < SS / 16; s++) acc += base[(size_t)s * QW] / io[(size_t)s * 8];
    }
    g_part[(chunk * 32 + bh) * 128 + tid] = acc;
}

__global__ __launch_bounds__(256) void reduce_stage2(int phase)
{
    int idx = blockIdx.x * 256 + threadIdx.x;
    float acc = 0.f;
#pragma unroll
    for (int c = 0; c < 16; c++) acc += g_part[c * 4096 + idx];
    int bh = idx >> 7, t = idx & 127;
    int isk = t >> 6, d = t & 63;
    g_sums[(size_t)(phase * 2 + isk) * 2048 + bh * 64 + d] = acc;
}

// ---------------- per-token dots: warp per token ------------------------------
__global__ __launch_bounds__(256) void dots_kernel(int phase)
{
    int warp = threadIdx.x >> 5, lane = threadIdx.x & 31;
    int tok  = blockIdx.x * 8 + warp;
    int b    = tok >> 12;

    __shared__ float sQ[8][64], sK[8][64];
    const float* vq = g_sums + (size_t)(phase == 0 ? 1 : 3) * 2048 + b * 512;
    const float* vk = g_sums + (size_t)(phase == 0 ? 0 : 2) * 2048 + b * 512;
    for (int idx = threadIdx.x; idx < 512; idx += 256) {
        sQ[idx >> 6][idx & 63] = vq[idx];
        sK[idx >> 6][idx & 63] = vk[idx];
    }
    __syncthreads();

    const float* tq = g_qkv + (size_t)tok * QW;
    float* outI = (phase == 0 ? g_io : g_hat) + (size_t)tok * 8;
    float* outO = outI + (size_t)NT * 8;

#pragma unroll
    for (int h = 0; h < 8; h++) {
        const float* qh = tq + h * 192;
        float vi = qh[lane] * sQ[h][lane] + qh[lane + 32] * sQ[h][lane + 32];
        float vo = qh[64 + lane] * sK[h][lane] + qh[64 + lane + 32] * sK[h][lane + 32];
#pragma unroll
        for (int off = 16; off; off >>= 1) {
            vi += __shfl_down_sync(0xFFFFFFFFu, vi, off);
            vo += __shfl_down_sync(0xFFFFFFFFu, vo, off);
        }
        if (lane == 0) { outI[h] = vi; outO[h] = vo; }
    }
}

// ---------------- softmax stats over seq per (b,h) ---------------------------
__global__ __launch_bounds__(256) void softmax_stats()
{
    int bh = blockIdx.x;
    int b = bh >> 3, h = bh & 7;
    __shared__ float red[256];
    const float* oh = g_hat + (size_t)NT * 8 + (size_t)b * SS * 8 + h;

    float m = -1e30f;
    for (int s = threadIdx.x; s < SS; s += 256) m = fmaxf(m, oh[(size_t)s * 8]);
    red[threadIdx.x] = m; __syncthreads();
    for (int o = 128; o; o >>= 1) {
        if (threadIdx.x < o) red[threadIdx.x] = fmaxf(red[threadIdx.x], red[threadIdx.x + o]);
        __syncthreads();
    }
    m = red[0]; __syncthreads();

    float sum = 0.f;
    for (int s = threadIdx.x; s < SS; s += 256) sum += expf(oh[(size_t)s * 8] - m);
    red[threadIdx.x] = sum; __syncthreads();
    for (int o = 128; o; o >>= 1) {
        if (threadIdx.x < o) red[threadIdx.x] += red[threadIdx.x + o];
        __syncthreads();
    }
    if (threadIdx.x == 0) { g_sm[bh] = m; g_sm[32 + bh] = red[0]; }
}

// -------- fused flow-attention core (emits scaled fp16 hi/lo values) ---------
__global__ __launch_bounds__(256) void token_kernel()
{
    int lt = threadIdx.x >> 6;
    int e  = threadIdx.x & 63;
    int tok = blockIdx.x * 4 + lt;
    int b   = tok >> 12;

    __shared__ float qi[4][8][65], kk[4][8][65], vw[4][8][65];
    __shared__ float Am[4][8][9];
    __shared__ float s_invi[4][8], s_sig[4][8], s_sm[4][8];

    const float* tq = g_qkv + (size_t)tok * QW;
    if (e < 8) {
        int h = e;
        float iv = g_io[(size_t)tok * 8 + h];
        float ih = g_hat[(size_t)tok * 8 + h];
        float oh = g_hat[(size_t)NT * 8 + (size_t)tok * 8 + h];
        int bh = b * 8 + h;
        s_invi[lt][h] = 1.0f / iv;
        s_sig[lt][h]  = 1.0f / (1.0f + expf(-ih));
        s_sm[lt][h]   = expf(oh - g_sm[bh]) / g_sm[32 + bh];
    }
    __syncthreads();

#pragma unroll
    for (int h = 0; h < 8; h++) {
        qi[lt][h][e] = tq[h * 192 + e] * s_invi[lt][h];
        kk[lt][h][e] = tq[h * 192 + 64 + e];
        vw[lt][h][e] = tq[h * 192 + 128 + e] * s_sm[lt][h];
    }
    __syncthreads();

    {
        int h = e >> 3, h2 = e & 7;
        float a = 0.f;
#pragma unroll 8
        for (int d = 0; d < 64; d++) a = fmaf(qi[lt][h][d], kk[lt][h2][d], a);
        Am[lt][h][h2] = a;
    }
    __syncthreads();

    __half* ovh = g_vhi + (size_t)tok * EE;
    __half* ovl = g_vlo + (size_t)tok * EE;
#pragma unroll
    for (int h = 0; h < 8; h++) {
        float acc = 0.f;
#pragma unroll
        for (int h2 = 0; h2 < 8; h2++) acc = fmaf(Am[lt][h][h2], vw[lt][h2][e], acc);
        // scale by 2^20 so fp16 hi/lo stay in the normal range (values ~1e-7)
        float vs = acc * s_sig[lt][h] * VAL_SCALE;
        __half hv = __float2half(vs);
        ovh[h * 64 + e] = hv;
        ovl[h * 64 + e] = __float2half(vs - __half2float(hv));
    }
}

// ---------------- launch ------------------------------------------------------
extern "C" void kernel_launch(void* const* d_in, const int* in_sizes, int n_in,
                              void* d_out, int out_size)
{
    (void)in_sizes; (void)n_in; (void)out_size;
    const float* x     = (const float*)d_in[0];
    const float* W_qkv = (const float*)d_in[1];
    const float* b_qkv = (const float*)d_in[2];
    const float* W_out = (const float*)d_in[3];
    const float* b_out = (const float*)d_in[4];
    float* out = (float*)d_out;

    float* p_qkv = nullptr;
    cudaGetSymbolAddress((void**)&p_qkv, g_qkv);
    __half *p_xhi, *p_xlo, *p_whi, *p_wohi, *p_vhi, *p_vlo;
    cudaGetSymbolAddress((void**)&p_xhi,  g_xhi);
    cudaGetSymbolAddress((void**)&p_xlo,  g_xlo);
    cudaGetSymbolAddress((void**)&p_whi,  g_whi);
    cudaGetSymbolAddress((void**)&p_wohi, g_wohi);
    cudaGetSymbolAddress((void**)&p_vhi,  g_vhi);
    cudaGetSymbolAddress((void**)&p_vlo,  g_vlo);

    cudaFuncSetAttribute(hmma_gemm, cudaFuncAttributeMaxDynamicSharedMemorySize,
                         SMEM_GEMM);

    // 0) convert operands to fp16 hi/lo
    {
        int n4 = NT * EE / 4;
        cvt_split<<<(n4 + 255) / 256, 256>>>((const float4*)x,
                                             (__half2*)p_xhi, (__half2*)p_xlo, n4);
        int w4 = QW * EE / 4;
        cvt_hi<<<(w4 + 255) / 256, 256>>>((const float4*)W_qkv, (__half2*)p_whi, w4);
        int o4 = EE * EE / 4;
        cvt_hi<<<(o4 + 255) / 256, 256>>>((const float4*)W_out, (__half2*)p_wohi, o4);
    }
    // 1) QKV projection (HMMA split-fp16) + sigmoid(q,k) epilogue
    hmma_gemm<<<dim3(QW / 128, NT / 256), 512, SMEM_GEMM>>>(
        p_xhi, p_xlo, p_whi, b_qkv, p_qkv, QW, EE, 1, 1.0f);
    // 2) sumQ/sumK over seq
    reduce_stage1<<<dim3(16, 32), 128>>>(0);
    reduce_stage2<<<16, 256>>>(0);
    // 3) i, o per (token, head)
    dots_kernel<<<NT / 8, 256>>>(0);
    // 4) sqd = sum q/i, skd = sum k/o
    reduce_stage1<<<dim3(16, 32), 128>>>(1);
    reduce_stage2<<<16, 256>>>(1);
    // 5) ihat, ohat
    dots_kernel<<<NT / 8, 256>>>(1);
    // 6) softmax stats
    softmax_stats<<<32, 256>>>();
    // 7) fused flow-attention core -> scaled values (fp16 hi/lo)
    token_kernel<<<NT / 4, 256>>>();
    // 8) output projection (HMMA split-fp16), unscale in epilogue
    hmma_gemm<<<dim3(EE / 128, NT / 256), 512, SMEM_GEMM>>>(
        p_vhi, p_vlo, p_wohi, b_out, out, EE, EE, 0, VAL_INV_SCALE);
}

// round 9
// speedup vs baseline: 1.0890x; 1.0890x over previous
#include <cuda_runtime.h>
#include <cuda_fp16.h>
#include <math.h>
#include <stdint.h>

// Problem constants (fixed by the reference)
#define BB   4
#define SS   4096
#define EE   512
#define HH   8
#define DD   64
#define NT   (BB*SS)        // 16384 tokens
#define QW   1536           // 3*E

#define VAL_SCALE     1048576.0f          // 2^20: lift values out of fp16 subnormals
#define VAL_INV_SCALE (1.0f / 1048576.0f)

// ---------------- scratch (static device globals; no allocation) -------------
__device__ float g_qkv[(size_t)NT * QW];   // sig(q), sig(k), raw v  (96 MB)
__device__ float g_sums[4 * 32 * 64];
__device__ float g_part[16 * 32 * 128];
__device__ float g_io[(size_t)NT * HH * 2];
__device__ float g_hat[(size_t)NT * HH * 2];
__device__ float g_sm[64];
// fp16 hi/lo GEMM operands
__device__ __half g_xhi[(size_t)NT * EE];
__device__ __half g_xlo[(size_t)NT * EE];
__device__ __half g_whi[(size_t)QW * EE];   // W_qkv hi
__device__ __half g_wohi[(size_t)EE * EE];  // W_out hi
__device__ __half g_vhi[(size_t)NT * EE];   // values*2^20 hi (GEMM2 A)
__device__ __half g_vlo[(size_t)NT * EE];   // values*2^20 lo

// ===================== portable PTX helpers (sm_80+) =========================
__device__ __forceinline__ uint32_t smem_u32(const void* p) {
    uint32_t a;
    asm("{ .reg .u64 t; cvta.to.shared.u64 t, %1; cvt.u32.u64 %0, t; }"
        : "=r"(a) : "l"(p));
    return a;
}
#define LDSM_X4(r0, r1, r2, r3, addr) \
    asm volatile("ldmatrix.sync.aligned.m8n8.x4.shared.b16 {%0,%1,%2,%3}, [%4];" \
        : "=r"(r0), "=r"(r1), "=r"(r2), "=r"(r3) : "r"(addr))
#define MMA_F16(d, a, b) \
    asm volatile("mma.sync.aligned.m16n8k16.row.col.f32.f16.f16.f32 " \
        "{%0,%1,%2,%3},{%4,%5,%6,%7},{%8,%9},{%0,%1,%2,%3};" \
        : "+f"((d)[0]), "+f"((d)[1]), "+f"((d)[2]), "+f"((d)[3]) \
        : "r"((a)[0]), "r"((a)[1]), "r"((a)[2]), "r"((a)[3]), \
          "r"((b)[0]), "r"((b)[1]))
#define CP_ASYNC16(dst, src) \
    asm volatile("cp.async.cg.shared.global [%0], [%1], 16;" \
        :: "r"(dst), "l"(src))
#define CP_COMMIT() asm volatile("cp.async.commit_group;" ::: "memory")
#define CP_WAIT(n)  asm volatile("cp.async.wait_group %0;" :: "n"(n) : "memory")

// SMEM geometry: rows of 32 fp16 (64B) padded to 80B (16B-aligned; the 8
// row-addresses of each ldmatrix phase land on distinct 16B banks).
#define PITCH_B   80u
#define PLANE_B   10240u               // 128 rows * 80B
#define STAGE_B   30720u               // Ahi, Alo, Bhi planes
#define NSTAGE    3
#define SMEM_GEMM (NSTAGE * STAGE_B)   // 92160 bytes -> 2 CTAs per SM

// ======== HMMA split-fp16 GEMM: C[m,n] = sum_k A[m,k]B[n,k] + bias[n] ========
// A supplied as fp16 hi+lo, B as fp16 hi. 2 products: Ahi*Bhi + Alo*Bhi.
// 128x128 tile, BK=32, 256 threads = 8 warps (2M x 4N), warp tile 64x32.
__device__ __forceinline__ void issue_stage(
    uint32_t sbase, int stage, int k0,
    const __half* __restrict__ ahi, const __half* __restrict__ alo,
    const __half* __restrict__ bhi, int K, int tid)
{
    const uint32_t sb = sbase + (uint32_t)stage * STAGE_B;
#pragma unroll
    for (int it = 0; it < 6; it++) {
        int idx   = it * 256 + tid;          // 0..1535
        int plane = idx >> 9;                // 0..2
        int rc    = idx & 511;
        int row   = rc >> 2;
        int c     = rc & 3;
        uint32_t dst = sb + (uint32_t)plane * PLANE_B
                     + (uint32_t)row * PITCH_B + (uint32_t)c * 16u;
        const __half* src = (plane == 0 ? ahi : (plane == 1 ? alo : bhi))
                          + (size_t)row * K + k0 + c * 8;
        CP_ASYNC16(dst, src);
    }
}

__global__ __launch_bounds__(256, 2) void hmma_gemm(
    const __half* __restrict__ Ahi, const __half* __restrict__ Alo,
    const __half* __restrict__ Bhi,
    const float* __restrict__ bias, float* __restrict__ C,
    int N, int K, int sigmode, float ascale)
{
    extern __shared__ char dynsmem[];
    const uint32_t sbase = smem_u32(dynsmem);

    const int tid   = threadIdx.x;
    const int warp  = tid >> 5;
    const int lane  = tid & 31;
    const int warpM = warp & 1;        // 2 x 64-row slabs
    const int warpN = warp >> 1;       // 4 x 32-col slabs

    const __half* ahi = Ahi + (size_t)blockIdx.y * 128 * K;
    const __half* alo = Alo + (size_t)blockIdx.y * 128 * K;
    const __half* bhi = Bhi + (size_t)blockIdx.x * 128 * K;

    float acc[16][4];
#pragma unroll
    for (int i = 0; i < 16; i++)
#pragma unroll
        for (int j = 0; j < 4; j++) acc[i][j] = 0.f;

    const int NC = K >> 5;   // chunks of 32

    const uint32_t a_lane = (uint32_t)(warpM * 64 + (lane & 15)) * PITCH_B
                          + (uint32_t)((lane >> 4) * 16);
    const uint32_t b_lane = 2u * PLANE_B
                          + (uint32_t)(warpN * 32 + (lane & 7) + ((lane >> 4) & 1) * 8) * PITCH_B
                          + (uint32_t)(((lane >> 3) & 1) * 16);

    // prologue: fill NSTAGE-1 stages
#pragma unroll
    for (int s = 0; s < NSTAGE - 1; s++) {
        issue_stage(sbase, s, s * 32, ahi, alo, bhi, K, tid);
        CP_COMMIT();
    }

    for (int c = 0; c < NC; c++) {
        CP_WAIT(NSTAGE - 2);
        __syncthreads();   // stage c resident; slot (c-1)%NSTAGE free for refill
        if (c + NSTAGE - 1 < NC)
            issue_stage(sbase, (c + NSTAGE - 1) % NSTAGE, (c + NSTAGE - 1) * 32,
                        ahi, alo, bhi, K, tid);
        CP_COMMIT();

        const uint32_t cur = sbase + (uint32_t)(c % NSTAGE) * STAGE_B;
#pragma unroll
        for (int ks = 0; ks < 2; ks++) {
            const uint32_t koff = (uint32_t)ks * 32u;   // 16 fp16 = 32B
            uint32_t bh[4][2];
#pragma unroll
            for (int p = 0; p < 2; p++) {
                uint32_t addr = cur + b_lane + (uint32_t)(p * 16) * PITCH_B + koff;
                LDSM_X4(bh[2*p][0], bh[2*p][1], bh[2*p+1][0], bh[2*p+1][1], addr);
            }
#pragma unroll
            for (int mi = 0; mi < 4; mi++) {
                uint32_t ah[4], al[4];
                uint32_t addr = cur + a_lane + (uint32_t)(mi * 16) * PITCH_B + koff;
                LDSM_X4(ah[0], ah[1], ah[2], ah[3], addr);
                LDSM_X4(al[0], al[1], al[2], al[3], addr + PLANE_B);
#pragma unroll
                for (int ni = 0; ni < 4; ni++) {
                    MMA_F16(acc[mi * 4 + ni], ah, bh[ni]);
                    MMA_F16(acc[mi * 4 + ni], al, bh[ni]);
                }
            }
        }
    }

    // ---- epilogue: unscale + bias + optional sigmoid ----
#pragma unroll
    for (int mi = 0; mi < 4; mi++) {
        const int r0 = blockIdx.y * 128 + warpM * 64 + mi * 16 + (lane >> 2);
#pragma unroll
        for (int ni = 0; ni < 4; ni++) {
            const int col = blockIdx.x * 128 + warpN * 32 + ni * 8 + (lane & 3) * 2;
            const float b0 = __ldg(bias + col);
            const float b1 = __ldg(bias + col + 1);
            const bool s0 = sigmode && ((col % 192) < 128);
            const bool s1 = sigmode && (((col + 1) % 192) < 128);
            float v0 = acc[mi * 4 + ni][0] * ascale + b0;
            float v1 = acc[mi * 4 + ni][1] * ascale + b1;
            float v2 = acc[mi * 4 + ni][2] * ascale + b0;
            float v3 = acc[mi * 4 + ni][3] * ascale + b1;
            if (s0) { v0 = 1.f / (1.f + __expf(-v0)); v2 = 1.f / (1.f + __expf(-v2)); }
            if (s1) { v1 = 1.f / (1.f + __expf(-v1)); v3 = 1.f / (1.f + __expf(-v3)); }
            *(float2*)(C + (size_t)r0 * N + col)       = make_float2(v0, v1);
            *(float2*)(C + (size_t)(r0 + 8) * N + col) = make_float2(v2, v3);
        }
    }
}

// ---------------- fp32 -> fp16 hi/lo converters -------------------------------
__global__ __launch_bounds__(256) void cvt_split(
    const float4* __restrict__ src, __half2* __restrict__ hi,
    __half2* __restrict__ lo, int n4)
{
    int i = blockIdx.x * 256 + threadIdx.x;
    if (i >= n4) return;
    float4 v = src[i];
    __half h0 = __float2half(v.x), h1 = __float2half(v.y);
    __half h2 = __float2half(v.z), h3 = __float2half(v.w);
    hi[2 * i]     = __half2(h0, h1);
    hi[2 * i + 1] = __half2(h2, h3);
    lo[2 * i]     = __half2(__float2half(v.x - __half2float(h0)),
                            __float2half(v.y - __half2float(h1)));
    lo[2 * i + 1] = __half2(__float2half(v.z - __half2float(h2)),
                            __float2half(v.w - __half2float(h3)));
}

__global__ __launch_bounds__(256) void cvt_hi(
    const float4* __restrict__ src, __half2* __restrict__ hi, int n4)
{
    int i = blockIdx.x * 256 + threadIdx.x;
    if (i >= n4) return;
    float4 v = src[i];
    hi[2 * i]     = __half2(__float2half(v.x), __float2half(v.y));
    hi[2 * i + 1] = __half2(__float2half(v.z), __float2half(v.w));
}

// ---------------- seq reductions: deterministic 2-stage ----------------------
__global__ __launch_bounds__(128) void reduce_stage1(int phase)
{
    int chunk = blockIdx.x;
    int bh    = blockIdx.y;
    int b = bh >> 3, h = bh & 7;
    int tid = threadIdx.x;
    int isk = tid >> 6;
    int d   = tid & 63;
    int s0  = chunk * (SS / 16);

    const float* base = g_qkv + ((size_t)(b * SS + s0)) * QW + h * 192 + isk * 64 + d;
    float acc = 0.f;
    if (phase == 0) {
        for (int s = 0; s < SS / 16; s++) acc += base[(size_t)s * QW];
    } else {
        const float* io = g_io + (isk ? (size_t)NT * 8 : 0) + ((size_t)(b * SS + s0)) * 8 + h;
        for (int s = 0; s < SS / 16; s++) acc += base[(size_t)s * QW] / io[(size_t)s * 8];
    }
    g_part[(chunk * 32 + bh) * 128 + tid] = acc;
}

__global__ __launch_bounds__(256) void reduce_stage2(int phase)
{
    int idx = blockIdx.x * 256 + threadIdx.x;
    float acc = 0.f;
#pragma unroll
    for (int c = 0; c < 16; c++) acc += g_part[c * 4096 + idx];
    int bh = idx >> 7, t = idx & 127;
    int isk = t >> 6, d = t & 63;
    g_sums[(size_t)(phase * 2 + isk) * 2048 + bh * 64 + d] = acc;
}

// ---------------- per-token dots: warp per token ------------------------------
__global__ __launch_bounds__(256) void dots_kernel(int phase)
{
    int warp = threadIdx.x >> 5, lane = threadIdx.x & 31;
    int tok  = blockIdx.x * 8 + warp;
    int b    = tok >> 12;

    __shared__ float sQ[8][64], sK[8][64];
    const float* vq = g_sums + (size_t)(phase == 0 ? 1 : 3) * 2048 + b * 512;
    const float* vk = g_sums + (size_t)(phase == 0 ? 0 : 2) * 2048 + b * 512;
    for (int idx = threadIdx.x; idx < 512; idx += 256) {
        sQ[idx >> 6][idx & 63] = vq[idx];
        sK[idx >> 6][idx & 63] = vk[idx];
    }
    __syncthreads();

    const float* tq = g_qkv + (size_t)tok * QW;
    float* outI = (phase == 0 ? g_io : g_hat) + (size_t)tok * 8;
    float* outO = outI + (size_t)NT * 8;

#pragma unroll
    for (int h = 0; h < 8; h++) {
        const float* qh = tq + h * 192;
        float vi = qh[lane] * sQ[h][lane] + qh[lane + 32] * sQ[h][lane + 32];
        float vo = qh[64 + lane] * sK[h][lane] + qh[64 + lane + 32] * sK[h][lane + 32];
#pragma unroll
        for (int off = 16; off; off >>= 1) {
            vi += __shfl_down_sync(0xFFFFFFFFu, vi, off);
            vo += __shfl_down_sync(0xFFFFFFFFu, vo, off);
        }
        if (lane == 0) { outI[h] = vi; outO[h] = vo; }
    }
}

// ---------------- softmax stats over seq per (b,h) ---------------------------
__global__ __launch_bounds__(256) void softmax_stats()
{
    int bh = blockIdx.x;
    int b = bh >> 3, h = bh & 7;
    __shared__ float red[256];
    const float* oh = g_hat + (size_t)NT * 8 + (size_t)b * SS * 8 + h;

    float m = -1e30f;
    for (int s = threadIdx.x; s < SS; s += 256) m = fmaxf(m, oh[(size_t)s * 8]);
    red[threadIdx.x] = m; __syncthreads();
    for (int o = 128; o; o >>= 1) {
        if (threadIdx.x < o) red[threadIdx.x] = fmaxf(red[threadIdx.x], red[threadIdx.x + o]);
        __syncthreads();
    }
    m = red[0]; __syncthreads();

    float sum = 0.f;
    for (int s = threadIdx.x; s < SS; s += 256) sum += expf(oh[(size_t)s * 8] - m);
    red[threadIdx.x] = sum; __syncthreads();
    for (int o = 128; o; o >>= 1) {
        if (threadIdx.x < o) red[threadIdx.x] += red[threadIdx.x + o];
        __syncthreads();
    }
    if (threadIdx.x == 0) { g_sm[bh] = m; g_sm[32 + bh] = red[0]; }
}

// -------- fused flow-attention core (emits scaled fp16 hi/lo values) ---------
__global__ __launch_bounds__(256) void token_kernel()
{
    int lt = threadIdx.x >> 6;
    int e  = threadIdx.x & 63;
    int tok = blockIdx.x * 4 + lt;
    int b   = tok >> 12;

    __shared__ float qi[4][8][65], kk[4][8][65], vw[4][8][65];
    __shared__ float Am[4][8][9];
    __shared__ float s_invi[4][8], s_sig[4][8], s_sm[4][8];

    const float* tq = g_qkv + (size_t)tok * QW;
    if (e < 8) {
        int h = e;
        float iv = g_io[(size_t)tok * 8 + h];
        float ih = g_hat[(size_t)tok * 8 + h];
        float oh = g_hat[(size_t)NT * 8 + (size_t)tok * 8 + h];
        int bh = b * 8 + h;
        s_invi[lt][h] = 1.0f / iv;
        s_sig[lt][h]  = 1.0f / (1.0f + expf(-ih));
        s_sm[lt][h]   = expf(oh - g_sm[bh]) / g_sm[32 + bh];
    }
    __syncthreads();

#pragma unroll
    for (int h = 0; h < 8; h++) {
        qi[lt][h][e] = tq[h * 192 + e] * s_invi[lt][h];
        kk[lt][h][e] = tq[h * 192 + 64 + e];
        vw[lt][h][e] = tq[h * 192 + 128 + e] * s_sm[lt][h];
    }
    __syncthreads();

    {
        int h = e >> 3, h2 = e & 7;
        float a = 0.f;
#pragma unroll 8
        for (int d = 0; d < 64; d++) a = fmaf(qi[lt][h][d], kk[lt][h2][d], a);
        Am[lt][h][h2] = a;
    }
    __syncthreads();

    __half* ovh = g_vhi + (size_t)tok * EE;
    __half* ovl = g_vlo + (size_t)tok * EE;
#pragma unroll
    for (int h = 0; h < 8; h++) {
        float acc = 0.f;
#pragma unroll
        for (int h2 = 0; h2 < 8; h2++) acc = fmaf(Am[lt][h][h2], vw[lt][h2][e], acc);
        // scale by 2^20 so fp16 hi/lo stay in the normal range (values ~1e-7)
        float vs = acc * s_sig[lt][h] * VAL_SCALE;
        __half hv = __float2half(vs);
        ovh[h * 64 + e] = hv;
        ovl[h * 64 + e] = __float2half(vs - __half2float(hv));
    }
}

// ---------------- launch ------------------------------------------------------
extern "C" void kernel_launch(void* const* d_in, const int* in_sizes, int n_in,
                              void* d_out, int out_size)
{
    (void)in_sizes; (void)n_in; (void)out_size;
    const float* x     = (const float*)d_in[0];
    const float* W_qkv = (const float*)d_in[1];
    const float* b_qkv = (const float*)d_in[2];
    const float* W_out = (const float*)d_in[3];
    const float* b_out = (const float*)d_in[4];
    float* out = (float*)d_out;

    float* p_qkv = nullptr;
    cudaGetSymbolAddress((void**)&p_qkv, g_qkv);
    __half *p_xhi, *p_xlo, *p_whi, *p_wohi, *p_vhi, *p_vlo;
    cudaGetSymbolAddress((void**)&p_xhi,  g_xhi);
    cudaGetSymbolAddress((void**)&p_xlo,  g_xlo);
    cudaGetSymbolAddress((void**)&p_whi,  g_whi);
    cudaGetSymbolAddress((void**)&p_wohi, g_wohi);
    cudaGetSymbolAddress((void**)&p_vhi,  g_vhi);
    cudaGetSymbolAddress((void**)&p_vlo,  g_vlo);

    cudaFuncSetAttribute(hmma_gemm, cudaFuncAttributeMaxDynamicSharedMemorySize,
                         SMEM_GEMM);

    // 0) convert operands to fp16 hi/lo
    {
        int n4 = NT * EE / 4;
        cvt_split<<<(n4 + 255) / 256, 256>>>((const float4*)x,
                                             (__half2*)p_xhi, (__half2*)p_xlo, n4);
        int w4 = QW * EE / 4;
        cvt_hi<<<(w4 + 255) / 256, 256>>>((const float4*)W_qkv, (__half2*)p_whi, w4);
        int o4 = EE * EE / 4;
        cvt_hi<<<(o4 + 255) / 256, 256>>>((const float4*)W_out, (__half2*)p_wohi, o4);
    }
    // 1) QKV projection (HMMA split-fp16) + sigmoid(q,k) epilogue
    hmma_gemm<<<dim3(QW / 128, NT / 128), 256, SMEM_GEMM>>>(
        p_xhi, p_xlo, p_whi, b_qkv, p_qkv, QW, EE, 1, 1.0f);
    // 2) sumQ/sumK over seq
    reduce_stage1<<<dim3(16, 32), 128>>>(0);
    reduce_stage2<<<16, 256>>>(0);
    // 3) i, o per (token, head)
    dots_kernel<<<NT / 8, 256>>>(0);
    // 4) sqd = sum q/i, skd = sum k/o
    reduce_stage1<<<dim3(16, 32), 128>>>(1);
    reduce_stage2<<<16, 256>>>(1);
    // 5) ihat, ohat
    dots_kernel<<<NT / 8, 256>>>(1);
    // 6) softmax stats
    softmax_stats<<<32, 256>>>();
    // 7) fused flow-attention core -> scaled values (fp16 hi/lo)
    token_kernel<<<NT / 4, 256>>>();
    // 8) output projection (HMMA split-fp16), unscale in epilogue
    hmma_gemm<<<dim3(EE / 128, NT / 128), 256, SMEM_GEMM>>>(
        p_vhi, p_vlo, p_wohi, b_out, out, EE, EE, 0, VAL_INV_SCALE);
}

// round 10
// speedup vs baseline: 1.1320x; 1.0395x over previous
#include <cuda_runtime.h>
#include <cuda_fp16.h>
#include <math.h>
#include <stdint.h>

// Problem constants (fixed by the reference)
#define BB   4
#define SS   4096
#define EE   512
#define HH   8
#define DD   64
#define NT   (BB*SS)        // 16384 tokens
#define QW   1536           // 3*E

#define VAL_SCALE     1048576.0f          // 2^20: lift values out of fp16 subnormals
#define VAL_INV_SCALE (1.0f / 1048576.0f)

// ---------------- scratch (static device globals; no allocation) -------------
__device__ float g_qkv[(size_t)NT * QW];   // sig(q), sig(k), raw v  (96 MB)
__device__ float g_sums[4 * 32 * 64];
__device__ float g_part[16 * 32 * 128];
__device__ float g_io[(size_t)NT * HH * 2];
__device__ float g_hat[(size_t)NT * HH * 2];
__device__ float g_sm[64];
// fp16 hi/lo GEMM operands
__device__ __half g_xhi[(size_t)NT * EE];
__device__ __half g_xlo[(size_t)NT * EE];
__device__ __half g_whi[(size_t)QW * EE];   // W_qkv hi
__device__ __half g_wohi[(size_t)EE * EE];  // W_out hi
__device__ __half g_vhi[(size_t)NT * EE];   // values*2^20 hi (GEMM2 A)
__device__ __half g_vlo[(size_t)NT * EE];   // values*2^20 lo

// ===================== portable PTX helpers (sm_80+) =========================
__device__ __forceinline__ uint32_t smem_u32(const void* p) {
    uint32_t a;
    asm("{ .reg .u64 t; cvta.to.shared.u64 t, %1; cvt.u32.u64 %0, t; }"
        : "=r"(a) : "l"(p));
    return a;
}
#define LDSM_X4(r0, r1, r2, r3, addr) \
    asm volatile("ldmatrix.sync.aligned.m8n8.x4.shared.b16 {%0,%1,%2,%3}, [%4];" \
        : "=r"(r0), "=r"(r1), "=r"(r2), "=r"(r3) : "r"(addr))
#define MMA_F16(d, a, b) \
    asm volatile("mma.sync.aligned.m16n8k16.row.col.f32.f16.f16.f32 " \
        "{%0,%1,%2,%3},{%4,%5,%6,%7},{%8,%9},{%0,%1,%2,%3};" \
        : "+f"((d)[0]), "+f"((d)[1]), "+f"((d)[2]), "+f"((d)[3]) \
        : "r"((a)[0]), "r"((a)[1]), "r"((a)[2]), "r"((a)[3]), \
          "r"((b)[0]), "r"((b)[1]))
#define CP_ASYNC16(dst, src) \
    asm volatile("cp.async.cg.shared.global [%0], [%1], 16;" \
        :: "r"(dst), "l"(src))
#define CP_COMMIT() asm volatile("cp.async.commit_group;" ::: "memory")
#define CP_WAIT(n)  asm volatile("cp.async.wait_group %0;" :: "n"(n) : "memory")

// SMEM geometry (BK=64): rows of 64 fp16 (128B) padded to 144B. The 8 row
// addresses of each ldmatrix phase differ by r*144 ≡ r*16 (mod 128) — all
// distinct 16B banks, conflict-free without swizzle math.
#define PITCH_B   144u
#define PLANE_B   18432u               // 128 rows * 144B
#define STAGE_B   55296u               // Ahi, Alo, Bhi planes
#define NSTAGE    2
#define SMEM_GEMM (NSTAGE * STAGE_B)   // 110592 bytes -> 2 CTAs per SM

// ======== HMMA split-fp16 GEMM: C[m,n] = sum_k A[m,k]B[n,k] + bias[n] ========
// A supplied as fp16 hi+lo, B as fp16 hi. 2 products: Ahi*Bhi + Alo*Bhi.
// 128x128 tile, BK=64, 256 threads = 8 warps (2M x 4N), warp tile 64x32.
__device__ __forceinline__ void issue_stage(
    uint32_t sbase, int stage, int k0,
    const __half* __restrict__ ahi, const __half* __restrict__ alo,
    const __half* __restrict__ bhi, int K, int tid)
{
    const uint32_t sb = sbase + (uint32_t)stage * STAGE_B;
#pragma unroll
    for (int it = 0; it < 12; it++) {
        int idx   = it * 256 + tid;          // 0..3071
        int plane = idx >> 10;               // 0..2 (1024 16B-chunks per plane)
        int rc    = idx & 1023;
        int row   = rc >> 3;
        int c     = rc & 7;
        uint32_t dst = sb + (uint32_t)plane * PLANE_B
                     + (uint32_t)row * PITCH_B + (uint32_t)c * 16u;
        const __half* src = (plane == 0 ? ahi : (plane == 1 ? alo : bhi))
                          + (size_t)row * K + k0 + c * 8;
        CP_ASYNC16(dst, src);
    }
}

__global__ __launch_bounds__(256, 2) void hmma_gemm(
    const __half* __restrict__ Ahi, const __half* __restrict__ Alo,
    const __half* __restrict__ Bhi,
    const float* __restrict__ bias, float* __restrict__ C,
    int N, int K, int sigmode, float ascale)
{
    extern __shared__ char dynsmem[];
    const uint32_t sbase = smem_u32(dynsmem);

    const int tid   = threadIdx.x;
    const int warp  = tid >> 5;
    const int lane  = tid & 31;
    const int warpM = warp & 1;        // 2 x 64-row slabs
    const int warpN = warp >> 1;       // 4 x 32-col slabs

    const __half* ahi = Ahi + (size_t)blockIdx.y * 128 * K;
    const __half* alo = Alo + (size_t)blockIdx.y * 128 * K;
    const __half* bhi = Bhi + (size_t)blockIdx.x * 128 * K;

    float acc[16][4];
#pragma unroll
    for (int i = 0; i < 16; i++)
#pragma unroll
        for (int j = 0; j < 4; j++) acc[i][j] = 0.f;

    const int NC = K >> 6;   // chunks of 64

    const uint32_t a_lane = (uint32_t)(warpM * 64 + (lane & 15)) * PITCH_B
                          + (uint32_t)((lane >> 4) * 16);
    const uint32_t b_lane = 2u * PLANE_B
                          + (uint32_t)(warpN * 32 + (lane & 7) + ((lane >> 4) & 1) * 8) * PITCH_B
                          + (uint32_t)(((lane >> 3) & 1) * 16);

    // prologue: fill stage 0
    issue_stage(sbase, 0, 0, ahi, alo, bhi, K, tid);
    CP_COMMIT();

    for (int c = 0; c < NC; c++) {
        CP_WAIT(0);
        __syncthreads();   // stage c resident; other slot free for refill
        if (c + 1 < NC)
            issue_stage(sbase, (c + 1) & 1, (c + 1) * 64, ahi, alo, bhi, K, tid);
        CP_COMMIT();

        const uint32_t cur = sbase + (uint32_t)(c & 1) * STAGE_B;
#pragma unroll
        for (int ks = 0; ks < 4; ks++) {
            const uint32_t koff = (uint32_t)ks * 32u;   // 16 fp16 = 32B
            uint32_t bh[4][2];
#pragma unroll
            for (int p = 0; p < 2; p++) {
                uint32_t addr = cur + b_lane + (uint32_t)(p * 16) * PITCH_B + koff;
                LDSM_X4(bh[2*p][0], bh[2*p][1], bh[2*p+1][0], bh[2*p+1][1], addr);
            }
            // A-fragment double buffer: load mi+1 while issuing mi's MMAs
            uint32_t ah[2][4], al[2][4];
            {
                uint32_t addr = cur + a_lane + koff;
                LDSM_X4(ah[0][0], ah[0][1], ah[0][2], ah[0][3], addr);
                LDSM_X4(al[0][0], al[0][1], al[0][2], al[0][3], addr + PLANE_B);
            }
#pragma unroll
            for (int mi = 0; mi < 4; mi++) {
                const int cu = mi & 1, nx = cu ^ 1;
                if (mi < 3) {
                    uint32_t addr = cur + a_lane
                                  + (uint32_t)((mi + 1) * 16) * PITCH_B + koff;
                    LDSM_X4(ah[nx][0], ah[nx][1], ah[nx][2], ah[nx][3], addr);
                    LDSM_X4(al[nx][0], al[nx][1], al[nx][2], al[nx][3], addr + PLANE_B);
                }
#pragma unroll
                for (int ni = 0; ni < 4; ni++) {
                    MMA_F16(acc[mi * 4 + ni], ah[cu], bh[ni]);
                    MMA_F16(acc[mi * 4 + ni], al[cu], bh[ni]);
                }
            }
        }
    }

    // ---- epilogue: unscale + bias + optional sigmoid ----
#pragma unroll
    for (int mi = 0; mi < 4; mi++) {
        const int r0 = blockIdx.y * 128 + warpM * 64 + mi * 16 + (lane >> 2);
#pragma unroll
        for (int ni = 0; ni < 4; ni++) {
            const int col = blockIdx.x * 128 + warpN * 32 + ni * 8 + (lane & 3) * 2;
            const float b0 = __ldg(bias + col);
            const float b1 = __ldg(bias + col + 1);
            const bool s0 = sigmode && ((col % 192) < 128);
            const bool s1 = sigmode && (((col + 1) % 192) < 128);
            float v0 = acc[mi * 4 + ni][0] * ascale + b0;
            float v1 = acc[mi * 4 + ni][1] * ascale + b1;
            float v2 = acc[mi * 4 + ni][2] * ascale + b0;
            float v3 = acc[mi * 4 + ni][3] * ascale + b1;
            if (s0) { v0 = 1.f / (1.f + __expf(-v0)); v2 = 1.f / (1.f + __expf(-v2)); }
            if (s1) { v1 = 1.f / (1.f + __expf(-v1)); v3 = 1.f / (1.f + __expf(-v3)); }
            *(float2*)(C + (size_t)r0 * N + col)       = make_float2(v0, v1);
            *(float2*)(C + (size_t)(r0 + 8) * N + col) = make_float2(v2, v3);
        }
    }
}

// ---------------- fp32 -> fp16 hi/lo converters -------------------------------
__global__ __launch_bounds__(256) void cvt_split(
    const float4* __restrict__ src, __half2* __restrict__ hi,
    __half2* __restrict__ lo, int n4)
{
    int i = blockIdx.x * 256 + threadIdx.x;
    if (i >= n4) return;
    float4 v = src[i];
    __half h0 = __float2half(v.x), h1 = __float2half(v.y);
    __half h2 = __float2half(v.z), h3 = __float2half(v.w);
    hi[2 * i]     = __half2(h0, h1);
    hi[2 * i + 1] = __half2(h2, h3);
    lo[2 * i]     = __half2(__float2half(v.x - __half2float(h0)),
                            __float2half(v.y - __half2float(h1)));
    lo[2 * i + 1] = __half2(__float2half(v.z - __half2float(h2)),
                            __float2half(v.w - __half2float(h3)));
}

__global__ __launch_bounds__(256) void cvt_hi(
    const float4* __restrict__ src, __half2* __restrict__ hi, int n4)
{
    int i = blockIdx.x * 256 + threadIdx.x;
    if (i >= n4) return;
    float4 v = src[i];
    hi[2 * i]     = __half2(__float2half(v.x), __float2half(v.y));
    hi[2 * i + 1] = __half2(__float2half(v.z), __float2half(v.w));
}

// ---------------- seq reductions: deterministic 2-stage ----------------------
__global__ __launch_bounds__(128) void reduce_stage1(int phase)
{
    int chunk = blockIdx.x;
    int bh    = blockIdx.y;
    int b = bh >> 3, h = bh & 7;
    int tid = threadIdx.x;
    int isk = tid >> 6;
    int d   = tid & 63;
    int s0  = chunk * (SS / 16);

    const float* base = g_qkv + ((size_t)(b * SS + s0)) * QW + h * 192 + isk * 64 + d;
    float acc = 0.f;
    if (phase == 0) {
        for (int s = 0; s < SS / 16; s++) acc += base[(size_t)s * QW];
    } else {
        const float* io = g_io + (isk ? (size_t)NT * 8 : 0) + ((size_t)(b * SS + s0)) * 8 + h;
        for (int s = 0; s < SS / 16; s++) acc += base[(size_t)s * QW] / io[(size_t)s * 8];
    }
    g_part[(chunk * 32 + bh) * 128 + tid] = acc;
}

__global__ __launch_bounds__(256) void reduce_stage2(int phase)
{
    int idx = blockIdx.x * 256 + threadIdx.x;
    float acc = 0.f;
#pragma unroll
    for (int c = 0; c < 16; c++) acc += g_part[c * 4096 + idx];
    int bh = idx >> 7, t = idx & 127;
    int isk = t >> 6, d = t & 63;
    g_sums[(size_t)(phase * 2 + isk) * 2048 + bh * 64 + d] = acc;
}

// ---------------- per-token dots: warp per token ------------------------------
__global__ __launch_bounds__(256) void dots_kernel(int phase)
{
    int warp = threadIdx.x >> 5, lane = threadIdx.x & 31;
    int tok  = blockIdx.x * 8 + warp;
    int b    = tok >> 12;

    __shared__ float sQ[8][64], sK[8][64];
    const float* vq = g_sums + (size_t)(phase == 0 ? 1 : 3) * 2048 + b * 512;
    const float* vk = g_sums + (size_t)(phase == 0 ? 0 : 2) * 2048 + b * 512;
    for (int idx = threadIdx.x; idx < 512; idx += 256) {
        sQ[idx >> 6][idx & 63] = vq[idx];
        sK[idx >> 6][idx & 63] = vk[idx];
    }
    __syncthreads();

    const float* tq = g_qkv + (size_t)tok * QW;
    float* outI = (phase == 0 ? g_io : g_hat) + (size_t)tok * 8;
    float* outO = outI + (size_t)NT * 8;

#pragma unroll
    for (int h = 0; h < 8; h++) {
        const float* qh = tq + h * 192;
        float vi = qh[lane] * sQ[h][lane] + qh[lane + 32] * sQ[h][lane + 32];
        float vo = qh[64 + lane] * sK[h][lane] + qh[64 + lane + 32] * sK[h][lane + 32];
#pragma unroll
        for (int off = 16; off; off >>= 1) {
            vi += __shfl_down_sync(0xFFFFFFFFu, vi, off);
            vo += __shfl_down_sync(0xFFFFFFFFu, vo, off);
        }
        if (lane == 0) { outI[h] = vi; outO[h] = vo; }
    }
}

// ---------------- softmax stats over seq per (b,h) ---------------------------
__global__ __launch_bounds__(256) void softmax_stats()
{
    int bh = blockIdx.x;
    int b = bh >> 3, h = bh & 7;
    __shared__ float red[256];
    const float* oh = g_hat + (size_t)NT * 8 + (size_t)b * SS * 8 + h;

    float m = -1e30f;
    for (int s = threadIdx.x; s < SS; s += 256) m = fmaxf(m, oh[(size_t)s * 8]);
    red[threadIdx.x] = m; __syncthreads();
    for (int o = 128; o; o >>= 1) {
        if (threadIdx.x < o) red[threadIdx.x] = fmaxf(red[threadIdx.x], red[threadIdx.x + o]);
        __syncthreads();
    }
    m = red[0]; __syncthreads();

    float sum = 0.f;
    for (int s = threadIdx.x; s < SS; s += 256) sum += expf(oh[(size_t)s * 8] - m);
    red[threadIdx.x] = sum; __syncthreads();
    for (int o = 128; o; o >>= 1) {
        if (threadIdx.x < o) red[threadIdx.x] += red[threadIdx.x + o];
        __syncthreads();
    }
    if (threadIdx.x == 0) { g_sm[bh] = m; g_sm[32 + bh] = red[0]; }
}

// -------- fused flow-attention core (emits scaled fp16 hi/lo values) ---------
__global__ __launch_bounds__(256) void token_kernel()
{
    int lt = threadIdx.x >> 6;
    int e  = threadIdx.x & 63;
    int tok = blockIdx.x * 4 + lt;
    int b   = tok >> 12;

    __shared__ float qi[4][8][65], kk[4][8][65], vw[4][8][65];
    __shared__ float Am[4][8][9];
    __shared__ float s_invi[4][8], s_sig[4][8], s_sm[4][8];

    const float* tq = g_qkv + (size_t)tok * QW;
    if (e < 8) {
        int h = e;
        float iv = g_io[(size_t)tok * 8 + h];
        float ih = g_hat[(size_t)tok * 8 + h];
        float oh = g_hat[(size_t)NT * 8 + (size_t)tok * 8 + h];
        int bh = b * 8 + h;
        s_invi[lt][h] = 1.0f / iv;
        s_sig[lt][h]  = 1.0f / (1.0f + expf(-ih));
        s_sm[lt][h]   = expf(oh - g_sm[bh]) / g_sm[32 + bh];
    }
    __syncthreads();

#pragma unroll
    for (int h = 0; h < 8; h++) {
        qi[lt][h][e] = tq[h * 192 + e] * s_invi[lt][h];
        kk[lt][h][e] = tq[h * 192 + 64 + e];
        vw[lt][h][e] = tq[h * 192 + 128 + e] * s_sm[lt][h];
    }
    __syncthreads();

    {
        int h = e >> 3, h2 = e & 7;
        float a = 0.f;
#pragma unroll 8
        for (int d = 0; d < 64; d++) a = fmaf(qi[lt][h][d], kk[lt][h2][d], a);
        Am[lt][h][h2] = a;
    }
    __syncthreads();

    __half* ovh = g_vhi + (size_t)tok * EE;
    __half* ovl = g_vlo + (size_t)tok * EE;
#pragma unroll
    for (int h = 0; h < 8; h++) {
        float acc = 0.f;
#pragma unroll
        for (int h2 = 0; h2 < 8; h2++) acc = fmaf(Am[lt][h][h2], vw[lt][h2][e], acc);
        // scale by 2^20 so fp16 hi/lo stay in the normal range (values ~1e-7)
        float vs = acc * s_sig[lt][h] * VAL_SCALE;
        __half hv = __float2half(vs);
        ovh[h * 64 + e] = hv;
        ovl[h * 64 + e] = __float2half(vs - __half2float(hv));
    }
}

// ---------------- launch ------------------------------------------------------
extern "C" void kernel_launch(void* const* d_in, const int* in_sizes, int n_in,
                              void* d_out, int out_size)
{
    (void)in_sizes; (void)n_in; (void)out_size;
    const float* x     = (const float*)d_in[0];
    const float* W_qkv = (const float*)d_in[1];
    const float* b_qkv = (const float*)d_in[2];
    const float* W_out = (const float*)d_in[3];
    const float* b_out = (const float*)d_in[4];
    float* out = (float*)d_out;

    float* p_qkv = nullptr;
    cudaGetSymbolAddress((void**)&p_qkv, g_qkv);
    __half *p_xhi, *p_xlo, *p_whi, *p_wohi, *p_vhi, *p_vlo;
    cudaGetSymbolAddress((void**)&p_xhi,  g_xhi);
    cudaGetSymbolAddress((void**)&p_xlo,  g_xlo);
    cudaGetSymbolAddress((void**)&p_whi,  g_whi);
    cudaGetSymbolAddress((void**)&p_wohi, g_wohi);
    cudaGetSymbolAddress((void**)&p_vhi,  g_vhi);
    cudaGetSymbolAddress((void**)&p_vlo,  g_vlo);

    cudaFuncSetAttribute(hmma_gemm, cudaFuncAttributeMaxDynamicSharedMemorySize,
                         SMEM_GEMM);

    // 0) convert operands to fp16 hi/lo
    {
        int n4 = NT * EE / 4;
        cvt_split<<<(n4 + 255) / 256, 256>>>((const float4*)x,
                                             (__half2*)p_xhi, (__half2*)p_xlo, n4);
        int w4 = QW * EE / 4;
        cvt_hi<<<(w4 + 255) / 256, 256>>>((const float4*)W_qkv, (__half2*)p_whi, w4);
        int o4 = EE * EE / 4;
        cvt_hi<<<(o4 + 255) / 256, 256>>>((const float4*)W_out, (__half2*)p_wohi, o4);
    }
    // 1) QKV projection (HMMA split-fp16) + sigmoid(q,k) epilogue
    hmma_gemm<<<dim3(QW / 128, NT / 128), 256, SMEM_GEMM>>>(
        p_xhi, p_xlo, p_whi, b_qkv, p_qkv, QW, EE, 1, 1.0f);
    // 2) sumQ/sumK over seq
    reduce_stage1<<<dim3(16, 32), 128>>>(0);
    reduce_stage2<<<16, 256>>>(0);
    // 3) i, o per (token, head)
    dots_kernel<<<NT / 8, 256>>>(0);
    // 4) sqd = sum q/i, skd = sum k/o
    reduce_stage1<<<dim3(16, 32), 128>>>(1);
    reduce_stage2<<<16, 256>>>(1);
    // 5) ihat, ohat
    dots_kernel<<<NT / 8, 256>>>(1);
    // 6) softmax stats
    softmax_stats<<<32, 256>>>();
    // 7) fused flow-attention core -> scaled values (fp16 hi/lo)
    token_kernel<<<NT / 4, 256>>>();
    // 8) output projection (HMMA split-fp16), unscale in epilogue
    hmma_gemm<<<dim3(EE / 128, NT / 128), 256, SMEM_GEMM>>>(
        p_vhi, p_vlo, p_wohi, b_out, out, EE, EE, 0, VAL_INV_SCALE);
}

// round 11
// speedup vs baseline: 1.2593x; 1.1125x over previous
#include <cuda_runtime.h>
#include <cuda_fp16.h>
#include <math.h>
#include <stdint.h>

// Problem constants (fixed by the reference)
#define BB   4
#define SS   4096
#define EE   512
#define HH   8
#define DD   64
#define NT   (BB*SS)        // 16384 tokens
#define QW   1536           // 3*E

#define VAL_SCALE     1048576.0f          // 2^20: lift values out of fp16 subnormals
#define VAL_INV_SCALE (1.0f / 1048576.0f)

// ---------------- scratch (static device globals; no allocation) -------------
__device__ float g_qkv[(size_t)NT * QW];   // sig(q), sig(k), raw v  (96 MB)
__device__ float g_sums[4 * 32 * 64];      // [sumQ, sumK, sqd, skd] x bh x d
__device__ float g_part[16 * 32 * 128];    // phase0 stage1 partials
__device__ float g_part2[(size_t)2048 * 1024]; // dots_fused warp partials (8 MB)
__device__ float g_io[(size_t)NT * HH * 2];
__device__ float g_hat[(size_t)NT * HH * 2];
__device__ float g_sm[64];
// fp16 hi/lo GEMM operands
__device__ __half g_xhi[(size_t)NT * EE];
__device__ __half g_xlo[(size_t)NT * EE];
__device__ __half g_whi[(size_t)QW * EE];   // W_qkv hi
__device__ __half g_wohi[(size_t)EE * EE];  // W_out hi
__device__ __half g_vhi[(size_t)NT * EE];   // values*2^20 hi (GEMM2 A)
__device__ __half g_vlo[(size_t)NT * EE];   // values*2^20 lo

// ===================== portable PTX helpers (sm_80+) =========================
__device__ __forceinline__ uint32_t smem_u32(const void* p) {
    uint32_t a;
    asm("{ .reg .u64 t; cvta.to.shared.u64 t, %1; cvt.u32.u64 %0, t; }"
        : "=r"(a) : "l"(p));
    return a;
}
#define LDSM_X4(r0, r1, r2, r3, addr) \
    asm volatile("ldmatrix.sync.aligned.m8n8.x4.shared.b16 {%0,%1,%2,%3}, [%4];" \
        : "=r"(r0), "=r"(r1), "=r"(r2), "=r"(r3) : "r"(addr))
#define MMA_F16(d, a, b) \
    asm volatile("mma.sync.aligned.m16n8k16.row.col.f32.f16.f16.f32 " \
        "{%0,%1,%2,%3},{%4,%5,%6,%7},{%8,%9},{%0,%1,%2,%3};" \
        : "+f"((d)[0]), "+f"((d)[1]), "+f"((d)[2]), "+f"((d)[3]) \
        : "r"((a)[0]), "r"((a)[1]), "r"((a)[2]), "r"((a)[3]), \
          "r"((b)[0]), "r"((b)[1]))
#define CP_ASYNC16(dst, src) \
    asm volatile("cp.async.cg.shared.global [%0], [%1], 16;" \
        :: "r"(dst), "l"(src))
#define CP_COMMIT() asm volatile("cp.async.commit_group;" ::: "memory")
#define CP_WAIT(n)  asm volatile("cp.async.wait_group %0;" :: "n"(n) : "memory")

// SMEM geometry (BK=64): rows of 64 fp16 (128B) padded to 144B. The 8 row
// addresses of each ldmatrix phase differ by r*144 ≡ r*16 (mod 128) — all
// distinct 16B banks, conflict-free without swizzle math.
#define PITCH_B   144u
#define PLANE_B   18432u               // 128 rows * 144B
#define STAGE_B   55296u               // Ahi, Alo, Bhi planes
#define NSTAGE    2
#define SMEM_GEMM (NSTAGE * STAGE_B)   // 110592 bytes -> 2 CTAs per SM

// ======== HMMA split-fp16 GEMM: C[m,n] = sum_k A[m,k]B[n,k] + bias[n] ========
// A supplied as fp16 hi+lo, B as fp16 hi. 2 products: Ahi*Bhi + Alo*Bhi.
// 128x128 tile, BK=64, 256 threads = 8 warps (2M x 4N), warp tile 64x32.
__device__ __forceinline__ void issue_stage(
    uint32_t sbase, int stage, int k0,
    const __half* __restrict__ ahi, const __half* __restrict__ alo,
    const __half* __restrict__ bhi, int K, int tid)
{
    const uint32_t sb = sbase + (uint32_t)stage * STAGE_B;
#pragma unroll
    for (int it = 0; it < 12; it++) {
        int idx   = it * 256 + tid;          // 0..3071
        int plane = idx >> 10;               // 0..2 (1024 16B-chunks per plane)
        int rc    = idx & 1023;
        int row   = rc >> 3;
        int c     = rc & 7;
        uint32_t dst = sb + (uint32_t)plane * PLANE_B
                     + (uint32_t)row * PITCH_B + (uint32_t)c * 16u;
        const __half* src = (plane == 0 ? ahi : (plane == 1 ? alo : bhi))
                          + (size_t)row * K + k0 + c * 8;
        CP_ASYNC16(dst, src);
    }
}

__global__ __launch_bounds__(256, 2) void hmma_gemm(
    const __half* __restrict__ Ahi, const __half* __restrict__ Alo,
    const __half* __restrict__ Bhi,
    const float* __restrict__ bias, float* __restrict__ C,
    int N, int K, int sigmode, float ascale)
{
    extern __shared__ char dynsmem[];
    const uint32_t sbase = smem_u32(dynsmem);

    const int tid   = threadIdx.x;
    const int warp  = tid >> 5;
    const int lane  = tid & 31;
    const int warpM = warp & 1;        // 2 x 64-row slabs
    const int warpN = warp >> 1;       // 4 x 32-col slabs

    const __half* ahi = Ahi + (size_t)blockIdx.y * 128 * K;
    const __half* alo = Alo + (size_t)blockIdx.y * 128 * K;
    const __half* bhi = Bhi + (size_t)blockIdx.x * 128 * K;

    float acc[16][4];
#pragma unroll
    for (int i = 0; i < 16; i++)
#pragma unroll
        for (int j = 0; j < 4; j++) acc[i][j] = 0.f;

    const int NC = K >> 6;   // chunks of 64

    const uint32_t a_lane = (uint32_t)(warpM * 64 + (lane & 15)) * PITCH_B
                          + (uint32_t)((lane >> 4) * 16);
    const uint32_t b_lane = 2u * PLANE_B
                          + (uint32_t)(warpN * 32 + (lane & 7) + ((lane >> 4) & 1) * 8) * PITCH_B
                          + (uint32_t)(((lane >> 3) & 1) * 16);

    // prologue: fill stage 0
    issue_stage(sbase, 0, 0, ahi, alo, bhi, K, tid);
    CP_COMMIT();

    for (int c = 0; c < NC; c++) {
        CP_WAIT(0);
        __syncthreads();   // stage c resident; other slot free for refill
        if (c + 1 < NC)
            issue_stage(sbase, (c + 1) & 1, (c + 1) * 64, ahi, alo, bhi, K, tid);
        CP_COMMIT();

        const uint32_t cur = sbase + (uint32_t)(c & 1) * STAGE_B;
#pragma unroll
        for (int ks = 0; ks < 4; ks++) {
            const uint32_t koff = (uint32_t)ks * 32u;   // 16 fp16 = 32B
            uint32_t bh[4][2];
#pragma unroll
            for (int p = 0; p < 2; p++) {
                uint32_t addr = cur + b_lane + (uint32_t)(p * 16) * PITCH_B + koff;
                LDSM_X4(bh[2*p][0], bh[2*p][1], bh[2*p+1][0], bh[2*p+1][1], addr);
            }
            // A-fragment double buffer: load mi+1 while issuing mi's MMAs
            uint32_t ah[2][4], al[2][4];
            {
                uint32_t addr = cur + a_lane + koff;
                LDSM_X4(ah[0][0], ah[0][1], ah[0][2], ah[0][3], addr);
                LDSM_X4(al[0][0], al[0][1], al[0][2], al[0][3], addr + PLANE_B);
            }
#pragma unroll
            for (int mi = 0; mi < 4; mi++) {
                const int cu = mi & 1, nx = cu ^ 1;
                if (mi < 3) {
                    uint32_t addr = cur + a_lane
                                  + (uint32_t)((mi + 1) * 16) * PITCH_B + koff;
                    LDSM_X4(ah[nx][0], ah[nx][1], ah[nx][2], ah[nx][3], addr);
                    LDSM_X4(al[nx][0], al[nx][1], al[nx][2], al[nx][3], addr + PLANE_B);
                }
                // hi sweep then lo sweep: accumulator reuse distance 4, not 1
#pragma unroll
                for (int ni = 0; ni < 4; ni++)
                    MMA_F16(acc[mi * 4 + ni], ah[cu], bh[ni]);
#pragma unroll
                for (int ni = 0; ni < 4; ni++)
                    MMA_F16(acc[mi * 4 + ni], al[cu], bh[ni]);
            }
        }
    }

    // ---- epilogue: unscale + bias + optional sigmoid ----
#pragma unroll
    for (int mi = 0; mi < 4; mi++) {
        const int r0 = blockIdx.y * 128 + warpM * 64 + mi * 16 + (lane >> 2);
#pragma unroll
        for (int ni = 0; ni < 4; ni++) {
            const int col = blockIdx.x * 128 + warpN * 32 + ni * 8 + (lane & 3) * 2;
            const float b0 = __ldg(bias + col);
            const float b1 = __ldg(bias + col + 1);
            const bool s0 = sigmode && ((col % 192) < 128);
            const bool s1 = sigmode && (((col + 1) % 192) < 128);
            float v0 = acc[mi * 4 + ni][0] * ascale + b0;
            float v1 = acc[mi * 4 + ni][1] * ascale + b1;
            float v2 = acc[mi * 4 + ni][2] * ascale + b0;
            float v3 = acc[mi * 4 + ni][3] * ascale + b1;
            if (s0) { v0 = 1.f / (1.f + __expf(-v0)); v2 = 1.f / (1.f + __expf(-v2)); }
            if (s1) { v1 = 1.f / (1.f + __expf(-v1)); v3 = 1.f / (1.f + __expf(-v3)); }
            *(float2*)(C + (size_t)r0 * N + col)       = make_float2(v0, v1);
            *(float2*)(C + (size_t)(r0 + 8) * N + col) = make_float2(v2, v3);
        }
    }
}

// ---------------- fp32 -> fp16 hi/lo converters -------------------------------
__global__ __launch_bounds__(256) void cvt_split(
    const float4* __restrict__ src, __half2* __restrict__ hi,
    __half2* __restrict__ lo, int n4)
{
    int i = blockIdx.x * 256 + threadIdx.x;
    if (i >= n4) return;
    float4 v = src[i];
    __half h0 = __float2half(v.x), h1 = __float2half(v.y);
    __half h2 = __float2half(v.z), h3 = __float2half(v.w);
    hi[2 * i]     = __half2(h0, h1);
    hi[2 * i + 1] = __half2(h2, h3);
    lo[2 * i]     = __half2(__float2half(v.x - __half2float(h0)),
                            __float2half(v.y - __half2float(h1)));
    lo[2 * i + 1] = __half2(__float2half(v.z - __half2float(h2)),
                            __float2half(v.w - __half2float(h3)));
}

__global__ __launch_bounds__(256) void cvt_hi(
    const float4* __restrict__ src, __half2* __restrict__ hi, int n4)
{
    int i = blockIdx.x * 256 + threadIdx.x;
    if (i >= n4) return;
    float4 v = src[i];
    hi[2 * i]     = __half2(__float2half(v.x), __float2half(v.y));
    hi[2 * i + 1] = __half2(__float2half(v.z), __float2half(v.w));
}

// ---------------- phase-0 seq reductions (sumQ/sumK): 2-stage ----------------
__global__ __launch_bounds__(128) void reduce_stage1()
{
    int chunk = blockIdx.x;
    int bh    = blockIdx.y;
    int b = bh >> 3, h = bh & 7;
    int tid = threadIdx.x;
    int isk = tid >> 6;
    int d   = tid & 63;
    int s0  = chunk * (SS / 16);

    const float* base = g_qkv + ((size_t)(b * SS + s0)) * QW + h * 192 + isk * 64 + d;
    float acc = 0.f;
    for (int s = 0; s < SS / 16; s++) acc += base[(size_t)s * QW];
    g_part[(chunk * 32 + bh) * 128 + tid] = acc;
}

__global__ __launch_bounds__(256) void reduce_stage2()
{
    int idx = blockIdx.x * 256 + threadIdx.x;
    float acc = 0.f;
#pragma unroll
    for (int c = 0; c < 16; c++) acc += g_part[c * 4096 + idx];
    int bh = idx >> 7, t = idx & 127;
    int isk = t >> 6, d = t & 63;
    g_sums[(size_t)isk * 2048 + bh * 64 + d] = acc;   // slot0=sumQ, slot1=sumK
}

// ------- fused dots(i,o) + partial accumulation of q/i, k/o -------------------
// 256 blocks x 256 threads; warp handles 8 consecutive tokens (block: 64).
__global__ __launch_bounds__(256) void dots_fused()
{
    int warp = threadIdx.x >> 5, lane = threadIdx.x & 31;
    int blk  = blockIdx.x;
    int b    = blk >> 6;

    __shared__ float sQ[8][64], sK[8][64];
    const float* vq = g_sums + (size_t)1 * 2048 + b * 512;   // sumK (dot q)
    const float* vk = g_sums + (size_t)0 * 2048 + b * 512;   // sumQ (dot k)
    for (int idx = threadIdx.x; idx < 512; idx += 256) {
        sQ[idx >> 6][idx & 63] = vq[idx];
        sK[idx >> 6][idx & 63] = vk[idx];
    }
    __syncthreads();

    float pq0[8], pq1[8], pk0[8], pk1[8];
#pragma unroll
    for (int h = 0; h < 8; h++) { pq0[h] = pq1[h] = pk0[h] = pk1[h] = 0.f; }

    for (int t = 0; t < 8; t++) {
        int tok = blk * 64 + warp * 8 + t;
        const float* tq = g_qkv + (size_t)tok * QW;
        float* outI = g_io + (size_t)tok * 8;
        float* outO = outI + (size_t)NT * 8;
#pragma unroll
        for (int h = 0; h < 8; h++) {
            const float* qh = tq + h * 192;
            float qlo = qh[lane],      qhi_ = qh[lane + 32];
            float klo = qh[64 + lane], khi  = qh[64 + lane + 32];
            float vi = qlo * sQ[h][lane] + qhi_ * sQ[h][lane + 32];
            float vo = klo * sK[h][lane] + khi  * sK[h][lane + 32];
#pragma unroll
            for (int off = 16; off; off >>= 1) {
                vi += __shfl_xor_sync(0xFFFFFFFFu, vi, off);
                vo += __shfl_xor_sync(0xFFFFFFFFu, vo, off);
            }
            float ri = 1.0f / vi, ro = 1.0f / vo;
            pq0[h] += qlo * ri;  pq1[h] += qhi_ * ri;
            pk0[h] += klo * ro;  pk1[h] += khi  * ro;
            if (lane == 0) { outI[h] = vi; outO[h] = vo; }
        }
    }

    // per-warp partials -> global
    float* p = g_part2 + (size_t)(blk * 8 + warp) * 1024;
#pragma unroll
    for (int h = 0; h < 8; h++) {
        p[h * 64 + lane]             = pq0[h];
        p[h * 64 + lane + 32]        = pq1[h];
        p[512 + h * 64 + lane]       = pk0[h];
        p[512 + h * 64 + lane + 32]  = pk1[h];
    }
}

// combine warp partials -> sqd (slot2), skd (slot3)
__global__ __launch_bounds__(256) void part2_reduce()
{
    int idx = blockIdx.x * 256 + threadIdx.x;   // 0..4095
    int b   = idx >> 10;
    int off = idx & 1023;
    const float* p = g_part2 + (size_t)b * 512 * 1024 + off;
    float acc = 0.f;
    for (int j = 0; j < 512; j++) acc += p[(size_t)j * 1024];
    int side = off >> 9;          // 0 = q -> sqd, 1 = k -> skd
    int hd   = off & 511;
    g_sums[(size_t)(2 + side) * 2048 + b * 512 + hd] = acc;
}

// ---------------- dots phase 1 (ihat, ohat): warp per token -------------------
__global__ __launch_bounds__(256) void dots_kernel()
{
    int warp = threadIdx.x >> 5, lane = threadIdx.x & 31;
    int tok  = blockIdx.x * 8 + warp;
    int b    = tok >> 12;

    __shared__ float sQ[8][64], sK[8][64];
    const float* vq = g_sums + (size_t)3 * 2048 + b * 512;   // skd (dot q)
    const float* vk = g_sums + (size_t)2 * 2048 + b * 512;   // sqd (dot k)
    for (int idx = threadIdx.x; idx < 512; idx += 256) {
        sQ[idx >> 6][idx & 63] = vq[idx];
        sK[idx >> 6][idx & 63] = vk[idx];
    }
    __syncthreads();

    const float* tq = g_qkv + (size_t)tok * QW;
    float* outI = g_hat + (size_t)tok * 8;
    float* outO = outI + (size_t)NT * 8;

#pragma unroll
    for (int h = 0; h < 8; h++) {
        const float* qh = tq + h * 192;
        float vi = qh[lane] * sQ[h][lane] + qh[lane + 32] * sQ[h][lane + 32];
        float vo = qh[64 + lane] * sK[h][lane] + qh[64 + lane + 32] * sK[h][lane + 32];
#pragma unroll
        for (int off = 16; off; off >>= 1) {
            vi += __shfl_down_sync(0xFFFFFFFFu, vi, off);
            vo += __shfl_down_sync(0xFFFFFFFFu, vo, off);
        }
        if (lane == 0) { outI[h] = vi; outO[h] = vo; }
    }
}

// ---------------- softmax stats over seq per (b,h) ---------------------------
__global__ __launch_bounds__(256) void softmax_stats()
{
    int bh = blockIdx.x;
    int b = bh >> 3, h = bh & 7;
    __shared__ float red[256];
    const float* oh = g_hat + (size_t)NT * 8 + (size_t)b * SS * 8 + h;

    float m = -1e30f;
    for (int s = threadIdx.x; s < SS; s += 256) m = fmaxf(m, oh[(size_t)s * 8]);
    red[threadIdx.x] = m; __syncthreads();
    for (int o = 128; o; o >>= 1) {
        if (threadIdx.x < o) red[threadIdx.x] = fmaxf(red[threadIdx.x], red[threadIdx.x + o]);
        __syncthreads();
    }
    m = red[0]; __syncthreads();

    float sum = 0.f;
    for (int s = threadIdx.x; s < SS; s += 256) sum += expf(oh[(size_t)s * 8] - m);
    red[threadIdx.x] = sum; __syncthreads();
    for (int o = 128; o; o >>= 1) {
        if (threadIdx.x < o) red[threadIdx.x] += red[threadIdx.x + o];
        __syncthreads();
    }
    if (threadIdx.x == 0) { g_sm[bh] = m; g_sm[32 + bh] = red[0]; }
}

// -------- fused flow-attention core (emits scaled fp16 hi/lo values) ---------
__global__ __launch_bounds__(256) void token_kernel()
{
    int lt = threadIdx.x >> 6;
    int e  = threadIdx.x & 63;
    int tok = blockIdx.x * 4 + lt;
    int b   = tok >> 12;

    __shared__ float qi[4][8][65], kk[4][8][65], vw[4][8][65];
    __shared__ float Am[4][8][9];
    __shared__ float s_invi[4][8], s_sig[4][8], s_sm[4][8];

    const float* tq = g_qkv + (size_t)tok * QW;
    if (e < 8) {
        int h = e;
        float iv = g_io[(size_t)tok * 8 + h];
        float ih = g_hat[(size_t)tok * 8 + h];
        float oh = g_hat[(size_t)NT * 8 + (size_t)tok * 8 + h];
        int bh = b * 8 + h;
        s_invi[lt][h] = 1.0f / iv;
        s_sig[lt][h]  = 1.0f / (1.0f + expf(-ih));
        s_sm[lt][h]   = expf(oh - g_sm[bh]) / g_sm[32 + bh];
    }
    __syncthreads();

#pragma unroll
    for (int h = 0; h < 8; h++) {
        qi[lt][h][e] = tq[h * 192 + e] * s_invi[lt][h];
        kk[lt][h][e] = tq[h * 192 + 64 + e];
        vw[lt][h][e] = tq[h * 192 + 128 + e] * s_sm[lt][h];
    }
    __syncthreads();

    {
        int h = e >> 3, h2 = e & 7;
        float a = 0.f;
#pragma unroll 8
        for (int d = 0; d < 64; d++) a = fmaf(qi[lt][h][d], kk[lt][h2][d], a);
        Am[lt][h][h2] = a;
    }
    __syncthreads();

    __half* ovh = g_vhi + (size_t)tok * EE;
    __half* ovl = g_vlo + (size_t)tok * EE;
#pragma unroll
    for (int h = 0; h < 8; h++) {
        float acc = 0.f;
#pragma unroll
        for (int h2 = 0; h2 < 8; h2++) acc = fmaf(Am[lt][h][h2], vw[lt][h2][e], acc);
        float vs = acc * s_sig[lt][h] * VAL_SCALE;
        __half hv = __float2half(vs);
        ovh[h * 64 + e] = hv;
        ovl[h * 64 + e] = __float2half(vs - __half2float(hv));
    }
}

// ---------------- launch ------------------------------------------------------
extern "C" void kernel_launch(void* const* d_in, const int* in_sizes, int n_in,
                              void* d_out, int out_size)
{
    (void)in_sizes; (void)n_in; (void)out_size;
    const float* x     = (const float*)d_in[0];
    const float* W_qkv = (const float*)d_in[1];
    const float* b_qkv = (const float*)d_in[2];
    const float* W_out = (const float*)d_in[3];
    const float* b_out = (const float*)d_in[4];
    float* out = (float*)d_out;

    float* p_qkv = nullptr;
    cudaGetSymbolAddress((void**)&p_qkv, g_qkv);
    __half *p_xhi, *p_xlo, *p_whi, *p_wohi, *p_vhi, *p_vlo;
    cudaGetSymbolAddress((void**)&p_xhi,  g_xhi);
    cudaGetSymbolAddress((void**)&p_xlo,  g_xlo);
    cudaGetSymbolAddress((void**)&p_whi,  g_whi);
    cudaGetSymbolAddress((void**)&p_wohi, g_wohi);
    cudaGetSymbolAddress((void**)&p_vhi,  g_vhi);
    cudaGetSymbolAddress((void**)&p_vlo,  g_vlo);

    cudaFuncSetAttribute(hmma_gemm, cudaFuncAttributeMaxDynamicSharedMemorySize,
                         SMEM_GEMM);

    // 0) convert operands to fp16 hi/lo
    {
        int n4 = NT * EE / 4;
        cvt_split<<<(n4 + 255) / 256, 256>>>((const float4*)x,
                                             (__half2*)p_xhi, (__half2*)p_xlo, n4);
        int w4 = QW * EE / 4;
        cvt_hi<<<(w4 + 255) / 256, 256>>>((const float4*)W_qkv, (__half2*)p_whi, w4);
        int o4 = EE * EE / 4;
        cvt_hi<<<(o4 + 255) / 256, 256>>>((const float4*)W_out, (__half2*)p_wohi, o4);
    }
    // 1) QKV projection (HMMA split-fp16) + sigmoid(q,k) epilogue
    hmma_gemm<<<dim3(QW / 128, NT / 128), 256, SMEM_GEMM>>>(
        p_xhi, p_xlo, p_whi, b_qkv, p_qkv, QW, EE, 1, 1.0f);
    // 2) sumQ/sumK over seq
    reduce_stage1<<<dim3(16, 32), 128>>>();
    reduce_stage2<<<16, 256>>>();
    // 3) fused: i,o per token + partial sums of q/i, k/o
    dots_fused<<<NT / 64, 256>>>();
    part2_reduce<<<16, 256>>>();
    // 4) ihat, ohat
    dots_kernel<<<NT / 8, 256>>>();
    // 5) softmax stats
    softmax_stats<<<32, 256>>>();
    // 6) fused flow-attention core -> scaled values (fp16 hi/lo)
    token_kernel<<<NT / 4, 256>>>();
    // 7) output projection (HMMA split-fp16), unscale in epilogue
    hmma_gemm<<<dim3(EE / 128, NT / 128), 256, SMEM_GEMM>>>(
        p_vhi, p_vlo, p_wohi, b_out, out, EE, EE, 0, VAL_INV_SCALE);
}

// round 12
// speedup vs baseline: 1.5996x; 1.2702x over previous
#include <cuda_runtime.h>
#include <cuda_fp16.h>
#include <math.h>
#include <stdint.h>

// Problem constants (fixed by the reference)
#define BB   4
#define SS   4096
#define EE   512
#define HH   8
#define DD   64
#define NT   (BB*SS)        // 16384 tokens
#define QW   1536           // 3*E

#define VAL_SCALE     1048576.0f          // 2^20: lift values out of fp16 subnormals
#define VAL_INV_SCALE (1.0f / 1048576.0f)

// ---------------- scratch (static device globals; no allocation) -------------
__device__ float g_qkv[(size_t)NT * QW];   // sig(q), sig(k), raw v  (96 MB)
__device__ float g_sums[4 * 32 * 64];      // [sumQ, sumK, sqd, skd] x bh x d
__device__ float g_part[16 * 32 * 128];    // phase0 stage1 partials
__device__ float g_part2[(size_t)2048 * 1024]; // dots_fused warp partials (8 MB)
__device__ float g_io[(size_t)NT * HH * 2];
__device__ float g_hat[(size_t)NT * HH * 2];
__device__ float g_sm[64];
// fp16 GEMM operands (hi only — pure fp16 GEMM path)
__device__ __half g_xhi[(size_t)NT * EE];
__device__ __half g_whi[(size_t)QW * EE];   // W_qkv hi
__device__ __half g_wohi[(size_t)EE * EE];  // W_out hi
__device__ __half g_vhi[(size_t)NT * EE];   // values*2^20 hi (GEMM2 A)

// ===================== portable PTX helpers (sm_80+) =========================
__device__ __forceinline__ uint32_t smem_u32(const void* p) {
    uint32_t a;
    asm("{ .reg .u64 t; cvta.to.shared.u64 t, %1; cvt.u32.u64 %0, t; }"
        : "=r"(a) : "l"(p));
    return a;
}
#define LDSM_X4(r0, r1, r2, r3, addr) \
    asm volatile("ldmatrix.sync.aligned.m8n8.x4.shared.b16 {%0,%1,%2,%3}, [%4];" \
        : "=r"(r0), "=r"(r1), "=r"(r2), "=r"(r3) : "r"(addr))
#define MMA_F16(d, a, b) \
    asm volatile("mma.sync.aligned.m16n8k16.row.col.f32.f16.f16.f32 " \
        "{%0,%1,%2,%3},{%4,%5,%6,%7},{%8,%9},{%0,%1,%2,%3};" \
        : "+f"((d)[0]), "+f"((d)[1]), "+f"((d)[2]), "+f"((d)[3]) \
        : "r"((a)[0]), "r"((a)[1]), "r"((a)[2]), "r"((a)[3]), \
          "r"((b)[0]), "r"((b)[1]))
#define CP_ASYNC16(dst, src) \
    asm volatile("cp.async.cg.shared.global [%0], [%1], 16;" \
        :: "r"(dst), "l"(src))
#define CP_COMMIT() asm volatile("cp.async.commit_group;" ::: "memory")
#define CP_WAIT(n)  asm volatile("cp.async.wait_group %0;" :: "n"(n) : "memory")

// SMEM geometry (BK=64): rows of 64 fp16 (128B) padded to 144B. The 8 row
// addresses of each ldmatrix phase differ by r*144 ≡ r*16 (mod 128) — all
// distinct 16B banks, conflict-free without swizzle math.
#define PITCH_B   144u
#define PLANE_B   18432u               // 128 rows * 144B
#define STAGE_B   36864u               // Ahi + Bhi planes
#define NSTAGE    3
#define SMEM_GEMM (NSTAGE * STAGE_B)   // 110592 bytes -> 2 CTAs per SM

// ========= HMMA fp16 GEMM: C[m,n] = sum_k A[m,k]B[n,k] + bias[n] =============
// 128x128 tile, BK=64, 256 threads = 8 warps (2M x 4N), warp tile 64x32.
__device__ __forceinline__ void issue_stage(
    uint32_t sbase, int stage, int k0,
    const __half* __restrict__ ahi, const __half* __restrict__ bhi,
    int K, int tid)
{
    const uint32_t sb = sbase + (uint32_t)stage * STAGE_B;
#pragma unroll
    for (int it = 0; it < 8; it++) {
        int idx   = it * 256 + tid;          // 0..2047
        int plane = idx >> 10;               // 0..1 (1024 16B-chunks per plane)
        int rc    = idx & 1023;
        int row   = rc >> 3;
        int c     = rc & 7;
        uint32_t dst = sb + (uint32_t)plane * PLANE_B
                     + (uint32_t)row * PITCH_B + (uint32_t)c * 16u;
        const __half* src = (plane == 0 ? ahi : bhi)
                          + (size_t)row * K + k0 + c * 8;
        CP_ASYNC16(dst, src);
    }
}

__global__ __launch_bounds__(256, 2) void hmma_gemm(
    const __half* __restrict__ Ahi, const __half* __restrict__ Bhi,
    const float* __restrict__ bias, float* __restrict__ C,
    int N, int K, int sigmode, float ascale)
{
    extern __shared__ char dynsmem[];
    const uint32_t sbase = smem_u32(dynsmem);

    const int tid   = threadIdx.x;
    const int warp  = tid >> 5;
    const int lane  = tid & 31;
    const int warpM = warp & 1;        // 2 x 64-row slabs
    const int warpN = warp >> 1;       // 4 x 32-col slabs

    const __half* ahi = Ahi + (size_t)blockIdx.y * 128 * K;
    const __half* bhi = Bhi + (size_t)blockIdx.x * 128 * K;

    float acc[16][4];
#pragma unroll
    for (int i = 0; i < 16; i++)
#pragma unroll
        for (int j = 0; j < 4; j++) acc[i][j] = 0.f;

    const int NC = K >> 6;   // chunks of 64

    const uint32_t a_lane = (uint32_t)(warpM * 64 + (lane & 15)) * PITCH_B
                          + (uint32_t)((lane >> 4) * 16);
    const uint32_t b_lane = PLANE_B
                          + (uint32_t)(warpN * 32 + (lane & 7) + ((lane >> 4) & 1) * 8) * PITCH_B
                          + (uint32_t)(((lane >> 3) & 1) * 16);

    // prologue: fill stages 0 and 1
    issue_stage(sbase, 0, 0, ahi, bhi, K, tid);
    CP_COMMIT();
    issue_stage(sbase, 1, 64, ahi, bhi, K, tid);
    CP_COMMIT();

    for (int c = 0; c < NC; c++) {
        CP_WAIT(1);          // stage c complete (one group may stay in flight)
        __syncthreads();
        if (c + 2 < NC)
            issue_stage(sbase, (c + 2) % NSTAGE, (c + 2) * 64, ahi, bhi, K, tid);
        CP_COMMIT();         // unconditional: keeps group accounting uniform

        const uint32_t cur = sbase + (uint32_t)(c % NSTAGE) * STAGE_B;
#pragma unroll
        for (int ks = 0; ks < 4; ks++) {
            const uint32_t koff = (uint32_t)ks * 32u;   // 16 fp16 = 32B
            uint32_t bh[4][2];
#pragma unroll
            for (int p = 0; p < 2; p++) {
                uint32_t addr = cur + b_lane + (uint32_t)(p * 16) * PITCH_B + koff;
                LDSM_X4(bh[2*p][0], bh[2*p][1], bh[2*p+1][0], bh[2*p+1][1], addr);
            }
            // A-fragment double buffer: load mi+1 while issuing mi's MMAs
            uint32_t ah[2][4];
            {
                uint32_t addr = cur + a_lane + koff;
                LDSM_X4(ah[0][0], ah[0][1], ah[0][2], ah[0][3], addr);
            }
#pragma unroll
            for (int mi = 0; mi < 4; mi++) {
                const int cu = mi & 1, nx = cu ^ 1;
                if (mi < 3) {
                    uint32_t addr = cur + a_lane
                                  + (uint32_t)((mi + 1) * 16) * PITCH_B + koff;
                    LDSM_X4(ah[nx][0], ah[nx][1], ah[nx][2], ah[nx][3], addr);
                }
#pragma unroll
                for (int ni = 0; ni < 4; ni++)
                    MMA_F16(acc[mi * 4 + ni], ah[cu], bh[ni]);
            }
        }
    }

    // ---- epilogue: unscale + bias + optional sigmoid ----
#pragma unroll
    for (int mi = 0; mi < 4; mi++) {
        const int r0 = blockIdx.y * 128 + warpM * 64 + mi * 16 + (lane >> 2);
#pragma unroll
        for (int ni = 0; ni < 4; ni++) {
            const int col = blockIdx.x * 128 + warpN * 32 + ni * 8 + (lane & 3) * 2;
            const float b0 = __ldg(bias + col);
            const float b1 = __ldg(bias + col + 1);
            const bool s0 = sigmode && ((col % 192) < 128);
            const bool s1 = sigmode && (((col + 1) % 192) < 128);
            float v0 = acc[mi * 4 + ni][0] * ascale + b0;
            float v1 = acc[mi * 4 + ni][1] * ascale + b1;
            float v2 = acc[mi * 4 + ni][2] * ascale + b0;
            float v3 = acc[mi * 4 + ni][3] * ascale + b1;
            if (s0) { v0 = 1.f / (1.f + __expf(-v0)); v2 = 1.f / (1.f + __expf(-v2)); }
            if (s1) { v1 = 1.f / (1.f + __expf(-v1)); v3 = 1.f / (1.f + __expf(-v3)); }
            *(float2*)(C + (size_t)r0 * N + col)       = make_float2(v0, v1);
            *(float2*)(C + (size_t)(r0 + 8) * N + col) = make_float2(v2, v3);
        }
    }
}

// ---------------- fp32 -> fp16 converter --------------------------------------
__global__ __launch_bounds__(256) void cvt_hi(
    const float4* __restrict__ src, __half2* __restrict__ hi, int n4)
{
    int i = blockIdx.x * 256 + threadIdx.x;
    if (i >= n4) return;
    float4 v = src[i];
    hi[2 * i]     = __half2(__float2half(v.x), __float2half(v.y));
    hi[2 * i + 1] = __half2(__float2half(v.z), __float2half(v.w));
}

// ---------------- phase-0 seq reductions (sumQ/sumK): 2-stage ----------------
__global__ __launch_bounds__(128) void reduce_stage1()
{
    int chunk = blockIdx.x;
    int bh    = blockIdx.y;
    int b = bh >> 3, h = bh & 7;
    int tid = threadIdx.x;
    int isk = tid >> 6;
    int d   = tid & 63;
    int s0  = chunk * (SS / 16);

    const float* base = g_qkv + ((size_t)(b * SS + s0)) * QW + h * 192 + isk * 64 + d;
    float acc = 0.f;
    for (int s = 0; s < SS / 16; s++) acc += base[(size_t)s * QW];
    g_part[(chunk * 32 + bh) * 128 + tid] = acc;
}

__global__ __launch_bounds__(256) void reduce_stage2()
{
    int idx = blockIdx.x * 256 + threadIdx.x;
    float acc = 0.f;
#pragma unroll
    for (int c = 0; c < 16; c++) acc += g_part[c * 4096 + idx];
    int bh = idx >> 7, t = idx & 127;
    int isk = t >> 6, d = t & 63;
    g_sums[(size_t)isk * 2048 + bh * 64 + d] = acc;   // slot0=sumQ, slot1=sumK
}

// ------- fused dots(i,o) + partial accumulation of q/i, k/o -------------------
__global__ __launch_bounds__(256) void dots_fused()
{
    int warp = threadIdx.x >> 5, lane = threadIdx.x & 31;
    int blk  = blockIdx.x;
    int b    = blk >> 6;

    __shared__ float sQ[8][64], sK[8][64];
    const float* vq = g_sums + (size_t)1 * 2048 + b * 512;   // sumK (dot q)
    const float* vk = g_sums + (size_t)0 * 2048 + b * 512;   // sumQ (dot k)
    for (int idx = threadIdx.x; idx < 512; idx += 256) {
        sQ[idx >> 6][idx & 63] = vq[idx];
        sK[idx >> 6][idx & 63] = vk[idx];
    }
    __syncthreads();

    float pq0[8], pq1[8], pk0[8], pk1[8];
#pragma unroll
    for (int h = 0; h < 8; h++) { pq0[h] = pq1[h] = pk0[h] = pk1[h] = 0.f; }

    for (int t = 0; t < 8; t++) {
        int tok = blk * 64 + warp * 8 + t;
        const float* tq = g_qkv + (size_t)tok * QW;
        float* outI = g_io + (size_t)tok * 8;
        float* outO = outI + (size_t)NT * 8;
#pragma unroll
        for (int h = 0; h < 8; h++) {
            const float* qh = tq + h * 192;
            float qlo = qh[lane],      qhi_ = qh[lane + 32];
            float klo = qh[64 + lane], khi  = qh[64 + lane + 32];
            float vi = qlo * sQ[h][lane] + qhi_ * sQ[h][lane + 32];
            float vo = klo * sK[h][lane] + khi  * sK[h][lane + 32];
#pragma unroll
            for (int off = 16; off; off >>= 1) {
                vi += __shfl_xor_sync(0xFFFFFFFFu, vi, off);
                vo += __shfl_xor_sync(0xFFFFFFFFu, vo, off);
            }
            float ri = 1.0f / vi, ro = 1.0f / vo;
            pq0[h] += qlo * ri;  pq1[h] += qhi_ * ri;
            pk0[h] += klo * ro;  pk1[h] += khi  * ro;
            if (lane == 0) { outI[h] = vi; outO[h] = vo; }
        }
    }

    float* p = g_part2 + (size_t)(blk * 8 + warp) * 1024;
#pragma unroll
    for (int h = 0; h < 8; h++) {
        p[h * 64 + lane]             = pq0[h];
        p[h * 64 + lane + 32]        = pq1[h];
        p[512 + h * 64 + lane]       = pk0[h];
        p[512 + h * 64 + lane + 32]  = pk1[h];
    }
}

// combine warp partials -> sqd (slot2), skd (slot3)
__global__ __launch_bounds__(256) void part2_reduce()
{
    int idx = blockIdx.x * 256 + threadIdx.x;   // 0..4095
    int b   = idx >> 10;
    int off = idx & 1023;
    const float* p = g_part2 + (size_t)b * 512 * 1024 + off;
    float acc = 0.f;
    for (int j = 0; j < 512; j++) acc += p[(size_t)j * 1024];
    int side = off >> 9;
    int hd   = off & 511;
    g_sums[(size_t)(2 + side) * 2048 + b * 512 + hd] = acc;
}

// ---------------- dots phase 1 (ihat, ohat): warp per token -------------------
__global__ __launch_bounds__(256) void dots_kernel()
{
    int warp = threadIdx.x >> 5, lane = threadIdx.x & 31;
    int tok  = blockIdx.x * 8 + warp;
    int b    = tok >> 12;

    __shared__ float sQ[8][64], sK[8][64];
    const float* vq = g_sums + (size_t)3 * 2048 + b * 512;   // skd (dot q)
    const float* vk = g_sums + (size_t)2 * 2048 + b * 512;   // sqd (dot k)
    for (int idx = threadIdx.x; idx < 512; idx += 256) {
        sQ[idx >> 6][idx & 63] = vq[idx];
        sK[idx >> 6][idx & 63] = vk[idx];
    }
    __syncthreads();

    const float* tq = g_qkv + (size_t)tok * QW;
    float* outI = g_hat + (size_t)tok * 8;
    float* outO = outI + (size_t)NT * 8;

#pragma unroll
    for (int h = 0; h < 8; h++) {
        const float* qh = tq + h * 192;
        float vi = qh[lane] * sQ[h][lane] + qh[lane + 32] * sQ[h][lane + 32];
        float vo = qh[64 + lane] * sK[h][lane] + qh[64 + lane + 32] * sK[h][lane + 32];
#pragma unroll
        for (int off = 16; off; off >>= 1) {
            vi += __shfl_down_sync(0xFFFFFFFFu, vi, off);
            vo += __shfl_down_sync(0xFFFFFFFFu, vo, off);
        }
        if (lane == 0) { outI[h] = vi; outO[h] = vo; }
    }
}

// ---------------- softmax stats over seq per (b,h) ---------------------------
__global__ __launch_bounds__(256) void softmax_stats()
{
    int bh = blockIdx.x;
    int b = bh >> 3, h = bh & 7;
    __shared__ float red[256];
    const float* oh = g_hat + (size_t)NT * 8 + (size_t)b * SS * 8 + h;

    float m = -1e30f;
    for (int s = threadIdx.x; s < SS; s += 256) m = fmaxf(m, oh[(size_t)s * 8]);
    red[threadIdx.x] = m; __syncthreads();
    for (int o = 128; o; o >>= 1) {
        if (threadIdx.x < o) red[threadIdx.x] = fmaxf(red[threadIdx.x], red[threadIdx.x + o]);
        __syncthreads();
    }
    m = red[0]; __syncthreads();

    float sum = 0.f;
    for (int s = threadIdx.x; s < SS; s += 256) sum += expf(oh[(size_t)s * 8] - m);
    red[threadIdx.x] = sum; __syncthreads();
    for (int o = 128; o; o >>= 1) {
        if (threadIdx.x < o) red[threadIdx.x] += red[threadIdx.x + o];
        __syncthreads();
    }
    if (threadIdx.x == 0) { g_sm[bh] = m; g_sm[32 + bh] = red[0]; }
}

// -------- fused flow-attention core (emits scaled fp16 values) ----------------
__global__ __launch_bounds__(256) void token_kernel()
{
    int lt = threadIdx.x >> 6;
    int e  = threadIdx.x & 63;
    int tok = blockIdx.x * 4 + lt;
    int b   = tok >> 12;

    __shared__ float qi[4][8][65], kk[4][8][65], vw[4][8][65];
    __shared__ float Am[4][8][9];
    __shared__ float s_invi[4][8], s_sig[4][8], s_sm[4][8];

    const float* tq = g_qkv + (size_t)tok * QW;
    if (e < 8) {
        int h = e;
        float iv = g_io[(size_t)tok * 8 + h];
        float ih = g_hat[(size_t)tok * 8 + h];
        float oh = g_hat[(size_t)NT * 8 + (size_t)tok * 8 + h];
        int bh = b * 8 + h;
        s_invi[lt][h] = 1.0f / iv;
        s_sig[lt][h]  = 1.0f / (1.0f + expf(-ih));
        s_sm[lt][h]   = expf(oh - g_sm[bh]) / g_sm[32 + bh];
    }
    __syncthreads();

#pragma unroll
    for (int h = 0; h < 8; h++) {
        qi[lt][h][e] = tq[h * 192 + e] * s_invi[lt][h];
        kk[lt][h][e] = tq[h * 192 + 64 + e];
        vw[lt][h][e] = tq[h * 192 + 128 + e] * s_sm[lt][h];
    }
    __syncthreads();

    {
        int h = e >> 3, h2 = e & 7;
        float a = 0.f;
#pragma unroll 8
        for (int d = 0; d < 64; d++) a = fmaf(qi[lt][h][d], kk[lt][h2][d], a);
        Am[lt][h][h2] = a;
    }
    __syncthreads();

    __half* ovh = g_vhi + (size_t)tok * EE;
#pragma unroll
    for (int h = 0; h < 8; h++) {
        float acc = 0.f;
#pragma unroll
        for (int h2 = 0; h2 < 8; h2++) acc = fmaf(Am[lt][h][h2], vw[lt][h2][e], acc);
        // scale by 2^20 so fp16 stays in the normal range (values ~1e-7)
        float vs = acc * s_sig[lt][h] * VAL_SCALE;
        ovh[h * 64 + e] = __float2half(vs);
    }
}

// ---------------- launch ------------------------------------------------------
extern "C" void kernel_launch(void* const* d_in, const int* in_sizes, int n_in,
                              void* d_out, int out_size)
{
    (void)in_sizes; (void)n_in; (void)out_size;
    const float* x     = (const float*)d_in[0];
    const float* W_qkv = (const float*)d_in[1];
    const float* b_qkv = (const float*)d_in[2];
    const float* W_out = (const float*)d_in[3];
    const float* b_out = (const float*)d_in[4];
    float* out = (float*)d_out;

    float* p_qkv = nullptr;
    cudaGetSymbolAddress((void**)&p_qkv, g_qkv);
    __half *p_xhi, *p_whi, *p_wohi, *p_vhi;
    cudaGetSymbolAddress((void**)&p_xhi,  g_xhi);
    cudaGetSymbolAddress((void**)&p_whi,  g_whi);
    cudaGetSymbolAddress((void**)&p_wohi, g_wohi);
    cudaGetSymbolAddress((void**)&p_vhi,  g_vhi);

    cudaFuncSetAttribute(hmma_gemm, cudaFuncAttributeMaxDynamicSharedMemorySize,
                         SMEM_GEMM);

    // 0) convert operands to fp16
    {
        int n4 = NT * EE / 4;
        cvt_hi<<<(n4 + 255) / 256, 256>>>((const float4*)x, (__half2*)p_xhi, n4);
        int w4 = QW * EE / 4;
        cvt_hi<<<(w4 + 255) / 256, 256>>>((const float4*)W_qkv, (__half2*)p_whi, w4);
        int o4 = EE * EE / 4;
        cvt_hi<<<(o4 + 255) / 256, 256>>>((const float4*)W_out, (__half2*)p_wohi, o4);
    }
    // 1) QKV projection (fp16 HMMA) + sigmoid(q,k) epilogue
    hmma_gemm<<<dim3(QW / 128, NT / 128), 256, SMEM_GEMM>>>(
        p_xhi, p_whi, b_qkv, p_qkv, QW, EE, 1, 1.0f);
    // 2) sumQ/sumK over seq
    reduce_stage1<<<dim3(16, 32), 128>>>();
    reduce_stage2<<<16, 256>>>();
    // 3) fused: i,o per token + partial sums of q/i, k/o
    dots_fused<<<NT / 64, 256>>>();
    part2_reduce<<<16, 256>>>();
    // 4) ihat, ohat
    dots_kernel<<<NT / 8, 256>>>();
    // 5) softmax stats
    softmax_stats<<<32, 256>>>();
    // 6) fused flow-attention core -> scaled values (fp16)
    token_kernel<<<NT / 4, 256>>>();
    // 7) output projection (fp16 HMMA), unscale in epilogue
    hmma_gemm<<<dim3(EE / 128, NT / 128), 256, SMEM_GEMM>>>(
        p_vhi, p_wohi, b_out, out, EE, EE, 0, VAL_INV_SCALE);
}

// round 13
// speedup vs baseline: 1.6498x; 1.0314x over previous
#include <cuda_runtime.h>
#include <cuda_fp16.h>
#include <math.h>
#include <stdint.h>

// Problem constants (fixed by the reference)
#define BB   4
#define SS   4096
#define EE   512
#define HH   8
#define DD   64
#define NT   (BB*SS)        // 16384 tokens
#define QW   1536           // 3*E

#define VAL_SCALE     1048576.0f          // 2^20: lift values out of fp16 subnormals
#define VAL_INV_SCALE (1.0f / 1048576.0f)

// ---------------- scratch (static device globals; no allocation) -------------
__device__ float g_qkv[(size_t)NT * QW];   // sig(q), sig(k), raw v  (96 MB)
__device__ float g_sums[4 * 32 * 64];      // [sumQ, sumK, sqd, skd] x bh x d
__device__ float g_csum[128 * QW];         // GEMM1 per-rowblock column sums (768 KB)
__device__ float g_part2[256 * 1024];      // dots_fused block partials (1 MB)
__device__ float g_io[(size_t)NT * HH * 2];
__device__ float g_hat[(size_t)NT * HH * 2];
__device__ float g_sm[64];
// fp16 GEMM operands (hi only — pure fp16 GEMM path)
__device__ __half g_xhi[(size_t)NT * EE];
__device__ __half g_whi[(size_t)QW * EE];   // W_qkv hi
__device__ __half g_wohi[(size_t)EE * EE];  // W_out hi
__device__ __half g_vhi[(size_t)NT * EE];   // values*2^20 hi (GEMM2 A)

// ===================== portable PTX helpers (sm_80+) =========================
__device__ __forceinline__ uint32_t smem_u32(const void* p) {
    uint32_t a;
    asm("{ .reg .u64 t; cvta.to.shared.u64 t, %1; cvt.u32.u64 %0, t; }"
        : "=r"(a) : "l"(p));
    return a;
}
#define LDSM_X4(r0, r1, r2, r3, addr) \
    asm volatile("ldmatrix.sync.aligned.m8n8.x4.shared.b16 {%0,%1,%2,%3}, [%4];" \
        : "=r"(r0), "=r"(r1), "=r"(r2), "=r"(r3) : "r"(addr))
#define MMA_F16(d, a, b) \
    asm volatile("mma.sync.aligned.m16n8k16.row.col.f32.f16.f16.f32 " \
        "{%0,%1,%2,%3},{%4,%5,%6,%7},{%8,%9},{%0,%1,%2,%3};" \
        : "+f"((d)[0]), "+f"((d)[1]), "+f"((d)[2]), "+f"((d)[3]) \
        : "r"((a)[0]), "r"((a)[1]), "r"((a)[2]), "r"((a)[3]), \
          "r"((b)[0]), "r"((b)[1]))
#define CP_ASYNC16(dst, src) \
    asm volatile("cp.async.cg.shared.global [%0], [%1], 16;" \
        :: "r"(dst), "l"(src))
#define CP_COMMIT() asm volatile("cp.async.commit_group;" ::: "memory")
#define CP_WAIT(n)  asm volatile("cp.async.wait_group %0;" :: "n"(n) : "memory")

// SMEM geometry (BK=64): rows of 64 fp16 (128B) padded to 144B. The 8 row
// addresses of each ldmatrix phase differ by r*144 ≡ r*16 (mod 128) — all
// distinct 16B banks, conflict-free without swizzle math.
#define PITCH_B   144u
#define PLANE_B   18432u               // 128 rows * 144B
#define STAGE_B   36864u               // Ahi + Bhi planes
#define NSTAGE    3
#define SMEM_GEMM (NSTAGE * STAGE_B)   // 110592 bytes -> 2 CTAs per SM

// ========= HMMA fp16 GEMM: C[m,n] = sum_k A[m,k]B[n,k] + bias[n] =============
// 128x128 tile, BK=64, 256 threads = 8 warps (2M x 4N), warp tile 64x32.
// sigmode: sigmoid on (n%192)<128 columns AND per-CTA column sums -> g_csum.
__device__ __forceinline__ void issue_stage(
    uint32_t sbase, int stage, int k0,
    const __half* __restrict__ ahi, const __half* __restrict__ bhi,
    int K, int tid)
{
    const uint32_t sb = sbase + (uint32_t)stage * STAGE_B;
#pragma unroll
    for (int it = 0; it < 8; it++) {
        int idx   = it * 256 + tid;          // 0..2047
        int plane = idx >> 10;               // 0..1
        int rc    = idx & 1023;
        int row   = rc >> 3;
        int c     = rc & 7;
        uint32_t dst = sb + (uint32_t)plane * PLANE_B
                     + (uint32_t)row * PITCH_B + (uint32_t)c * 16u;
        const __half* src = (plane == 0 ? ahi : bhi)
                          + (size_t)row * K + k0 + c * 8;
        CP_ASYNC16(dst, src);
    }
}

__global__ __launch_bounds__(256, 2) void hmma_gemm(
    const __half* __restrict__ Ahi, const __half* __restrict__ Bhi,
    const float* __restrict__ bias, float* __restrict__ C,
    int N, int K, int sigmode, float ascale)
{
    extern __shared__ char dynsmem[];
    const uint32_t sbase = smem_u32(dynsmem);

    const int tid   = threadIdx.x;
    const int warp  = tid >> 5;
    const int lane  = tid & 31;
    const int warpM = warp & 1;        // 2 x 64-row slabs
    const int warpN = warp >> 1;       // 4 x 32-col slabs

    const __half* ahi = Ahi + (size_t)blockIdx.y * 128 * K;
    const __half* bhi = Bhi + (size_t)blockIdx.x * 128 * K;

    float acc[16][4];
#pragma unroll
    for (int i = 0; i < 16; i++)
#pragma unroll
        for (int j = 0; j < 4; j++) acc[i][j] = 0.f;

    const int NC = K >> 6;   // chunks of 64

    const uint32_t a_lane = (uint32_t)(warpM * 64 + (lane & 15)) * PITCH_B
                          + (uint32_t)((lane >> 4) * 16);
    const uint32_t b_lane = PLANE_B
                          + (uint32_t)(warpN * 32 + (lane & 7) + ((lane >> 4) & 1) * 8) * PITCH_B
                          + (uint32_t)(((lane >> 3) & 1) * 16);

    // prologue: fill stages 0 and 1
    issue_stage(sbase, 0, 0, ahi, bhi, K, tid);
    CP_COMMIT();
    issue_stage(sbase, 1, 64, ahi, bhi, K, tid);
    CP_COMMIT();

    for (int c = 0; c < NC; c++) {
        CP_WAIT(1);
        __syncthreads();
        if (c + 2 < NC)
            issue_stage(sbase, (c + 2) % NSTAGE, (c + 2) * 64, ahi, bhi, K, tid);
        CP_COMMIT();

        const uint32_t cur = sbase + (uint32_t)(c % NSTAGE) * STAGE_B;
#pragma unroll
        for (int ks = 0; ks < 4; ks++) {
            const uint32_t koff = (uint32_t)ks * 32u;
            uint32_t bh[4][2];
#pragma unroll
            for (int p = 0; p < 2; p++) {
                uint32_t addr = cur + b_lane + (uint32_t)(p * 16) * PITCH_B + koff;
                LDSM_X4(bh[2*p][0], bh[2*p][1], bh[2*p+1][0], bh[2*p+1][1], addr);
            }
            uint32_t ah[2][4];
            {
                uint32_t addr = cur + a_lane + koff;
                LDSM_X4(ah[0][0], ah[0][1], ah[0][2], ah[0][3], addr);
            }
#pragma unroll
            for (int mi = 0; mi < 4; mi++) {
                const int cu = mi & 1, nx = cu ^ 1;
                if (mi < 3) {
                    uint32_t addr = cur + a_lane
                                  + (uint32_t)((mi + 1) * 16) * PITCH_B + koff;
                    LDSM_X4(ah[nx][0], ah[nx][1], ah[nx][2], ah[nx][3], addr);
                }
#pragma unroll
                for (int ni = 0; ni < 4; ni++)
                    MMA_F16(acc[mi * 4 + ni], ah[cu], bh[ni]);
            }
        }
    }

    // ---- epilogue: unscale + bias + optional sigmoid + column sums ----
    float scol0[4], scol1[4];
#pragma unroll
    for (int ni = 0; ni < 4; ni++) { scol0[ni] = 0.f; scol1[ni] = 0.f; }

#pragma unroll
    for (int mi = 0; mi < 4; mi++) {
        const int r0 = blockIdx.y * 128 + warpM * 64 + mi * 16 + (lane >> 2);
#pragma unroll
        for (int ni = 0; ni < 4; ni++) {
            const int col = blockIdx.x * 128 + warpN * 32 + ni * 8 + (lane & 3) * 2;
            const float b0 = __ldg(bias + col);
            const float b1 = __ldg(bias + col + 1);
            const bool s0 = sigmode && ((col % 192) < 128);
            const bool s1 = sigmode && (((col + 1) % 192) < 128);
            float v0 = acc[mi * 4 + ni][0] * ascale + b0;
            float v1 = acc[mi * 4 + ni][1] * ascale + b1;
            float v2 = acc[mi * 4 + ni][2] * ascale + b0;
            float v3 = acc[mi * 4 + ni][3] * ascale + b1;
            if (s0) { v0 = 1.f / (1.f + __expf(-v0)); v2 = 1.f / (1.f + __expf(-v2)); }
            if (s1) { v1 = 1.f / (1.f + __expf(-v1)); v3 = 1.f / (1.f + __expf(-v3)); }
            if (sigmode) { scol0[ni] += v0 + v2; scol1[ni] += v1 + v3; }
            *(float2*)(C + (size_t)r0 * N + col)       = make_float2(v0, v1);
            *(float2*)(C + (size_t)(r0 + 8) * N + col) = make_float2(v2, v3);
        }
    }

    if (sigmode) {
        // reduce over the 8 lanes sharing a column (same lane&3)
#pragma unroll
        for (int ni = 0; ni < 4; ni++) {
#pragma unroll
            for (int off = 4; off <= 16; off <<= 1) {
                scol0[ni] += __shfl_xor_sync(0xFFFFFFFFu, scol0[ni], off);
                scol1[ni] += __shfl_xor_sync(0xFFFFFFFFu, scol1[ni], off);
            }
        }
        float* scs = (float*)dynsmem;   // mainloop smem is dead; [8 warps][32]
        __syncthreads();
        if (lane < 4) {
#pragma unroll
            for (int ni = 0; ni < 4; ni++) {
                scs[warp * 32 + ni * 8 + lane * 2]     = scol0[ni];
                scs[warp * 32 + ni * 8 + lane * 2 + 1] = scol1[ni];
            }
        }
        __syncthreads();
        if (warpM == 0 && lane < 4) {
#pragma unroll
            for (int ni = 0; ni < 4; ni++) {
                int sl = ni * 8 + lane * 2;
                float t0 = scs[warp * 32 + sl]     + scs[(warp + 1) * 32 + sl];
                float t1 = scs[warp * 32 + sl + 1] + scs[(warp + 1) * 32 + sl + 1];
                int colg = blockIdx.x * 128 + warpN * 32 + sl;
                g_csum[blockIdx.y * QW + colg]     = t0;
                g_csum[blockIdx.y * QW + colg + 1] = t1;
            }
        }
    }
}

// ---- finish sumQ/sumK: combine 32 row-block partials per batch --------------
__global__ __launch_bounds__(256) void colsum_finish()
{
    int idx = blockIdx.x * 256 + threadIdx.x;   // 0..4095
    int b    = idx >> 10;
    int slot = idx & 1023;                       // h*128 + isk*64 + d
    int h = slot >> 7, r = slot & 127;
    int isk = r >> 6, d = r & 63;
    int col = h * 192 + isk * 64 + d;
    float acc = 0.f;
#pragma unroll
    for (int j = 0; j < 32; j++)
        acc += g_csum[(b * 32 + j) * QW + col];
    g_sums[(size_t)isk * 2048 + (b * 8 + h) * 64 + d] = acc;
}

// ---------------- fused fp32 -> fp16 converter (x, W_qkv, W_out) --------------
__global__ __launch_bounds__(256) void cvt_all(
    const float4* __restrict__ x, const float4* __restrict__ w,
    const float4* __restrict__ wo,
    __half2* __restrict__ xhi, __half2* __restrict__ whi,
    __half2* __restrict__ wohi)
{
    const int NX = NT * EE / 4, NW = QW * EE / 4, NO = EE * EE / 4;
    int i = blockIdx.x * 256 + threadIdx.x;
    const float4* src; __half2* dst; int j;
    if (i < NX)            { src = x;  dst = xhi;  j = i; }
    else if (i < NX + NW)  { src = w;  dst = whi;  j = i - NX; }
    else if (i < NX + NW + NO) { src = wo; dst = wohi; j = i - NX - NW; }
    else return;
    float4 v = src[j];
    dst[2 * j]     = __half2(__float2half(v.x), __float2half(v.y));
    dst[2 * j + 1] = __half2(__float2half(v.z), __float2half(v.w));
}

// ------- fused dots(i,o) + block-level partial sums of q/i, k/o ---------------
__global__ __launch_bounds__(256) void dots_fused()
{
    int warp = threadIdx.x >> 5, lane = threadIdx.x & 31;
    int blk  = blockIdx.x;
    int b    = blk >> 6;

    __shared__ float sQ[8][64], sK[8][64];
    __shared__ float spart[8][1024];
    const float* vq = g_sums + (size_t)1 * 2048 + b * 512;   // sumK (dot q)
    const float* vk = g_sums + (size_t)0 * 2048 + b * 512;   // sumQ (dot k)
    for (int idx = threadIdx.x; idx < 512; idx += 256) {
        sQ[idx >> 6][idx & 63] = vq[idx];
        sK[idx >> 6][idx & 63] = vk[idx];
    }
    __syncthreads();

    float pq0[8], pq1[8], pk0[8], pk1[8];
#pragma unroll
    for (int h = 0; h < 8; h++) { pq0[h] = pq1[h] = pk0[h] = pk1[h] = 0.f; }

    for (int t = 0; t < 8; t++) {
        int tok = blk * 64 + warp * 8 + t;
        const float* tq = g_qkv + (size_t)tok * QW;
        float* outI = g_io + (size_t)tok * 8;
        float* outO = outI + (size_t)NT * 8;
#pragma unroll
        for (int h = 0; h < 8; h++) {
            const float* qh = tq + h * 192;
            float qlo = qh[lane],      qhi_ = qh[lane + 32];
            float klo = qh[64 + lane], khi  = qh[64 + lane + 32];
            float vi = qlo * sQ[h][lane] + qhi_ * sQ[h][lane + 32];
            float vo = klo * sK[h][lane] + khi  * sK[h][lane + 32];
#pragma unroll
            for (int off = 16; off; off >>= 1) {
                vi += __shfl_xor_sync(0xFFFFFFFFu, vi, off);
                vo += __shfl_xor_sync(0xFFFFFFFFu, vo, off);
            }
            float ri = 1.0f / vi, ro = 1.0f / vo;
            pq0[h] += qlo * ri;  pq1[h] += qhi_ * ri;
            pk0[h] += klo * ro;  pk1[h] += khi  * ro;
            if (lane == 0) { outI[h] = vi; outO[h] = vo; }
        }
    }

#pragma unroll
    for (int h = 0; h < 8; h++) {
        spart[warp][h * 64 + lane]            = pq0[h];
        spart[warp][h * 64 + lane + 32]       = pq1[h];
        spart[warp][512 + h * 64 + lane]      = pk0[h];
        spart[warp][512 + h * 64 + lane + 32] = pk1[h];
    }
    __syncthreads();
    for (int s = threadIdx.x; s < 1024; s += 256) {
        float a = 0.f;
#pragma unroll
        for (int w = 0; w < 8; w++) a += spart[w][s];
        g_part2[blk * 1024 + s] = a;
    }
}

// combine block partials -> sqd (slot2), skd (slot3)
__global__ __launch_bounds__(256) void part2_reduce()
{
    int idx = blockIdx.x * 256 + threadIdx.x;   // 0..4095
    int b   = idx >> 10;
    int off = idx & 1023;
    float acc = 0.f;
#pragma unroll 8
    for (int j = 0; j < 64; j++)
        acc += g_part2[(b * 64 + j) * 1024 + off];
    int side = off >> 9;
    int hd   = off & 511;
    g_sums[(size_t)(2 + side) * 2048 + b * 512 + hd] = acc;
}

// ---------------- dots phase 1 (ihat, ohat): warp per token -------------------
__global__ __launch_bounds__(256) void dots_kernel()
{
    int warp = threadIdx.x >> 5, lane = threadIdx.x & 31;
    int tok  = blockIdx.x * 8 + warp;
    int b    = tok >> 12;

    __shared__ float sQ[8][64], sK[8][64];
    const float* vq = g_sums + (size_t)3 * 2048 + b * 512;   // skd (dot q)
    const float* vk = g_sums + (size_t)2 * 2048 + b * 512;   // sqd (dot k)
    for (int idx = threadIdx.x; idx < 512; idx += 256) {
        sQ[idx >> 6][idx & 63] = vq[idx];
        sK[idx >> 6][idx & 63] = vk[idx];
    }
    __syncthreads();

    const float* tq = g_qkv + (size_t)tok * QW;
    float* outI = g_hat + (size_t)tok * 8;
    float* outO = outI + (size_t)NT * 8;

#pragma unroll
    for (int h = 0; h < 8; h++) {
        const float* qh = tq + h * 192;
        float vi = qh[lane] * sQ[h][lane] + qh[lane + 32] * sQ[h][lane + 32];
        float vo = qh[64 + lane] * sK[h][lane] + qh[64 + lane + 32] * sK[h][lane + 32];
#pragma unroll
        for (int off = 16; off; off >>= 1) {
            vi += __shfl_down_sync(0xFFFFFFFFu, vi, off);
            vo += __shfl_down_sync(0xFFFFFFFFu, vo, off);
        }
        if (lane == 0) { outI[h] = vi; outO[h] = vo; }
    }
}

// ---------------- softmax stats over seq per (b,h) ---------------------------
__global__ __launch_bounds__(256) void softmax_stats()
{
    int bh = blockIdx.x;
    int b = bh >> 3, h = bh & 7;
    __shared__ float red[256];
    const float* oh = g_hat + (size_t)NT * 8 + (size_t)b * SS * 8 + h;

    float m = -1e30f;
    for (int s = threadIdx.x; s < SS; s += 256) m = fmaxf(m, oh[(size_t)s * 8]);
    red[threadIdx.x] = m; __syncthreads();
    for (int o = 128; o; o >>= 1) {
        if (threadIdx.x < o) red[threadIdx.x] = fmaxf(red[threadIdx.x], red[threadIdx.x + o]);
        __syncthreads();
    }
    m = red[0]; __syncthreads();

    float sum = 0.f;
    for (int s = threadIdx.x; s < SS; s += 256) sum += expf(oh[(size_t)s * 8] - m);
    red[threadIdx.x] = sum; __syncthreads();
    for (int o = 128; o; o >>= 1) {
        if (threadIdx.x < o) red[threadIdx.x] += red[threadIdx.x + o];
        __syncthreads();
    }
    if (threadIdx.x == 0) { g_sm[bh] = m; g_sm[32 + bh] = red[0]; }
}

// -------- fused flow-attention core (emits scaled fp16 values) ----------------
__global__ __launch_bounds__(256) void token_kernel()
{
    int lt = threadIdx.x >> 6;
    int e  = threadIdx.x & 63;
    int tok = blockIdx.x * 4 + lt;
    int b   = tok >> 12;

    __shared__ float qi[4][8][65], kk[4][8][65], vw[4][8][65];
    __shared__ float Am[4][8][9];
    __shared__ float s_invi[4][8], s_sig[4][8], s_sm[4][8];

    const float* tq = g_qkv + (size_t)tok * QW;
    if (e < 8) {
        int h = e;
        float iv = g_io[(size_t)tok * 8 + h];
        float ih = g_hat[(size_t)tok * 8 + h];
        float oh = g_hat[(size_t)NT * 8 + (size_t)tok * 8 + h];
        int bh = b * 8 + h;
        s_invi[lt][h] = 1.0f / iv;
        s_sig[lt][h]  = 1.0f / (1.0f + expf(-ih));
        s_sm[lt][h]   = expf(oh - g_sm[bh]) / g_sm[32 + bh];
    }
    __syncthreads();

#pragma unroll
    for (int h = 0; h < 8; h++) {
        qi[lt][h][e] = tq[h * 192 + e] * s_invi[lt][h];
        kk[lt][h][e] = tq[h * 192 + 64 + e];
        vw[lt][h][e] = tq[h * 192 + 128 + e] * s_sm[lt][h];
    }
    __syncthreads();

    {
        int h = e >> 3, h2 = e & 7;
        float a = 0.f;
#pragma unroll 8
        for (int d = 0; d < 64; d++) a = fmaf(qi[lt][h][d], kk[lt][h2][d], a);
        Am[lt][h][h2] = a;
    }
    __syncthreads();

    __half* ovh = g_vhi + (size_t)tok * EE;
#pragma unroll
    for (int h = 0; h < 8; h++) {
        float acc = 0.f;
#pragma unroll
        for (int h2 = 0; h2 < 8; h2++) acc = fmaf(Am[lt][h][h2], vw[lt][h2][e], acc);
        float vs = acc * s_sig[lt][h] * VAL_SCALE;
        ovh[h * 64 + e] = __float2half(vs);
    }
}

// ---------------- launch ------------------------------------------------------
extern "C" void kernel_launch(void* const* d_in, const int* in_sizes, int n_in,
                              void* d_out, int out_size)
{
    (void)in_sizes; (void)n_in; (void)out_size;
    const float* x     = (const float*)d_in[0];
    const float* W_qkv = (const float*)d_in[1];
    const float* b_qkv = (const float*)d_in[2];
    const float* W_out = (const float*)d_in[3];
    const float* b_out = (const float*)d_in[4];
    float* out = (float*)d_out;

    float* p_qkv = nullptr;
    cudaGetSymbolAddress((void**)&p_qkv, g_qkv);
    __half *p_xhi, *p_whi, *p_wohi, *p_vhi;
    cudaGetSymbolAddress((void**)&p_xhi,  g_xhi);
    cudaGetSymbolAddress((void**)&p_whi,  g_whi);
    cudaGetSymbolAddress((void**)&p_wohi, g_wohi);
    cudaGetSymbolAddress((void**)&p_vhi,  g_vhi);

    cudaFuncSetAttribute(hmma_gemm, cudaFuncAttributeMaxDynamicSharedMemorySize,
                         SMEM_GEMM);

    // 0) convert all operands to fp16 (single kernel)
    {
        const int NTOT = NT * EE / 4 + QW * EE / 4 + EE * EE / 4;
        cvt_all<<<(NTOT + 255) / 256, 256>>>(
            (const float4*)x, (const float4*)W_qkv, (const float4*)W_out,
            (__half2*)p_xhi, (__half2*)p_whi, (__half2*)p_wohi);
    }
    // 1) QKV projection (fp16 HMMA) + sigmoid + fused column sums
    hmma_gemm<<<dim3(QW / 128, NT / 128), 256, SMEM_GEMM>>>(
        p_xhi, p_whi, b_qkv, p_qkv, QW, EE, 1, 1.0f);
    // 2) finish sumQ/sumK
    colsum_finish<<<16, 256>>>();
    // 3) fused: i,o per token + block partial sums of q/i, k/o
    dots_fused<<<NT / 64, 256>>>();
    part2_reduce<<<16, 256>>>();
    // 4) ihat, ohat
    dots_kernel<<<NT / 8, 256>>>();
    // 5) softmax stats
    softmax_stats<<<32, 256>>>();
    // 6) fused flow-attention core -> scaled values (fp16)
    token_kernel<<<NT / 4, 256>>>();
    // 7) output projection (fp16 HMMA), unscale in epilogue
    hmma_gemm<<<dim3(EE / 128, NT / 128), 256, SMEM_GEMM>>>(
        p_vhi, p_wohi, b_out, out, EE, EE, 0, VAL_INV_SCALE);
}

// round 14
// speedup vs baseline: 1.6755x; 1.0156x over previous
#include <cuda_runtime.h>
#include <cuda_fp16.h>
#include <math.h>
#include <stdint.h>

// Problem constants (fixed by the reference)
#define BB   4
#define SS   4096
#define EE   512
#define HH   8
#define DD   64
#define NT   (BB*SS)        // 16384 tokens
#define QW   1536           // 3*E

#define VAL_SCALE     1048576.0f          // 2^20: lift values out of fp16 subnormals
#define VAL_INV_SCALE (1.0f / 1048576.0f)

// ---------------- scratch (static device globals; no allocation) -------------
__device__ __half g_qkvh[(size_t)NT * QW]; // sig(q), sig(k), v in fp16 (48 MB)
__device__ float g_sums[4 * 32 * 64];      // [sumQ, sumK, sqd, skd] x bh x d
__device__ float g_csum[128 * QW];         // GEMM1 per-rowblock column sums
__device__ float g_part2[1024 * 1024];     // dots_fused block partials (4 MB)
__device__ float g_io[(size_t)NT * HH * 2];
__device__ float g_hat[(size_t)NT * HH * 2];
__device__ float g_sm[64];
// fp16 GEMM operands
__device__ __half g_xhi[(size_t)NT * EE];
__device__ __half g_whi[(size_t)QW * EE];   // W_qkv hi
__device__ __half g_wohi[(size_t)EE * EE];  // W_out hi
__device__ __half g_vhi[(size_t)NT * EE];   // values*2^20 hi (GEMM2 A)

// ===================== portable PTX helpers (sm_80+) =========================
__device__ __forceinline__ uint32_t smem_u32(const void* p) {
    uint32_t a;
    asm("{ .reg .u64 t; cvta.to.shared.u64 t, %1; cvt.u32.u64 %0, t; }"
        : "=r"(a) : "l"(p));
    return a;
}
#define LDSM_X4(r0, r1, r2, r3, addr) \
    asm volatile("ldmatrix.sync.aligned.m8n8.x4.shared.b16 {%0,%1,%2,%3}, [%4];" \
        : "=r"(r0), "=r"(r1), "=r"(r2), "=r"(r3) : "r"(addr))
#define MMA_F16(d, a, b) \
    asm volatile("mma.sync.aligned.m16n8k16.row.col.f32.f16.f16.f32 " \
        "{%0,%1,%2,%3},{%4,%5,%6,%7},{%8,%9},{%0,%1,%2,%3};" \
        : "+f"((d)[0]), "+f"((d)[1]), "+f"((d)[2]), "+f"((d)[3]) \
        : "r"((a)[0]), "r"((a)[1]), "r"((a)[2]), "r"((a)[3]), \
          "r"((b)[0]), "r"((b)[1]))
#define CP_ASYNC16(dst, src) \
    asm volatile("cp.async.cg.shared.global [%0], [%1], 16;" \
        :: "r"(dst), "l"(src))
#define CP_COMMIT() asm volatile("cp.async.commit_group;" ::: "memory")
#define CP_WAIT(n)  asm volatile("cp.async.wait_group %0;" :: "n"(n) : "memory")

// SMEM geometry (BK=64): rows of 64 fp16 (128B) padded to 144B.
#define PITCH_B   144u
#define PLANE_B   18432u               // 128 rows * 144B
#define STAGE_B   36864u               // Ahi + Bhi planes
#define NSTAGE    3
#define SMEM_GEMM (NSTAGE * STAGE_B)   // 110592 bytes -> 2 CTAs per SM

// ========= HMMA fp16 GEMM: C[m,n] = sum_k A[m,k]B[n,k] + bias[n] =============
// 128x128 tile, BK=64, 256 threads = 8 warps (2M x 4N), warp tile 64x32.
// sigmode: sigmoid on (n%192)<128 cols, fp16 output + per-CTA column sums.
__device__ __forceinline__ void issue_stage(
    uint32_t sbase, int stage, int k0,
    const __half* __restrict__ ahi, const __half* __restrict__ bhi,
    int K, int tid)
{
    const uint32_t sb = sbase + (uint32_t)stage * STAGE_B;
#pragma unroll
    for (int it = 0; it < 8; it++) {
        int idx   = it * 256 + tid;
        int plane = idx >> 10;
        int rc    = idx & 1023;
        int row   = rc >> 3;
        int c     = rc & 7;
        uint32_t dst = sb + (uint32_t)plane * PLANE_B
                     + (uint32_t)row * PITCH_B + (uint32_t)c * 16u;
        const __half* src = (plane == 0 ? ahi : bhi)
                          + (size_t)row * K + k0 + c * 8;
        CP_ASYNC16(dst, src);
    }
}

__global__ __launch_bounds__(256, 2) void hmma_gemm(
    const __half* __restrict__ Ahi, const __half* __restrict__ Bhi,
    const float* __restrict__ bias, float* __restrict__ Cf,
    __half* __restrict__ Ch,
    int N, int K, int sigmode, float ascale)
{
    extern __shared__ char dynsmem[];
    const uint32_t sbase = smem_u32(dynsmem);

    const int tid   = threadIdx.x;
    const int warp  = tid >> 5;
    const int lane  = tid & 31;
    const int warpM = warp & 1;
    const int warpN = warp >> 1;

    const __half* ahi = Ahi + (size_t)blockIdx.y * 128 * K;
    const __half* bhi = Bhi + (size_t)blockIdx.x * 128 * K;

    float acc[16][4];
#pragma unroll
    for (int i = 0; i < 16; i++)
#pragma unroll
        for (int j = 0; j < 4; j++) acc[i][j] = 0.f;

    const int NC = K >> 6;

    const uint32_t a_lane = (uint32_t)(warpM * 64 + (lane & 15)) * PITCH_B
                          + (uint32_t)((lane >> 4) * 16);
    const uint32_t b_lane = PLANE_B
                          + (uint32_t)(warpN * 32 + (lane & 7) + ((lane >> 4) & 1) * 8) * PITCH_B
                          + (uint32_t)(((lane >> 3) & 1) * 16);

    issue_stage(sbase, 0, 0, ahi, bhi, K, tid);
    CP_COMMIT();
    issue_stage(sbase, 1, 64, ahi, bhi, K, tid);
    CP_COMMIT();

    for (int c = 0; c < NC; c++) {
        CP_WAIT(1);
        __syncthreads();
        if (c + 2 < NC)
            issue_stage(sbase, (c + 2) % NSTAGE, (c + 2) * 64, ahi, bhi, K, tid);
        CP_COMMIT();

        const uint32_t cur = sbase + (uint32_t)(c % NSTAGE) * STAGE_B;
#pragma unroll
        for (int ks = 0; ks < 4; ks++) {
            const uint32_t koff = (uint32_t)ks * 32u;
            uint32_t bh[4][2];
#pragma unroll
            for (int p = 0; p < 2; p++) {
                uint32_t addr = cur + b_lane + (uint32_t)(p * 16) * PITCH_B + koff;
                LDSM_X4(bh[2*p][0], bh[2*p][1], bh[2*p+1][0], bh[2*p+1][1], addr);
            }
            uint32_t ah[2][4];
            {
                uint32_t addr = cur + a_lane + koff;
                LDSM_X4(ah[0][0], ah[0][1], ah[0][2], ah[0][3], addr);
            }
#pragma unroll
            for (int mi = 0; mi < 4; mi++) {
                const int cu = mi & 1, nx = cu ^ 1;
                if (mi < 3) {
                    uint32_t addr = cur + a_lane
                                  + (uint32_t)((mi + 1) * 16) * PITCH_B + koff;
                    LDSM_X4(ah[nx][0], ah[nx][1], ah[nx][2], ah[nx][3], addr);
                }
#pragma unroll
                for (int ni = 0; ni < 4; ni++)
                    MMA_F16(acc[mi * 4 + ni], ah[cu], bh[ni]);
            }
        }
    }

    // ---- epilogue: unscale + bias + optional sigmoid + column sums ----
    float scol0[4], scol1[4];
#pragma unroll
    for (int ni = 0; ni < 4; ni++) { scol0[ni] = 0.f; scol1[ni] = 0.f; }

#pragma unroll
    for (int mi = 0; mi < 4; mi++) {
        const int r0 = blockIdx.y * 128 + warpM * 64 + mi * 16 + (lane >> 2);
#pragma unroll
        for (int ni = 0; ni < 4; ni++) {
            const int col = blockIdx.x * 128 + warpN * 32 + ni * 8 + (lane & 3) * 2;
            const float b0 = __ldg(bias + col);
            const float b1 = __ldg(bias + col + 1);
            float v0 = acc[mi * 4 + ni][0] * ascale + b0;
            float v1 = acc[mi * 4 + ni][1] * ascale + b1;
            float v2 = acc[mi * 4 + ni][2] * ascale + b0;
            float v3 = acc[mi * 4 + ni][3] * ascale + b1;
            if (sigmode) {
                const bool s0 = (col % 192) < 128;
                const bool s1 = ((col + 1) % 192) < 128;
                if (s0) { v0 = 1.f / (1.f + __expf(-v0)); v2 = 1.f / (1.f + __expf(-v2)); }
                if (s1) { v1 = 1.f / (1.f + __expf(-v1)); v3 = 1.f / (1.f + __expf(-v3)); }
                scol0[ni] += v0 + v2; scol1[ni] += v1 + v3;
                *(__half2*)(Ch + (size_t)r0 * N + col) =
                    __half2(__float2half(v0), __float2half(v1));
                *(__half2*)(Ch + (size_t)(r0 + 8) * N + col) =
                    __half2(__float2half(v2), __float2half(v3));
            } else {
                *(float2*)(Cf + (size_t)r0 * N + col)       = make_float2(v0, v1);
                *(float2*)(Cf + (size_t)(r0 + 8) * N + col) = make_float2(v2, v3);
            }
        }
    }

    if (sigmode) {
#pragma unroll
        for (int ni = 0; ni < 4; ni++) {
#pragma unroll
            for (int off = 4; off <= 16; off <<= 1) {
                scol0[ni] += __shfl_xor_sync(0xFFFFFFFFu, scol0[ni], off);
                scol1[ni] += __shfl_xor_sync(0xFFFFFFFFu, scol1[ni], off);
            }
        }
        float* scs = (float*)dynsmem;   // mainloop smem is dead
        __syncthreads();
        if (lane < 4) {
#pragma unroll
            for (int ni = 0; ni < 4; ni++) {
                scs[warp * 32 + ni * 8 + lane * 2]     = scol0[ni];
                scs[warp * 32 + ni * 8 + lane * 2 + 1] = scol1[ni];
            }
        }
        __syncthreads();
        if (warpM == 0 && lane < 4) {
#pragma unroll
            for (int ni = 0; ni < 4; ni++) {
                int sl = ni * 8 + lane * 2;
                float t0 = scs[warp * 32 + sl]     + scs[(warp + 1) * 32 + sl];
                float t1 = scs[warp * 32 + sl + 1] + scs[(warp + 1) * 32 + sl + 1];
                int colg = blockIdx.x * 128 + warpN * 32 + sl;
                g_csum[blockIdx.y * QW + colg]     = t0;
                g_csum[blockIdx.y * QW + colg + 1] = t1;
            }
        }
    }
}

// ---- finish sumQ/sumK: combine 32 row-block partials per batch --------------
__global__ __launch_bounds__(256) void colsum_finish()
{
    int idx = blockIdx.x * 256 + threadIdx.x;   // 0..4095
    int b    = idx >> 10;
    int slot = idx & 1023;                       // h*128 + isk*64 + d
    int h = slot >> 7, r = slot & 127;
    int isk = r >> 6, d = r & 63;
    int col = h * 192 + isk * 64 + d;
    float acc = 0.f;
#pragma unroll
    for (int j = 0; j < 32; j++)
        acc += g_csum[(b * 32 + j) * QW + col];
    g_sums[(size_t)isk * 2048 + (b * 8 + h) * 64 + d] = acc;
}

// ---------------- fused fp32 -> fp16 converter (x, W_qkv, W_out) --------------
__global__ __launch_bounds__(256) void cvt_all(
    const float4* __restrict__ x, const float4* __restrict__ w,
    const float4* __restrict__ wo,
    __half2* __restrict__ xhi, __half2* __restrict__ whi,
    __half2* __restrict__ wohi)
{
    const int NX = NT * EE / 4, NW = QW * EE / 4, NO = EE * EE / 4;
    int i = blockIdx.x * 256 + threadIdx.x;
    const float4* src; __half2* dst; int j;
    if (i < NX)            { src = x;  dst = xhi;  j = i; }
    else if (i < NX + NW)  { src = w;  dst = whi;  j = i - NX; }
    else if (i < NX + NW + NO) { src = wo; dst = wohi; j = i - NX - NW; }
    else return;
    float4 v = src[j];
    dst[2 * j]     = __half2(__float2half(v.x), __float2half(v.y));
    dst[2 * j + 1] = __half2(__float2half(v.z), __float2half(v.w));
}

// ------- fused dots(i,o) + block partial sums of q/i, k/o ---------------------
// 1024 blocks x 256 threads; warp handles 2 tokens (block: 16).
__global__ __launch_bounds__(256) void dots_fused()
{
    int warp = threadIdx.x >> 5, lane = threadIdx.x & 31;
    int blk  = blockIdx.x;
    int b    = blk >> 8;

    __shared__ float2 sQ[8][32], sK[8][32];
    __shared__ float spart[8][1024];
    const float2* vq = (const float2*)(g_sums + (size_t)1 * 2048 + b * 512); // sumK
    const float2* vk = (const float2*)(g_sums + (size_t)0 * 2048 + b * 512); // sumQ
    for (int idx = threadIdx.x; idx < 256; idx += 256) {
        sQ[idx >> 5][idx & 31] = vq[idx];
        sK[idx >> 5][idx & 31] = vk[idx];
    }
    __syncthreads();

    float pqx[8], pqy[8], pkx[8], pky[8];
#pragma unroll
    for (int h = 0; h < 8; h++) { pqx[h] = pqy[h] = pkx[h] = pky[h] = 0.f; }

#pragma unroll
    for (int t = 0; t < 2; t++) {
        int tok = blk * 16 + warp * 2 + t;
        const __half* tq = g_qkvh + (size_t)tok * QW;
        float* outI = g_io + (size_t)tok * 8;
        float* outO = outI + (size_t)NT * 8;
#pragma unroll
        for (int h = 0; h < 8; h++) {
            const __half2* qh2 = (const __half2*)(tq + h * 192);
            const __half2* kh2 = (const __half2*)(tq + h * 192 + 64);
            float2 q2 = __half22float2(qh2[lane]);
            float2 k2 = __half22float2(kh2[lane]);
            float2 sq = sQ[h][lane], sk = sK[h][lane];
            float vi = q2.x * sq.x + q2.y * sq.y;
            float vo = k2.x * sk.x + k2.y * sk.y;
#pragma unroll
            for (int off = 16; off; off >>= 1) {
                vi += __shfl_xor_sync(0xFFFFFFFFu, vi, off);
                vo += __shfl_xor_sync(0xFFFFFFFFu, vo, off);
            }
            float ri = 1.0f / vi, ro = 1.0f / vo;
            pqx[h] += q2.x * ri;  pqy[h] += q2.y * ri;
            pkx[h] += k2.x * ro;  pky[h] += k2.y * ro;
            if (lane == 0) { outI[h] = vi; outO[h] = vo; }
        }
    }

    // slot = h*64 + d, d = 2*lane (+1)
    float2* spq = (float2*)spart[warp];
#pragma unroll
    for (int h = 0; h < 8; h++) {
        spq[h * 32 + lane]       = make_float2(pqx[h], pqy[h]);
        spq[256 + h * 32 + lane] = make_float2(pkx[h], pky[h]);
    }
    __syncthreads();
    for (int s = threadIdx.x; s < 1024; s += 256) {
        float a = 0.f;
#pragma unroll
        for (int w = 0; w < 8; w++) a += spart[w][s];
        g_part2[blk * 1024 + s] = a;
    }
}

// combine block partials -> sqd (slot2), skd (slot3)
__global__ __launch_bounds__(256) void part2_reduce()
{
    int idx = blockIdx.x * 256 + threadIdx.x;   // 0..4095
    int b   = idx >> 10;
    int off = idx & 1023;
    float acc = 0.f;
#pragma unroll 8
    for (int j = 0; j < 256; j++)
        acc += g_part2[(b * 256 + j) * 1024 + off];
    int side = off >> 9;
    int hd   = off & 511;
    g_sums[(size_t)(2 + side) * 2048 + b * 512 + hd] = acc;
}

// ---------------- dots phase 1 (ihat, ohat): warp per token -------------------
__global__ __launch_bounds__(256) void dots_kernel()
{
    int warp = threadIdx.x >> 5, lane = threadIdx.x & 31;
    int tok  = blockIdx.x * 8 + warp;
    int b    = tok >> 12;

    __shared__ float2 sQ[8][32], sK[8][32];
    const float2* vq = (const float2*)(g_sums + (size_t)3 * 2048 + b * 512); // skd
    const float2* vk = (const float2*)(g_sums + (size_t)2 * 2048 + b * 512); // sqd
    for (int idx = threadIdx.x; idx < 256; idx += 256) {
        sQ[idx >> 5][idx & 31] = vq[idx];
        sK[idx >> 5][idx & 31] = vk[idx];
    }
    __syncthreads();

    const __half* tq = g_qkvh + (size_t)tok * QW;
    float* outI = g_hat + (size_t)tok * 8;
    float* outO = outI + (size_t)NT * 8;

#pragma unroll
    for (int h = 0; h < 8; h++) {
        const __half2* qh2 = (const __half2*)(tq + h * 192);
        const __half2* kh2 = (const __half2*)(tq + h * 192 + 64);
        float2 q2 = __half22float2(qh2[lane]);
        float2 k2 = __half22float2(kh2[lane]);
        float2 sq = sQ[h][lane], sk = sK[h][lane];
        float vi = q2.x * sq.x + q2.y * sq.y;
        float vo = k2.x * sk.x + k2.y * sk.y;
#pragma unroll
        for (int off = 16; off; off >>= 1) {
            vi += __shfl_down_sync(0xFFFFFFFFu, vi, off);
            vo += __shfl_down_sync(0xFFFFFFFFu, vo, off);
        }
        if (lane == 0) { outI[h] = vi; outO[h] = vo; }
    }
}

// ---------------- softmax stats over seq per (b,h) ---------------------------
__global__ __launch_bounds__(256) void softmax_stats()
{
    int bh = blockIdx.x;
    int b = bh >> 3, h = bh & 7;
    __shared__ float red[256];
    const float* oh = g_hat + (size_t)NT * 8 + (size_t)b * SS * 8 + h;

    float m = -1e30f;
    for (int s = threadIdx.x; s < SS; s += 256) m = fmaxf(m, oh[(size_t)s * 8]);
    red[threadIdx.x] = m; __syncthreads();
    for (int o = 128; o; o >>= 1) {
        if (threadIdx.x < o) red[threadIdx.x] = fmaxf(red[threadIdx.x], red[threadIdx.x + o]);
        __syncthreads();
    }
    m = red[0]; __syncthreads();

    float sum = 0.f;
    for (int s = threadIdx.x; s < SS; s += 256) sum += expf(oh[(size_t)s * 8] - m);
    red[threadIdx.x] = sum; __syncthreads();
    for (int o = 128; o; o >>= 1) {
        if (threadIdx.x < o) red[threadIdx.x] += red[threadIdx.x + o];
        __syncthreads();
    }
    if (threadIdx.x == 0) { g_sm[bh] = m; g_sm[32 + bh] = red[0]; }
}

// -------- fused flow-attention core (emits scaled fp16 values) ----------------
__global__ __launch_bounds__(256) void token_kernel()
{
    int lt = threadIdx.x >> 6;
    int e  = threadIdx.x & 63;
    int tok = blockIdx.x * 4 + lt;
    int b   = tok >> 12;

    __shared__ float qi[4][8][65], kk[4][8][65], vw[4][8][65];
    __shared__ float Am[4][8][9];
    __shared__ float s_invi[4][8], s_sig[4][8], s_sm[4][8];

    const __half* tq = g_qkvh + (size_t)tok * QW;
    if (e < 8) {
        int h = e;
        float iv = g_io[(size_t)tok * 8 + h];
        float ih = g_hat[(size_t)tok * 8 + h];
        float oh = g_hat[(size_t)NT * 8 + (size_t)tok * 8 + h];
        int bh = b * 8 + h;
        s_invi[lt][h] = 1.0f / iv;
        s_sig[lt][h]  = 1.0f / (1.0f + expf(-ih));
        s_sm[lt][h]   = expf(oh - g_sm[bh]) / g_sm[32 + bh];
    }
    __syncthreads();

#pragma unroll
    for (int h = 0; h < 8; h++) {
        qi[lt][h][e] = __half2float(tq[h * 192 + e])       * s_invi[lt][h];
        kk[lt][h][e] = __half2float(tq[h * 192 + 64 + e]);
        vw[lt][h][e] = __half2float(tq[h * 192 + 128 + e]) * s_sm[lt][h];
    }
    __syncthreads();

    {
        int h = e >> 3, h2 = e & 7;
        float a = 0.f;
#pragma unroll 8
        for (int d = 0; d < 64; d++) a = fmaf(qi[lt][h][d], kk[lt][h2][d], a);
        Am[lt][h][h2] = a;
    }
    __syncthreads();

    __half* ovh = g_vhi + (size_t)tok * EE;
#pragma unroll
    for (int h = 0; h < 8; h++) {
        float acc = 0.f;
#pragma unroll
        for (int h2 = 0; h2 < 8; h2++) acc = fmaf(Am[lt][h][h2], vw[lt][h2][e], acc);
        float vs = acc * s_sig[lt][h] * VAL_SCALE;
        ovh[h * 64 + e] = __float2half(vs);
    }
}

// ---------------- launch ------------------------------------------------------
extern "C" void kernel_launch(void* const* d_in, const int* in_sizes, int n_in,
                              void* d_out, int out_size)
{
    (void)in_sizes; (void)n_in; (void)out_size;
    const float* x     = (const float*)d_in[0];
    const float* W_qkv = (const float*)d_in[1];
    const float* b_qkv = (const float*)d_in[2];
    const float* W_out = (const float*)d_in[3];
    const float* b_out = (const float*)d_in[4];
    float* out = (float*)d_out;

    __half *p_qkvh, *p_xhi, *p_whi, *p_wohi, *p_vhi;
    cudaGetSymbolAddress((void**)&p_qkvh, g_qkvh);
    cudaGetSymbolAddress((void**)&p_xhi,  g_xhi);
    cudaGetSymbolAddress((void**)&p_whi,  g_whi);
    cudaGetSymbolAddress((void**)&p_wohi, g_wohi);
    cudaGetSymbolAddress((void**)&p_vhi,  g_vhi);

    cudaFuncSetAttribute(hmma_gemm, cudaFuncAttributeMaxDynamicSharedMemorySize,
                         SMEM_GEMM);

    // 0) convert all operands to fp16 (single kernel)
    {
        const int NTOT = NT * EE / 4 + QW * EE / 4 + EE * EE / 4;
        cvt_all<<<(NTOT + 255) / 256, 256>>>(
            (const float4*)x, (const float4*)W_qkv, (const float4*)W_out,
            (__half2*)p_xhi, (__half2*)p_whi, (__half2*)p_wohi);
    }
    // 1) QKV projection + sigmoid + fused column sums; fp16 output
    hmma_gemm<<<dim3(QW / 128, NT / 128), 256, SMEM_GEMM>>>(
        p_xhi, p_whi, b_qkv, nullptr, p_qkvh, QW, EE, 1, 1.0f);
    // 2) finish sumQ/sumK
    colsum_finish<<<16, 256>>>();
    // 3) fused: i,o per token + block partial sums of q/i, k/o
    dots_fused<<<NT / 16, 256>>>();
    part2_reduce<<<16, 256>>>();
    // 4) ihat, ohat
    dots_kernel<<<NT / 8, 256>>>();
    // 5) softmax stats
    softmax_stats<<<32, 256>>>();
    // 6) fused flow-attention core -> scaled values (fp16)
    token_kernel<<<NT / 4, 256>>>();
    // 7) output projection (fp16 HMMA), fp32 output, unscale in epilogue
    hmma_gemm<<<dim3(EE / 128, NT / 128), 256, SMEM_GEMM>>>(
        p_vhi, p_wohi, b_out, out, nullptr, EE, EE, 0, VAL_INV_SCALE);
}

// round 15
// speedup vs baseline: 1.8182x; 1.0852x over previous
#include <cuda_runtime.h>
#include <cuda_fp16.h>
#include <math.h>
#include <stdint.h>

// Problem constants (fixed by the reference)
#define BB   4
#define SS   4096
#define EE   512
#define HH   8
#define DD   64
#define NT   (BB*SS)        // 16384 tokens
#define QW   1536           // 3*E

#define VAL_SCALE     1048576.0f          // 2^20: lift values out of fp16 subnormals
#define VAL_INV_SCALE (1.0f / 1048576.0f)

// ---------------- scratch (static device globals; no allocation) -------------
__device__ __half g_qkvh[(size_t)NT * QW]; // sig(q), sig(k), v in fp16 (48 MB)
__device__ float g_sums[4 * 32 * 64];      // [sumQ, sumK, sqd, skd] x bh x d
__device__ float g_csum[128 * QW];         // GEMM1 per-rowblock column sums
__device__ float g_part2[512 * 1024];      // dots_fused block partials (2 MB)
__device__ float g_io[(size_t)NT * HH * 2];
__device__ float g_hat[(size_t)NT * HH * 2];
__device__ float g_sm[64];
// fp16 GEMM operands
__device__ __half g_xhi[(size_t)NT * EE];
__device__ __half g_whi[(size_t)QW * EE];   // W_qkv hi
__device__ __half g_wohi[(size_t)EE * EE];  // W_out hi
__device__ __half g_vhi[(size_t)NT * EE];   // values*2^20 hi (GEMM2 A)

// ===================== portable PTX helpers (sm_80+) =========================
__device__ __forceinline__ uint32_t smem_u32(const void* p) {
    uint32_t a;
    asm("{ .reg .u64 t; cvta.to.shared.u64 t, %1; cvt.u32.u64 %0, t; }"
        : "=r"(a) : "l"(p));
    return a;
}
#define LDSM_X4(r0, r1, r2, r3, addr) \
    asm volatile("ldmatrix.sync.aligned.m8n8.x4.shared.b16 {%0,%1,%2,%3}, [%4];" \
        : "=r"(r0), "=r"(r1), "=r"(r2), "=r"(r3) : "r"(addr))
#define MMA_F16(d, a, b) \
    asm volatile("mma.sync.aligned.m16n8k16.row.col.f32.f16.f16.f32 " \
        "{%0,%1,%2,%3},{%4,%5,%6,%7},{%8,%9},{%0,%1,%2,%3};" \
        : "+f"((d)[0]), "+f"((d)[1]), "+f"((d)[2]), "+f"((d)[3]) \
        : "r"((a)[0]), "r"((a)[1]), "r"((a)[2]), "r"((a)[3]), \
          "r"((b)[0]), "r"((b)[1]))
#define CP_ASYNC16(dst, src) \
    asm volatile("cp.async.cg.shared.global [%0], [%1], 16;" \
        :: "r"(dst), "l"(src))
#define CP_COMMIT() asm volatile("cp.async.commit_group;" ::: "memory")
#define CP_WAIT(n)  asm volatile("cp.async.wait_group %0;" :: "n"(n) : "memory")

// SMEM geometry (BK=64): rows of 64 fp16 (128B) padded to 144B.
#define PITCH_B   144u
#define PLANE_B   18432u               // 128 rows * 144B
#define STAGE_B   36864u               // Ahi + Bhi planes
#define NSTAGE    3
#define SMEM_GEMM (NSTAGE * STAGE_B)   // 110592 bytes -> 2 CTAs per SM

// ========= HMMA fp16 GEMM: C[m,n] = sum_k A[m,k]B[n,k] + bias[n] =============
__device__ __forceinline__ void issue_stage(
    uint32_t sbase, int stage, int k0,
    const __half* __restrict__ ahi, const __half* __restrict__ bhi,
    int K, int tid)
{
    const uint32_t sb = sbase + (uint32_t)stage * STAGE_B;
#pragma unroll
    for (int it = 0; it < 8; it++) {
        int idx   = it * 256 + tid;
        int plane = idx >> 10;
        int rc    = idx & 1023;
        int row   = rc >> 3;
        int c     = rc & 7;
        uint32_t dst = sb + (uint32_t)plane * PLANE_B
                     + (uint32_t)row * PITCH_B + (uint32_t)c * 16u;
        const __half* src = (plane == 0 ? ahi : bhi)
                          + (size_t)row * K + k0 + c * 8;
        CP_ASYNC16(dst, src);
    }
}

__global__ __launch_bounds__(256, 2) void hmma_gemm(
    const __half* __restrict__ Ahi, const __half* __restrict__ Bhi,
    const float* __restrict__ bias, float* __restrict__ Cf,
    __half* __restrict__ Ch,
    int N, int K, int sigmode, float ascale)
{
    extern __shared__ char dynsmem[];
    const uint32_t sbase = smem_u32(dynsmem);

    const int tid   = threadIdx.x;
    const int warp  = tid >> 5;
    const int lane  = tid & 31;
    const int warpM = warp & 1;
    const int warpN = warp >> 1;

    const __half* ahi = Ahi + (size_t)blockIdx.y * 128 * K;
    const __half* bhi = Bhi + (size_t)blockIdx.x * 128 * K;

    float acc[16][4];
#pragma unroll
    for (int i = 0; i < 16; i++)
#pragma unroll
        for (int j = 0; j < 4; j++) acc[i][j] = 0.f;

    const int NC = K >> 6;

    const uint32_t a_lane = (uint32_t)(warpM * 64 + (lane & 15)) * PITCH_B
                          + (uint32_t)((lane >> 4) * 16);
    const uint32_t b_lane = PLANE_B
                          + (uint32_t)(warpN * 32 + (lane & 7) + ((lane >> 4) & 1) * 8) * PITCH_B
                          + (uint32_t)(((lane >> 3) & 1) * 16);

    issue_stage(sbase, 0, 0, ahi, bhi, K, tid);
    CP_COMMIT();
    issue_stage(sbase, 1, 64, ahi, bhi, K, tid);
    CP_COMMIT();

    for (int c = 0; c < NC; c++) {
        CP_WAIT(1);
        __syncthreads();
        if (c + 2 < NC)
            issue_stage(sbase, (c + 2) % NSTAGE, (c + 2) * 64, ahi, bhi, K, tid);
        CP_COMMIT();

        const uint32_t cur = sbase + (uint32_t)(c % NSTAGE) * STAGE_B;
#pragma unroll
        for (int ks = 0; ks < 4; ks++) {
            const uint32_t koff = (uint32_t)ks * 32u;
            uint32_t bh[4][2];
#pragma unroll
            for (int p = 0; p < 2; p++) {
                uint32_t addr = cur + b_lane + (uint32_t)(p * 16) * PITCH_B + koff;
                LDSM_X4(bh[2*p][0], bh[2*p][1], bh[2*p+1][0], bh[2*p+1][1], addr);
            }
            uint32_t ah[2][4];
            {
                uint32_t addr = cur + a_lane + koff;
                LDSM_X4(ah[0][0], ah[0][1], ah[0][2], ah[0][3], addr);
            }
#pragma unroll
            for (int mi = 0; mi < 4; mi++) {
                const int cu = mi & 1, nx = cu ^ 1;
                if (mi < 3) {
                    uint32_t addr = cur + a_lane
                                  + (uint32_t)((mi + 1) * 16) * PITCH_B + koff;
                    LDSM_X4(ah[nx][0], ah[nx][1], ah[nx][2], ah[nx][3], addr);
                }
#pragma unroll
                for (int ni = 0; ni < 4; ni++)
                    MMA_F16(acc[mi * 4 + ni], ah[cu], bh[ni]);
            }
        }
    }

    // ---- epilogue: unscale + bias + optional sigmoid + column sums ----
    float scol0[4], scol1[4];
#pragma unroll
    for (int ni = 0; ni < 4; ni++) { scol0[ni] = 0.f; scol1[ni] = 0.f; }

#pragma unroll
    for (int mi = 0; mi < 4; mi++) {
        const int r0 = blockIdx.y * 128 + warpM * 64 + mi * 16 + (lane >> 2);
#pragma unroll
        for (int ni = 0; ni < 4; ni++) {
            const int col = blockIdx.x * 128 + warpN * 32 + ni * 8 + (lane & 3) * 2;
            const float b0 = __ldg(bias + col);
            const float b1 = __ldg(bias + col + 1);
            float v0 = acc[mi * 4 + ni][0] * ascale + b0;
            float v1 = acc[mi * 4 + ni][1] * ascale + b1;
            float v2 = acc[mi * 4 + ni][2] * ascale + b0;
            float v3 = acc[mi * 4 + ni][3] * ascale + b1;
            if (sigmode) {
                const bool s0 = (col % 192) < 128;
                const bool s1 = ((col + 1) % 192) < 128;
                if (s0) { v0 = 1.f / (1.f + __expf(-v0)); v2 = 1.f / (1.f + __expf(-v2)); }
                if (s1) { v1 = 1.f / (1.f + __expf(-v1)); v3 = 1.f / (1.f + __expf(-v3)); }
                scol0[ni] += v0 + v2; scol1[ni] += v1 + v3;
                *(__half2*)(Ch + (size_t)r0 * N + col) =
                    __half2(__float2half(v0), __float2half(v1));
                *(__half2*)(Ch + (size_t)(r0 + 8) * N + col) =
                    __half2(__float2half(v2), __float2half(v3));
            } else {
                *(float2*)(Cf + (size_t)r0 * N + col)       = make_float2(v0, v1);
                *(float2*)(Cf + (size_t)(r0 + 8) * N + col) = make_float2(v2, v3);
            }
        }
    }

    if (sigmode) {
#pragma unroll
        for (int ni = 0; ni < 4; ni++) {
#pragma unroll
            for (int off = 4; off <= 16; off <<= 1) {
                scol0[ni] += __shfl_xor_sync(0xFFFFFFFFu, scol0[ni], off);
                scol1[ni] += __shfl_xor_sync(0xFFFFFFFFu, scol1[ni], off);
            }
        }
        float* scs = (float*)dynsmem;
        __syncthreads();
        if (lane < 4) {
#pragma unroll
            for (int ni = 0; ni < 4; ni++) {
                scs[warp * 32 + ni * 8 + lane * 2]     = scol0[ni];
                scs[warp * 32 + ni * 8 + lane * 2 + 1] = scol1[ni];
            }
        }
        __syncthreads();
        if (warpM == 0 && lane < 4) {
#pragma unroll
            for (int ni = 0; ni < 4; ni++) {
                int sl = ni * 8 + lane * 2;
                float t0 = scs[warp * 32 + sl]     + scs[(warp + 1) * 32 + sl];
                float t1 = scs[warp * 32 + sl + 1] + scs[(warp + 1) * 32 + sl + 1];
                int colg = blockIdx.x * 128 + warpN * 32 + sl;
                g_csum[blockIdx.y * QW + colg]     = t0;
                g_csum[blockIdx.y * QW + colg + 1] = t1;
            }
        }
    }
}

// ---- finish sumQ/sumK: combine 32 row-block partials per batch --------------
__global__ __launch_bounds__(256) void colsum_finish()
{
    int idx = blockIdx.x * 256 + threadIdx.x;   // 0..4095
    int b    = idx >> 10;
    int slot = idx & 1023;                       // h*128 + isk*64 + d
    int h = slot >> 7, r = slot & 127;
    int isk = r >> 6, d = r & 63;
    int col = h * 192 + isk * 64 + d;
    float acc = 0.f;
#pragma unroll
    for (int j = 0; j < 32; j++)
        acc += g_csum[(b * 32 + j) * QW + col];
    g_sums[(size_t)isk * 2048 + (b * 8 + h) * 64 + d] = acc;
}

// ---------------- fused fp32 -> fp16 converter (x, W_qkv, W_out) --------------
__global__ __launch_bounds__(256) void cvt_all(
    const float4* __restrict__ x, const float4* __restrict__ w,
    const float4* __restrict__ wo,
    __half2* __restrict__ xhi, __half2* __restrict__ whi,
    __half2* __restrict__ wohi)
{
    const int NX = NT * EE / 4, NW = QW * EE / 4, NO = EE * EE / 4;
    int i = blockIdx.x * 256 + threadIdx.x;
    const float4* src; __half2* dst; int j;
    if (i < NX)            { src = x;  dst = xhi;  j = i; }
    else if (i < NX + NW)  { src = w;  dst = whi;  j = i - NX; }
    else if (i < NX + NW + NO) { src = wo; dst = wohi; j = i - NX - NW; }
    else return;
    float4 v = src[j];
    dst[2 * j]     = __half2(__float2half(v.x), __float2half(v.y));
    dst[2 * j + 1] = __half2(__float2half(v.z), __float2half(v.w));
}

// ------- fused dots(i,o) + block partial sums of q/i, k/o ---------------------
// 512 blocks x 256 threads; warp handles 4 tokens; shfl chains interleaved.
__global__ __launch_bounds__(256) void dots_fused()
{
    int warp = threadIdx.x >> 5, lane = threadIdx.x & 31;
    int blk  = blockIdx.x;
    int b    = blk >> 7;                 // 128 blocks per batch

    __shared__ float2 sQ[8][32], sK[8][32];
    __shared__ float spart[8][1024];
    const float2* vq = (const float2*)(g_sums + (size_t)1 * 2048 + b * 512); // sumK
    const float2* vk = (const float2*)(g_sums + (size_t)0 * 2048 + b * 512); // sumQ
    if (threadIdx.x < 256) {
        int idx = threadIdx.x;
        sQ[idx >> 5][idx & 31] = vq[idx];
        sK[idx >> 5][idx & 31] = vk[idx];
    }
    __syncthreads();

    float pqx[8], pqy[8], pkx[8], pky[8];
#pragma unroll
    for (int h = 0; h < 8; h++) { pqx[h] = pqy[h] = pkx[h] = pky[h] = 0.f; }

    const int tok0 = blk * 32 + warp * 4;

#pragma unroll
    for (int h = 0; h < 8; h++) {
        float2 q2[4], k2[4];
        float vi[4], vo[4];
        const float2 sq = sQ[h][lane], sk = sK[h][lane];
#pragma unroll
        for (int t = 0; t < 4; t++) {
            const __half* tq = g_qkvh + (size_t)(tok0 + t) * QW;
            q2[t] = __half22float2(((const __half2*)(tq + h * 192))[lane]);
            k2[t] = __half22float2(((const __half2*)(tq + h * 192 + 64))[lane]);
            vi[t] = q2[t].x * sq.x + q2[t].y * sq.y;
            vo[t] = k2[t].x * sk.x + k2[t].y * sk.y;
        }
        // interleaved butterflies: 8 independent shfls per level
#pragma unroll
        for (int off = 16; off; off >>= 1) {
#pragma unroll
            for (int t = 0; t < 4; t++) {
                vi[t] += __shfl_xor_sync(0xFFFFFFFFu, vi[t], off);
                vo[t] += __shfl_xor_sync(0xFFFFFFFFu, vo[t], off);
            }
        }
#pragma unroll
        for (int t = 0; t < 4; t++) {
            float ri = 1.0f / vi[t], ro = 1.0f / vo[t];
            pqx[h] += q2[t].x * ri;  pqy[h] += q2[t].y * ri;
            pkx[h] += k2[t].x * ro;  pky[h] += k2[t].y * ro;
            if (lane == 0) {
                g_io[(size_t)(tok0 + t) * 8 + h]                   = vi[t];
                g_io[(size_t)NT * 8 + (size_t)(tok0 + t) * 8 + h]  = vo[t];
            }
        }
    }

    float2* spq = (float2*)spart[warp];
#pragma unroll
    for (int h = 0; h < 8; h++) {
        spq[h * 32 + lane]       = make_float2(pqx[h], pqy[h]);
        spq[256 + h * 32 + lane] = make_float2(pkx[h], pky[h]);
    }
    __syncthreads();
    for (int s = threadIdx.x; s < 1024; s += 256) {
        float a = 0.f;
#pragma unroll
        for (int w = 0; w < 8; w++) a += spart[w][s];
        g_part2[blk * 1024 + s] = a;
    }
}

// combine block partials -> sqd (slot2), skd (slot3)
__global__ __launch_bounds__(256) void part2_reduce()
{
    int idx = blockIdx.x * 256 + threadIdx.x;   // 0..4095
    int b   = idx >> 10;
    int off = idx & 1023;
    float acc = 0.f;
#pragma unroll 8
    for (int j = 0; j < 128; j++)
        acc += g_part2[(b * 128 + j) * 1024 + off];
    int side = off >> 9;
    int hd   = off & 511;
    g_sums[(size_t)(2 + side) * 2048 + b * 512 + hd] = acc;
}

// ------ dots phase 1 (ihat, ohat): warp per 4 tokens, interleaved shfl --------
__global__ __launch_bounds__(256) void dots_kernel()
{
    int warp = threadIdx.x >> 5, lane = threadIdx.x & 31;
    int blk  = blockIdx.x;
    int b    = blk >> 7;

    __shared__ float2 sQ[8][32], sK[8][32];
    const float2* vq = (const float2*)(g_sums + (size_t)3 * 2048 + b * 512); // skd
    const float2* vk = (const float2*)(g_sums + (size_t)2 * 2048 + b * 512); // sqd
    if (threadIdx.x < 256) {
        int idx = threadIdx.x;
        sQ[idx >> 5][idx & 31] = vq[idx];
        sK[idx >> 5][idx & 31] = vk[idx];
    }
    __syncthreads();

    const int tok0 = blk * 32 + warp * 4;

#pragma unroll
    for (int h = 0; h < 8; h++) {
        float vi[4], vo[4];
        const float2 sq = sQ[h][lane], sk = sK[h][lane];
#pragma unroll
        for (int t = 0; t < 4; t++) {
            const __half* tq = g_qkvh + (size_t)(tok0 + t) * QW;
            float2 q2 = __half22float2(((const __half2*)(tq + h * 192))[lane]);
            float2 k2 = __half22float2(((const __half2*)(tq + h * 192 + 64))[lane]);
            vi[t] = q2.x * sq.x + q2.y * sq.y;
            vo[t] = k2.x * sk.x + k2.y * sk.y;
        }
#pragma unroll
        for (int off = 16; off; off >>= 1) {
#pragma unroll
            for (int t = 0; t < 4; t++) {
                vi[t] += __shfl_xor_sync(0xFFFFFFFFu, vi[t], off);
                vo[t] += __shfl_xor_sync(0xFFFFFFFFu, vo[t], off);
            }
        }
        if (lane == 0) {
#pragma unroll
            for (int t = 0; t < 4; t++) {
                g_hat[(size_t)(tok0 + t) * 8 + h]                  = vi[t];
                g_hat[(size_t)NT * 8 + (size_t)(tok0 + t) * 8 + h] = vo[t];
            }
        }
    }
}

// ---------------- softmax stats over seq per (b,h) ---------------------------
__global__ __launch_bounds__(256) void softmax_stats()
{
    int bh = blockIdx.x;
    int b = bh >> 3, h = bh & 7;
    __shared__ float red[256];
    const float* oh = g_hat + (size_t)NT * 8 + (size_t)b * SS * 8 + h;

    float m = -1e30f;
    for (int s = threadIdx.x; s < SS; s += 256) m = fmaxf(m, oh[(size_t)s * 8]);
    red[threadIdx.x] = m; __syncthreads();
    for (int o = 128; o; o >>= 1) {
        if (threadIdx.x < o) red[threadIdx.x] = fmaxf(red[threadIdx.x], red[threadIdx.x + o]);
        __syncthreads();
    }
    m = red[0]; __syncthreads();

    float sum = 0.f;
    for (int s = threadIdx.x; s < SS; s += 256) sum += expf(oh[(size_t)s * 8] - m);
    red[threadIdx.x] = sum; __syncthreads();
    for (int o = 128; o; o >>= 1) {
        if (threadIdx.x < o) red[threadIdx.x] += red[threadIdx.x + o];
        __syncthreads();
    }
    if (threadIdx.x == 0) { g_sm[bh] = m; g_sm[32 + bh] = red[0]; }
}

// -------- fused flow-attention core (emits scaled fp16 values) ----------------
__global__ __launch_bounds__(256) void token_kernel()
{
    int lt = threadIdx.x >> 6;
    int e  = threadIdx.x & 63;
    int tok = blockIdx.x * 4 + lt;
    int b   = tok >> 12;

    __shared__ float qi[4][8][65], kk[4][8][65], vw[4][8][65];
    __shared__ float Am[4][8][9];
    __shared__ float s_invi[4][8], s_sig[4][8], s_sm[4][8];

    const __half* tq = g_qkvh + (size_t)tok * QW;
    if (e < 8) {
        int h = e;
        float iv = g_io[(size_t)tok * 8 + h];
        float ih = g_hat[(size_t)tok * 8 + h];
        float oh = g_hat[(size_t)NT * 8 + (size_t)tok * 8 + h];
        int bh = b * 8 + h;
        s_invi[lt][h] = 1.0f / iv;
        s_sig[lt][h]  = 1.0f / (1.0f + expf(-ih));
        s_sm[lt][h]   = expf(oh - g_sm[bh]) / g_sm[32 + bh];
    }
    __syncthreads();

#pragma unroll
    for (int h = 0; h < 8; h++) {
        qi[lt][h][e] = __half2float(tq[h * 192 + e])       * s_invi[lt][h];
        kk[lt][h][e] = __half2float(tq[h * 192 + 64 + e]);
        vw[lt][h][e] = __half2float(tq[h * 192 + 128 + e]) * s_sm[lt][h];
    }
    __syncthreads();

    {
        int h = e >> 3, h2 = e & 7;
        float a = 0.f;
#pragma unroll 8
        for (int d = 0; d < 64; d++) a = fmaf(qi[lt][h][d], kk[lt][h2][d], a);
        Am[lt][h][h2] = a;
    }
    __syncthreads();

    __half* ovh = g_vhi + (size_t)tok * EE;
#pragma unroll
    for (int h = 0; h < 8; h++) {
        float acc = 0.f;
#pragma unroll
        for (int h2 = 0; h2 < 8; h2++) acc = fmaf(Am[lt][h][h2], vw[lt][h2][e], acc);
        float vs = acc * s_sig[lt][h] * VAL_SCALE;
        ovh[h * 64 + e] = __float2half(vs);
    }
}

// ---------------- launch ------------------------------------------------------
extern "C" void kernel_launch(void* const* d_in, const int* in_sizes, int n_in,
                              void* d_out, int out_size)
{
    (void)in_sizes; (void)n_in; (void)out_size;
    const float* x     = (const float*)d_in[0];
    const float* W_qkv = (const float*)d_in[1];
    const float* b_qkv = (const float*)d_in[2];
    const float* W_out = (const float*)d_in[3];
    const float* b_out = (const float*)d_in[4];
    float* out = (float*)d_out;

    __half *p_qkvh, *p_xhi, *p_whi, *p_wohi, *p_vhi;
    cudaGetSymbolAddress((void**)&p_qkvh, g_qkvh);
    cudaGetSymbolAddress((void**)&p_xhi,  g_xhi);
    cudaGetSymbolAddress((void**)&p_whi,  g_whi);
    cudaGetSymbolAddress((void**)&p_wohi, g_wohi);
    cudaGetSymbolAddress((void**)&p_vhi,  g_vhi);

    cudaFuncSetAttribute(hmma_gemm, cudaFuncAttributeMaxDynamicSharedMemorySize,
                         SMEM_GEMM);

    // 0) convert all operands to fp16 (single kernel)
    {
        const int NTOT = NT * EE / 4 + QW * EE / 4 + EE * EE / 4;
        cvt_all<<<(NTOT + 255) / 256, 256>>>(
            (const float4*)x, (const float4*)W_qkv, (const float4*)W_out,
            (__half2*)p_xhi, (__half2*)p_whi, (__half2*)p_wohi);
    }
    // 1) QKV projection + sigmoid + fused column sums; fp16 output
    hmma_gemm<<<dim3(QW / 128, NT / 128), 256, SMEM_GEMM>>>(
        p_xhi, p_whi, b_qkv, nullptr, p_qkvh, QW, EE, 1, 1.0f);
    // 2) finish sumQ/sumK
    colsum_finish<<<16, 256>>>();
    // 3) fused: i,o per token + block partial sums of q/i, k/o
    dots_fused<<<NT / 32, 256>>>();
    part2_reduce<<<16, 256>>>();
    // 4) ihat, ohat
    dots_kernel<<<NT / 32, 256>>>();
    // 5) softmax stats
    softmax_stats<<<32, 256>>>();
    // 6) fused flow-attention core -> scaled values (fp16)
    token_kernel<<<NT / 4, 256>>>();
    // 7) output projection (fp16 HMMA), fp32 output, unscale in epilogue
    hmma_gemm<<<dim3(EE / 128, NT / 128), 256, SMEM_GEMM>>>(
        p_vhi, p_wohi, b_out, out, nullptr, EE, EE, 0, VAL_INV_SCALE);
}

// round 16
// speedup vs baseline: 1.8637x; 1.0250x over previous
#include <cuda_runtime.h>
#include <cuda_fp16.h>
#include <math.h>
#include <stdint.h>

// Problem constants (fixed by the reference)
#define BB   4
#define SS   4096
#define EE   512
#define HH   8
#define DD   64
#define NT   (BB*SS)        // 16384 tokens
#define QW   1536           // 3*E

#define VAL_SCALE     1048576.0f          // 2^20: lift values out of fp16 subnormals
#define VAL_INV_SCALE (1.0f / 1048576.0f)

// ---------------- scratch (static device globals; no allocation) -------------
__device__ __half g_qkvh[(size_t)NT * QW]; // sig(q), sig(k), v in fp16 (48 MB)
__device__ float g_sums[4 * 32 * 64];      // [sumQ, sumK, sqd, skd] x bh x d
__device__ float g_csum[128 * QW];         // GEMM1 per-rowblock column sums
__device__ float g_part2[512 * 1024];      // dots_fused block partials (2 MB)
__device__ float g_io[(size_t)NT * HH * 2];
__device__ float g_hat[(size_t)NT * HH * 2];
__device__ float g_sm[64];
// fp16 GEMM operands
__device__ __half g_xhi[(size_t)NT * EE];
__device__ __half g_whi[(size_t)QW * EE];   // W_qkv hi
__device__ __half g_wohi[(size_t)EE * EE];  // W_out hi
__device__ __half g_vhi[(size_t)NT * EE];   // values*2^20 hi (GEMM2 A)

// ===================== portable PTX helpers (sm_80+) =========================
__device__ __forceinline__ uint32_t smem_u32(const void* p) {
    uint32_t a;
    asm("{ .reg .u64 t; cvta.to.shared.u64 t, %1; cvt.u32.u64 %0, t; }"
        : "=r"(a) : "l"(p));
    return a;
}
#define LDSM_X4(r0, r1, r2, r3, addr) \
    asm volatile("ldmatrix.sync.aligned.m8n8.x4.shared.b16 {%0,%1,%2,%3}, [%4];" \
        : "=r"(r0), "=r"(r1), "=r"(r2), "=r"(r3) : "r"(addr))
#define MMA_F16(d, a, b) \
    asm volatile("mma.sync.aligned.m16n8k16.row.col.f32.f16.f16.f32 " \
        "{%0,%1,%2,%3},{%4,%5,%6,%7},{%8,%9},{%0,%1,%2,%3};" \
        : "+f"((d)[0]), "+f"((d)[1]), "+f"((d)[2]), "+f"((d)[3]) \
        : "r"((a)[0]), "r"((a)[1]), "r"((a)[2]), "r"((a)[3]), \
          "r"((b)[0]), "r"((b)[1]))
#define CP_ASYNC16(dst, src) \
    asm volatile("cp.async.cg.shared.global [%0], [%1], 16;" \
        :: "r"(dst), "l"(src))
#define CP_COMMIT() asm volatile("cp.async.commit_group;" ::: "memory")
#define CP_WAIT(n)  asm volatile("cp.async.wait_group %0;" :: "n"(n) : "memory")

// SMEM geometry (BK=64): rows of 64 fp16 (128B) padded to 144B.
#define PITCH_B   144u
#define PLANE_B   18432u               // 128 rows * 144B
#define STAGE_B   36864u               // Ahi + Bhi planes
#define NSTAGE    3
#define SMEM_GEMM (NSTAGE * STAGE_B)   // 110592 bytes -> 2 CTAs per SM

// ========= HMMA fp16 GEMM: C[m,n] = sum_k A[m,k]B[n,k] + bias[n] =============
__device__ __forceinline__ void issue_stage(
    uint32_t sbase, int stage, int k0,
    const __half* __restrict__ ahi, const __half* __restrict__ bhi,
    int K, int tid)
{
    const uint32_t sb = sbase + (uint32_t)stage * STAGE_B;
#pragma unroll
    for (int it = 0; it < 8; it++) {
        int idx   = it * 256 + tid;
        int plane = idx >> 10;
        int rc    = idx & 1023;
        int row   = rc >> 3;
        int c     = rc & 7;
        uint32_t dst = sb + (uint32_t)plane * PLANE_B
                     + (uint32_t)row * PITCH_B + (uint32_t)c * 16u;
        const __half* src = (plane == 0 ? ahi : bhi)
                          + (size_t)row * K + k0 + c * 8;
        CP_ASYNC16(dst, src);
    }
}

__global__ __launch_bounds__(256, 2) void hmma_gemm(
    const __half* __restrict__ Ahi, const __half* __restrict__ Bhi,
    const float* __restrict__ bias, float* __restrict__ Cf,
    __half* __restrict__ Ch,
    int N, int K, int sigmode, float ascale)
{
    extern __shared__ char dynsmem[];
    const uint32_t sbase = smem_u32(dynsmem);

    const int tid   = threadIdx.x;
    const int warp  = tid >> 5;
    const int lane  = tid & 31;
    const int warpM = warp & 1;
    const int warpN = warp >> 1;

    const __half* ahi = Ahi + (size_t)blockIdx.y * 128 * K;
    const __half* bhi = Bhi + (size_t)blockIdx.x * 128 * K;

    float acc[16][4];
#pragma unroll
    for (int i = 0; i < 16; i++)
#pragma unroll
        for (int j = 0; j < 4; j++) acc[i][j] = 0.f;

    const int NC = K >> 6;

    const uint32_t a_lane = (uint32_t)(warpM * 64 + (lane & 15)) * PITCH_B
                          + (uint32_t)((lane >> 4) * 16);
    const uint32_t b_lane = PLANE_B
                          + (uint32_t)(warpN * 32 + (lane & 7) + ((lane >> 4) & 1) * 8) * PITCH_B
                          + (uint32_t)(((lane >> 3) & 1) * 16);

    issue_stage(sbase, 0, 0, ahi, bhi, K, tid);
    CP_COMMIT();
    issue_stage(sbase, 1, 64, ahi, bhi, K, tid);
    CP_COMMIT();

    for (int c = 0; c < NC; c++) {
        CP_WAIT(1);
        __syncthreads();
        if (c + 2 < NC)
            issue_stage(sbase, (c + 2) % NSTAGE, (c + 2) * 64, ahi, bhi, K, tid);
        CP_COMMIT();

        const uint32_t cur = sbase + (uint32_t)(c % NSTAGE) * STAGE_B;

        // B fragments double-buffered across ks
        uint32_t bhB[2][4][2];
#pragma unroll
        for (int p = 0; p < 2; p++) {
            uint32_t addr = cur + b_lane + (uint32_t)(p * 16) * PITCH_B;
            LDSM_X4(bhB[0][2*p][0], bhB[0][2*p][1],
                    bhB[0][2*p+1][0], bhB[0][2*p+1][1], addr);
        }

#pragma unroll
        for (int ks = 0; ks < 4; ks++) {
            const int cb = ks & 1;
            if (ks < 3) {
                const uint32_t koff2 = (uint32_t)(ks + 1) * 32u;
#pragma unroll
                for (int p = 0; p < 2; p++) {
                    uint32_t addr = cur + b_lane + (uint32_t)(p * 16) * PITCH_B + koff2;
                    LDSM_X4(bhB[cb^1][2*p][0], bhB[cb^1][2*p][1],
                            bhB[cb^1][2*p+1][0], bhB[cb^1][2*p+1][1], addr);
                }
            }
            const uint32_t koff = (uint32_t)ks * 32u;
            uint32_t ah[2][4];
            {
                uint32_t addr = cur + a_lane + koff;
                LDSM_X4(ah[0][0], ah[0][1], ah[0][2], ah[0][3], addr);
            }
#pragma unroll
            for (int mi = 0; mi < 4; mi++) {
                const int cu = mi & 1, nx = cu ^ 1;
                if (mi < 3) {
                    uint32_t addr = cur + a_lane
                                  + (uint32_t)((mi + 1) * 16) * PITCH_B + koff;
                    LDSM_X4(ah[nx][0], ah[nx][1], ah[nx][2], ah[nx][3], addr);
                }
#pragma unroll
                for (int ni = 0; ni < 4; ni++)
                    MMA_F16(acc[mi * 4 + ni], ah[cu], bhB[cb][ni]);
            }
        }
    }

    // ---- epilogue: unscale + bias + optional sigmoid + column sums ----
    float scol0[4], scol1[4];
#pragma unroll
    for (int ni = 0; ni < 4; ni++) { scol0[ni] = 0.f; scol1[ni] = 0.f; }

#pragma unroll
    for (int mi = 0; mi < 4; mi++) {
        const int r0 = blockIdx.y * 128 + warpM * 64 + mi * 16 + (lane >> 2);
#pragma unroll
        for (int ni = 0; ni < 4; ni++) {
            const int col = blockIdx.x * 128 + warpN * 32 + ni * 8 + (lane & 3) * 2;
            const float b0 = __ldg(bias + col);
            const float b1 = __ldg(bias + col + 1);
            float v0 = acc[mi * 4 + ni][0] * ascale + b0;
            float v1 = acc[mi * 4 + ni][1] * ascale + b1;
            float v2 = acc[mi * 4 + ni][2] * ascale + b0;
            float v3 = acc[mi * 4 + ni][3] * ascale + b1;
            if (sigmode) {
                const bool s0 = (col % 192) < 128;
                const bool s1 = ((col + 1) % 192) < 128;
                if (s0) { v0 = 1.f / (1.f + __expf(-v0)); v2 = 1.f / (1.f + __expf(-v2)); }
                if (s1) { v1 = 1.f / (1.f + __expf(-v1)); v3 = 1.f / (1.f + __expf(-v3)); }
                scol0[ni] += v0 + v2; scol1[ni] += v1 + v3;
                *(__half2*)(Ch + (size_t)r0 * N + col) =
                    __half2(__float2half(v0), __float2half(v1));
                *(__half2*)(Ch + (size_t)(r0 + 8) * N + col) =
                    __half2(__float2half(v2), __float2half(v3));
            } else {
                *(float2*)(Cf + (size_t)r0 * N + col)       = make_float2(v0, v1);
                *(float2*)(Cf + (size_t)(r0 + 8) * N + col) = make_float2(v2, v3);
            }
        }
    }

    if (sigmode) {
#pragma unroll
        for (int ni = 0; ni < 4; ni++) {
#pragma unroll
            for (int off = 4; off <= 16; off <<= 1) {
                scol0[ni] += __shfl_xor_sync(0xFFFFFFFFu, scol0[ni], off);
                scol1[ni] += __shfl_xor_sync(0xFFFFFFFFu, scol1[ni], off);
            }
        }
        float* scs = (float*)dynsmem;
        __syncthreads();
        if (lane < 4) {
#pragma unroll
            for (int ni = 0; ni < 4; ni++) {
                scs[warp * 32 + ni * 8 + lane * 2]     = scol0[ni];
                scs[warp * 32 + ni * 8 + lane * 2 + 1] = scol1[ni];
            }
        }
        __syncthreads();
        if (warpM == 0 && lane < 4) {
#pragma unroll
            for (int ni = 0; ni < 4; ni++) {
                int sl = ni * 8 + lane * 2;
                float t0 = scs[warp * 32 + sl]     + scs[(warp + 1) * 32 + sl];
                float t1 = scs[warp * 32 + sl + 1] + scs[(warp + 1) * 32 + sl + 1];
                int colg = blockIdx.x * 128 + warpN * 32 + sl;
                g_csum[blockIdx.y * QW + colg]     = t0;
                g_csum[blockIdx.y * QW + colg + 1] = t1;
            }
        }
    }
}

// ---- finish sumQ/sumK: combine 32 row-block partials per batch --------------
__global__ __launch_bounds__(256) void colsum_finish()
{
    int idx = blockIdx.x * 256 + threadIdx.x;   // 0..4095
    int b    = idx >> 10;
    int slot = idx & 1023;                       // h*128 + isk*64 + d
    int h = slot >> 7, r = slot & 127;
    int isk = r >> 6, d = r & 63;
    int col = h * 192 + isk * 64 + d;
    float acc = 0.f;
#pragma unroll
    for (int j = 0; j < 32; j++)
        acc += g_csum[(b * 32 + j) * QW + col];
    g_sums[(size_t)isk * 2048 + (b * 8 + h) * 64 + d] = acc;
}

// ---------------- fused fp32 -> fp16 converter (x, W_qkv, W_out) --------------
__global__ __launch_bounds__(256) void cvt_all(
    const float4* __restrict__ x, const float4* __restrict__ w,
    const float4* __restrict__ wo,
    __half2* __restrict__ xhi, __half2* __restrict__ whi,
    __half2* __restrict__ wohi)
{
    const int NX = NT * EE / 4, NW = QW * EE / 4, NO = EE * EE / 4;
    int i = blockIdx.x * 256 + threadIdx.x;
    const float4* src; __half2* dst; int j;
    if (i < NX)            { src = x;  dst = xhi;  j = i; }
    else if (i < NX + NW)  { src = w;  dst = whi;  j = i - NX; }
    else if (i < NX + NW + NO) { src = wo; dst = wohi; j = i - NX - NW; }
    else return;
    float4 v = src[j];
    dst[2 * j]     = __half2(__float2half(v.x), __float2half(v.y));
    dst[2 * j + 1] = __half2(__float2half(v.z), __float2half(v.w));
}

// ------- fused dots(i,o) + block partial sums of q/i, k/o ---------------------
// 512 blocks x 256 threads; warp handles 4 tokens; shfl chains interleaved.
__global__ __launch_bounds__(256) void dots_fused()
{
    int warp = threadIdx.x >> 5, lane = threadIdx.x & 31;
    int blk  = blockIdx.x;
    int b    = blk >> 7;                 // 128 blocks per batch

    __shared__ float2 sQ[8][32], sK[8][32];
    __shared__ float spart[8][1024];
    const float2* vq = (const float2*)(g_sums + (size_t)1 * 2048 + b * 512); // sumK
    const float2* vk = (const float2*)(g_sums + (size_t)0 * 2048 + b * 512); // sumQ
    if (threadIdx.x < 256) {
        int idx = threadIdx.x;
        sQ[idx >> 5][idx & 31] = vq[idx];
        sK[idx >> 5][idx & 31] = vk[idx];
    }
    __syncthreads();

    float pqx[8], pqy[8], pkx[8], pky[8];
#pragma unroll
    for (int h = 0; h < 8; h++) { pqx[h] = pqy[h] = pkx[h] = pky[h] = 0.f; }

    const int tok0 = blk * 32 + warp * 4;

#pragma unroll
    for (int h = 0; h < 8; h++) {
        float2 q2[4], k2[4];
        float vi[4], vo[4];
        const float2 sq = sQ[h][lane], sk = sK[h][lane];
#pragma unroll
        for (int t = 0; t < 4; t++) {
            const __half* tq = g_qkvh + (size_t)(tok0 + t) * QW;
            q2[t] = __half22float2(((const __half2*)(tq + h * 192))[lane]);
            k2[t] = __half22float2(((const __half2*)(tq + h * 192 + 64))[lane]);
            vi[t] = q2[t].x * sq.x + q2[t].y * sq.y;
            vo[t] = k2[t].x * sk.x + k2[t].y * sk.y;
        }
#pragma unroll
        for (int off = 16; off; off >>= 1) {
#pragma unroll
            for (int t = 0; t < 4; t++) {
                vi[t] += __shfl_xor_sync(0xFFFFFFFFu, vi[t], off);
                vo[t] += __shfl_xor_sync(0xFFFFFFFFu, vo[t], off);
            }
        }
#pragma unroll
        for (int t = 0; t < 4; t++) {
            float ri = 1.0f / vi[t], ro = 1.0f / vo[t];
            pqx[h] += q2[t].x * ri;  pqy[h] += q2[t].y * ri;
            pkx[h] += k2[t].x * ro;  pky[h] += k2[t].y * ro;
            if (lane == 0) {
                g_io[(size_t)(tok0 + t) * 8 + h]                   = vi[t];
                g_io[(size_t)NT * 8 + (size_t)(tok0 + t) * 8 + h]  = vo[t];
            }
        }
    }

    float2* spq = (float2*)spart[warp];
#pragma unroll
    for (int h = 0; h < 8; h++) {
        spq[h * 32 + lane]       = make_float2(pqx[h], pqy[h]);
        spq[256 + h * 32 + lane] = make_float2(pkx[h], pky[h]);
    }
    __syncthreads();
    for (int s = threadIdx.x; s < 1024; s += 256) {
        float a = 0.f;
#pragma unroll
        for (int w = 0; w < 8; w++) a += spart[w][s];
        g_part2[blk * 1024 + s] = a;
    }
}

// combine block partials -> sqd (slot2), skd (slot3)
__global__ __launch_bounds__(256) void part2_reduce()
{
    int idx = blockIdx.x * 256 + threadIdx.x;   // 0..4095
    int b   = idx >> 10;
    int off = idx & 1023;
    float acc = 0.f;
#pragma unroll 8
    for (int j = 0; j < 128; j++)
        acc += g_part2[(b * 128 + j) * 1024 + off];
    int side = off >> 9;
    int hd   = off & 511;
    g_sums[(size_t)(2 + side) * 2048 + b * 512 + hd] = acc;
}

// ------ dots phase 1 (ihat, ohat): warp per 4 tokens, interleaved shfl --------
__global__ __launch_bounds__(256) void dots_kernel()
{
    int warp = threadIdx.x >> 5, lane = threadIdx.x & 31;
    int blk  = blockIdx.x;
    int b    = blk >> 7;

    __shared__ float2 sQ[8][32], sK[8][32];
    const float2* vq = (const float2*)(g_sums + (size_t)3 * 2048 + b * 512); // skd
    const float2* vk = (const float2*)(g_sums + (size_t)2 * 2048 + b * 512); // sqd
    if (threadIdx.x < 256) {
        int idx = threadIdx.x;
        sQ[idx >> 5][idx & 31] = vq[idx];
        sK[idx >> 5][idx & 31] = vk[idx];
    }
    __syncthreads();

    const int tok0 = blk * 32 + warp * 4;

#pragma unroll
    for (int h = 0; h < 8; h++) {
        float vi[4], vo[4];
        const float2 sq = sQ[h][lane], sk = sK[h][lane];
#pragma unroll
        for (int t = 0; t < 4; t++) {
            const __half* tq = g_qkvh + (size_t)(tok0 + t) * QW;
            float2 q2 = __half22float2(((const __half2*)(tq + h * 192))[lane]);
            float2 k2 = __half22float2(((const __half2*)(tq + h * 192 + 64))[lane]);
            vi[t] = q2.x * sq.x + q2.y * sq.y;
            vo[t] = k2.x * sk.x + k2.y * sk.y;
        }
#pragma unroll
        for (int off = 16; off; off >>= 1) {
#pragma unroll
            for (int t = 0; t < 4; t++) {
                vi[t] += __shfl_xor_sync(0xFFFFFFFFu, vi[t], off);
                vo[t] += __shfl_xor_sync(0xFFFFFFFFu, vo[t], off);
            }
        }
        if (lane == 0) {
#pragma unroll
            for (int t = 0; t < 4; t++) {
                g_hat[(size_t)(tok0 + t) * 8 + h]                  = vi[t];
                g_hat[(size_t)NT * 8 + (size_t)(tok0 + t) * 8 + h] = vo[t];
            }
        }
    }
}

// ---------------- softmax stats over seq per (b,h) ---------------------------
__global__ __launch_bounds__(256) void softmax_stats()
{
    int bh = blockIdx.x;
    int b = bh >> 3, h = bh & 7;
    __shared__ float red[256];
    const float* oh = g_hat + (size_t)NT * 8 + (size_t)b * SS * 8 + h;

    float m = -1e30f;
    for (int s = threadIdx.x; s < SS; s += 256) m = fmaxf(m, oh[(size_t)s * 8]);
    red[threadIdx.x] = m; __syncthreads();
    for (int o = 128; o; o >>= 1) {
        if (threadIdx.x < o) red[threadIdx.x] = fmaxf(red[threadIdx.x], red[threadIdx.x + o]);
        __syncthreads();
    }
    m = red[0]; __syncthreads();

    float sum = 0.f;
    for (int s = threadIdx.x; s < SS; s += 256) sum += expf(oh[(size_t)s * 8] - m);
    red[threadIdx.x] = sum; __syncthreads();
    for (int o = 128; o; o >>= 1) {
        if (threadIdx.x < o) red[threadIdx.x] += red[threadIdx.x + o];
        __syncthreads();
    }
    if (threadIdx.x == 0) { g_sm[bh] = m; g_sm[32 + bh] = red[0]; }
}

// -------- fused flow-attention core (vectorized loads, fp16 out) --------------
__global__ __launch_bounds__(256) void token_kernel()
{
    int lt = threadIdx.x >> 6;
    int e  = threadIdx.x & 63;
    int tok = blockIdx.x * 4 + lt;
    int b   = tok >> 12;

    __shared__ float qi[4][8][66], kk[4][8][66], vw[4][8][66];
    __shared__ float Am[4][8][9];
    __shared__ float s_invi[4][8], s_sig[4][8], s_sm[4][8];

    if (e < 8) {
        int h = e;
        float iv = g_io[(size_t)tok * 8 + h];
        float ih = g_hat[(size_t)tok * 8 + h];
        float oh = g_hat[(size_t)NT * 8 + (size_t)tok * 8 + h];
        int bh = b * 8 + h;
        s_invi[lt][h] = 1.0f / iv;
        s_sig[lt][h]  = 1.0f / (1.0f + expf(-ih));
        s_sm[lt][h]   = expf(oh - g_sm[bh]) / g_sm[32 + bh];
    }
    __syncthreads();

    // cooperative vectorized load: plane-major, fully coalesced __half2
    const int tokBase = blockIdx.x * 4;
#pragma unroll
    for (int pl = 0; pl < 3; pl++) {
#pragma unroll
        for (int it = 0; it < 4; it++) {
            int idx = it * 256 + threadIdx.x;       // 0..1023
            int t   = idx >> 8;
            int h   = (idx >> 5) & 7;
            int e2  = idx & 31;
            const __half2* src = (const __half2*)(g_qkvh
                + (size_t)(tokBase + t) * QW) + h * 96 + pl * 32 + e2;
            float2 v = __half22float2(*src);
            if (pl == 0) {
                float s = s_invi[t][h];
                *(float2*)&qi[t][h][2 * e2] = make_float2(v.x * s, v.y * s);
            } else if (pl == 1) {
                *(float2*)&kk[t][h][2 * e2] = v;
            } else {
                float s = s_sm[t][h];
                *(float2*)&vw[t][h][2 * e2] = make_float2(v.x * s, v.y * s);
            }
        }
    }
    __syncthreads();

    {
        int h = e >> 3, h2 = e & 7;
        float a = 0.f;
#pragma unroll 8
        for (int d = 0; d < 64; d++) a = fmaf(qi[lt][h][d], kk[lt][h2][d], a);
        Am[lt][h][h2] = a;
    }
    __syncthreads();

    __half* ovh = g_vhi + (size_t)tok * EE;
#pragma unroll
    for (int h = 0; h < 8; h++) {
        float acc = 0.f;
#pragma unroll
        for (int h2 = 0; h2 < 8; h2++) acc = fmaf(Am[lt][h][h2], vw[lt][h2][e], acc);
        float vs = acc * s_sig[lt][h] * VAL_SCALE;
        ovh[h * 64 + e] = __float2half(vs);
    }
}

// ---------------- launch ------------------------------------------------------
extern "C" void kernel_launch(void* const* d_in, const int* in_sizes, int n_in,
                              void* d_out, int out_size)
{
    (void)in_sizes; (void)n_in; (void)out_size;
    const float* x     = (const float*)d_in[0];
    const float* W_qkv = (const float*)d_in[1];
    const float* b_qkv = (const float*)d_in[2];
    const float* W_out = (const float*)d_in[3];
    const float* b_out = (const float*)d_in[4];
    float* out = (float*)d_out;

    __half *p_qkvh, *p_xhi, *p_whi, *p_wohi, *p_vhi;
    cudaGetSymbolAddress((void**)&p_qkvh, g_qkvh);
    cudaGetSymbolAddress((void**)&p_xhi,  g_xhi);
    cudaGetSymbolAddress((void**)&p_whi,  g_whi);
    cudaGetSymbolAddress((void**)&p_wohi, g_wohi);
    cudaGetSymbolAddress((void**)&p_vhi,  g_vhi);

    cudaFuncSetAttribute(hmma_gemm, cudaFuncAttributeMaxDynamicSharedMemorySize,
                         SMEM_GEMM);

    // 0) convert all operands to fp16 (single kernel)
    {
        const int NTOT = NT * EE / 4 + QW * EE / 4 + EE * EE / 4;
        cvt_all<<<(NTOT + 255) / 256, 256>>>(
            (const float4*)x, (const float4*)W_qkv, (const float4*)W_out,
            (__half2*)p_xhi, (__half2*)p_whi, (__half2*)p_wohi);
    }
    // 1) QKV projection + sigmoid + fused column sums; fp16 output
    hmma_gemm<<<dim3(QW / 128, NT / 128), 256, SMEM_GEMM>>>(
        p_xhi, p_whi, b_qkv, nullptr, p_qkvh, QW, EE, 1, 1.0f);
    // 2) finish sumQ/sumK
    colsum_finish<<<16, 256>>>();
    // 3) fused: i,o per token + block partial sums of q/i, k/o
    dots_fused<<<NT / 32, 256>>>();
    part2_reduce<<<16, 256>>>();
    // 4) ihat, ohat
    dots_kernel<<<NT / 32, 256>>>();
    // 5) softmax stats
    softmax_stats<<<32, 256>>>();
    // 6) fused flow-attention core -> scaled values (fp16)
    token_kernel<<<NT / 4, 256>>>();
    // 7) output projection (fp16 HMMA), fp32 output, unscale in epilogue
    hmma_gemm<<<dim3(EE / 128, NT / 128), 256, SMEM_GEMM>>>(
        p_vhi, p_wohi, b_out, out, nullptr, EE, EE, 0, VAL_INV_SCALE);
}